// round 12
// baseline (speedup 1.0000x reference)
#include <cuda_runtime.h>
#include <cuda_bf16.h>
#include <math.h>
#include <stdint.h>

#define D_    512
#define S_    512
#define B_    4
#define H_    8
#define L_    6
#define DFF_  2048
#define V_    32000
#define BS_   (B_ * S_)
#define NEGV  (-1e10f)

#if defined(__CUDA_ARCH_FEAT_SM103_ALL) || defined(__CUDA_ARCH_FEAT_SM100_ALL) || defined(__CUDA_ARCH_FEAT_SM101_ALL)
#define HAS_TC 1
#else
#define HAS_TC 0
#endif

typedef __nv_bfloat16  bf16;
typedef __nv_bfloat162 bf162;

// ---------------------------------------------------------------------------
// Scratch (device globals)
// ---------------------------------------------------------------------------
__device__ float g_x[BS_ * D_];
__device__ float g_a[BS_ * D_];
__device__ float g_out[BS_ * D_];
__device__ float g_f[BS_ * D_];
__device__ float g_y0[BS_ * D_];
__device__ float g_o[BS_ * D_];

__device__ bf16 g_xh[BS_ * D_],   g_xl[BS_ * D_];
__device__ bf16 g_outh[BS_ * D_], g_outl[BS_ * D_];
__device__ bf16 g_ath[BS_ * D_],  g_atl[BS_ * D_];
__device__ bf16 g_y0h[BS_ * D_],  g_y0l[BS_ * D_];
__device__ bf16 g_oh[BS_ * D_],   g_ol[BS_ * D_];
__device__ bf16 g_hh[BS_ * DFF_], g_hl[BS_ * DFF_];

// Attention scratch
__device__ bf16  g_qkvh[BS_ * 3 * D_], g_qkvl[BS_ * 3 * D_];
__device__ bf16  g_kv2h[BS_ * 2 * D_], g_kv2l[BS_ * 2 * D_];
__device__ bf16  g_q2h[BS_ * D_],      g_q2l[BS_ * D_];
__device__ bf16  g_ph[32ull * S_ * S_], g_pl[32ull * S_ * S_]; // unnormalized probs
__device__ float g_linv[32ull * S_];                           // 1/rowsum
__device__ bf16  g_vth[32ull * 64 * S_], g_vtl[32ull * 64 * S_];

// Transposed+split weights arena (element offsets). Per-layer-contiguous QKV.
#define DD      (512ull * 512ull)
#define DDF     (512ull * 2048ull)
#define O_EQKV  0ull
#define O_EWO   4718592ull
#define O_EW1   6291456ull
#define O_EW2   12582912ull
#define O_DQKV1 18874368ull
#define O_DWO1  19660800ull
#define O_DWQ2  19922944ull
#define O_DKV2  20185088ull
#define O_DWO2  20709376ull
#define O_DW1   20971520ull
#define O_DW2   22020096ull
#define O_WOUT  23068672ull
#define NWTOT   39452672ull
__device__ bf16 g_wh[NWTOT];
__device__ bf16 g_wl[NWTOT];

// ---------------------------------------------------------------------------
// PTX helpers
// ---------------------------------------------------------------------------
__device__ __forceinline__ uint32_t s2u(const void* p) {
    uint32_t a;
    asm("{ .reg .u64 t; cvta.to.shared.u64 t, %1; cvt.u32.u64 %0, t; }"
        : "=r"(a) : "l"(p));
    return a;
}
__device__ __forceinline__ uint32_t swz(uint32_t o) { return o ^ ((o >> 3) & 0x70u); }

__device__ __forceinline__ void mbar_init(uint32_t a, uint32_t c) {
    asm volatile("mbarrier.init.shared.b64 [%0], %1;" :: "r"(a), "r"(c) : "memory");
}
__device__ __forceinline__ void mbar_wait(uint32_t a, uint32_t ph) {
    uint32_t done;
    asm volatile(
        "{\n\t.reg .pred p;\n\t"
        "mbarrier.try_wait.parity.acquire.cta.shared::cta.b64 p, [%1], %2;\n\t"
        "selp.b32 %0,1,0,p;\n\t}"
        : "=r"(done) : "r"(a), "r"(ph) : "memory");
    if (!done) {
        asm volatile(
            "{\n\t.reg .pred P1;\n\t"
            "WAIT_LOOP_%=:\n\t"
            "mbarrier.try_wait.parity.acquire.cta.shared::cta.b64 P1, [%0], %1, 0x989680;\n\t"
            "@P1 bra.uni WAIT_DONE_%=;\n\t"
            "bra.uni WAIT_LOOP_%=;\n\t"
            "WAIT_DONE_%=:\n\t}"
            :: "r"(a), "r"(ph) : "memory");
    }
}
#define FENCE_ASYNC() asm volatile("fence.proxy.async.shared::cta;" ::: "memory")

__device__ __forceinline__ void cpasync16(uint32_t saddr, const void* g) {
    asm volatile("cp.async.cg.shared.global [%0], [%1], 16;"
                 :: "r"(saddr), "l"(g));
}
#define CP_COMMIT() asm volatile("cp.async.commit_group;" ::: "memory")
#define CP_WAIT1()  asm volatile("cp.async.wait_group 1;" ::: "memory")
#define CP_WAIT0()  asm volatile("cp.async.wait_group 0;" ::: "memory")

#if HAS_TC
__device__ __forceinline__ uint64_t mkdesc(uint32_t addr) {
    const uint64_t base = (2ull << 61) | (1ull << 46) | (64ull << 32) | (1ull << 16);
    return base | ((uint64_t)(addr >> 4) & 0x3FFFull);
}
__device__ __forceinline__ void mma_f16_ss(uint32_t d, uint64_t ad, uint64_t bd,
                                           uint32_t idesc, uint32_t en) {
    asm volatile(
        "{\n\t.reg .pred p;\n\tsetp.ne.u32 p, %5, 0;\n\t"
        "tcgen05.mma.cta_group::1.kind::f16 [%0], %1, %2, %3, {%4,%4,%4,%4}, p;\n\t}"
        :: "r"(d), "l"(ad), "l"(bd), "r"(idesc), "r"(0u), "r"(en) : "memory");
}
#define TC_ALLOC(sa, n)  asm volatile("tcgen05.alloc.cta_group::1.sync.aligned.shared::cta.b32 [%0], %1;" :: "r"(sa), "r"(n) : "memory")
#define TC_DEALLOC(t, n) asm volatile("tcgen05.dealloc.cta_group::1.sync.aligned.b32 %0, %1;" :: "r"(t), "r"(n))
#define TC_COMMIT(mb)    asm volatile("tcgen05.commit.cta_group::1.mbarrier::arrive::one.shared::cluster.b64 [%0];" :: "r"(mb) : "memory")
#define TC_FENCE_AFTER() asm volatile("tcgen05.fence::after_thread_sync;" ::: "memory")
#define TC_WAIT_LD()     asm volatile("tcgen05.wait::ld.sync.aligned;" ::: "memory")

#define TCLD32(r, a) \
    asm volatile( \
        "tcgen05.ld.sync.aligned.32x32b.x32.b32 " \
        "{%0, %1, %2, %3, %4, %5, %6, %7, " \
        " %8, %9, %10, %11, %12, %13, %14, %15, " \
        " %16, %17, %18, %19, %20, %21, %22, %23, " \
        " %24, %25, %26, %27, %28, %29, %30, %31}, [%32];" \
        : "=r"((r)[0]),  "=r"((r)[1]),  "=r"((r)[2]),  "=r"((r)[3]), \
          "=r"((r)[4]),  "=r"((r)[5]),  "=r"((r)[6]),  "=r"((r)[7]), \
          "=r"((r)[8]),  "=r"((r)[9]),  "=r"((r)[10]), "=r"((r)[11]), \
          "=r"((r)[12]), "=r"((r)[13]), "=r"((r)[14]), "=r"((r)[15]), \
          "=r"((r)[16]), "=r"((r)[17]), "=r"((r)[18]), "=r"((r)[19]), \
          "=r"((r)[20]), "=r"((r)[21]), "=r"((r)[22]), "=r"((r)[23]), \
          "=r"((r)[24]), "=r"((r)[25]), "=r"((r)[26]), "=r"((r)[27]), \
          "=r"((r)[28]), "=r"((r)[29]), "=r"((r)[30]), "=r"((r)[31]) \
        : "r"(a))
#endif  // HAS_TC

#define IDESC_N(n) ((1u<<4)|(1u<<7)|(1u<<10)|(((n)/8u)<<17)|(8u<<24))

__device__ __forceinline__ void split_store4(bf16* __restrict__ Hh,
                                             bf16* __restrict__ Hl,
                                             size_t idx, float4 v) {
    bf16 hx = __float2bfloat16_rn(v.x), hy = __float2bfloat16_rn(v.y);
    bf16 hz = __float2bfloat16_rn(v.z), hw = __float2bfloat16_rn(v.w);
    bf16 lx = __float2bfloat16_rn(v.x - __bfloat162float(hx));
    bf16 ly = __float2bfloat16_rn(v.y - __bfloat162float(hy));
    bf16 lz = __float2bfloat16_rn(v.z - __bfloat162float(hz));
    bf16 lw = __float2bfloat16_rn(v.w - __bfloat162float(hw));
    bf162 p;
    p.x = hx; p.y = hy; *(bf162*)(Hh + idx)     = p;
    p.x = hz; p.y = hw; *(bf162*)(Hh + idx + 2) = p;
    p.x = lx; p.y = ly; *(bf162*)(Hl + idx)     = p;
    p.x = lz; p.y = lw; *(bf162*)(Hl + idx + 2) = p;
}

// ---------------------------------------------------------------------------
// Mega weight-conversion kernel
// ---------------------------------------------------------------------------
struct WcvEntry {
    const float* src;
    unsigned long long dst;
    unsigned long long lstride;
    int K, N, ntx, nty, nz, tstart;
};
struct WcvTable { WcvEntry e[17]; };

__global__ __launch_bounds__(256) void wconv_all(
    WcvTable tab, int nent, bf16* __restrict__ oh, bf16* __restrict__ ol)
{
    __shared__ float tile[32][33];
    int tid = blockIdx.x;
    int i = 0;
    while (i + 1 < nent && tid >= tab.e[i + 1].tstart) i++;
    const WcvEntry E = tab.e[i];
    int t = tid - E.tstart;
    int per_z = E.ntx * E.nty;
    int z  = t / per_z;
    int rm = t - z * per_z;
    int txb = rm % E.ntx, tyb = rm / E.ntx;
    const int n0 = txb * 32, k0 = tyb * 32;
    const int K = E.K, N = E.N;
    const float* Wb = E.src + (size_t)z * K * N;
    bf16* ohb = oh + E.dst + (size_t)z * E.lstride;
    bf16* olb = ol + E.dst + (size_t)z * E.lstride;

    const int tx = threadIdx.x, ty = threadIdx.y;
    #pragma unroll
    for (int ii = 0; ii < 4; ii++)
        tile[ty + 8 * ii][tx] = Wb[(size_t)(k0 + ty + 8 * ii) * N + n0 + tx];
    __syncthreads();
    #pragma unroll
    for (int ii = 0; ii < 4; ii++) {
        float v = tile[tx][ty + 8 * ii];
        int n = n0 + ty + 8 * ii, k = k0 + tx;
        size_t idx = (size_t)n * K + k;
        bf16 h = __float2bfloat16_rn(v);
        ohb[idx] = h;
        olb[idx] = __float2bfloat16_rn(v - __bfloat162float(h));
    }
}

// ---------------------------------------------------------------------------
// Embedding + positional encoding (+ bf16 split)
// ---------------------------------------------------------------------------
__global__ __launch_bounds__(128) void embed_kernel(
    const int* __restrict__ ids, const float* __restrict__ emb,
    float* __restrict__ out, bf16* __restrict__ oh, bf16* __restrict__ ol)
{
    const int row = blockIdx.x;
    const int s   = row & (S_ - 1);
    const int tok = ids[row];
    const int t   = threadIdx.x;
    const float c = -logf(10000.0f) / (float)D_;
    float4 v;
    float tmp[4];
    #pragma unroll
    for (int j = 0; j < 4; j++) {
        int d  = t * 4 + j;
        int tj = d >> 1;
        float div = expf((float)(2 * tj) * c);
        float ang = (float)s * div;
        float pe  = (d & 1) ? cosf(ang) : sinf(ang);
        tmp[j] = emb[(size_t)tok * D_ + d] + pe;
    }
    v.x = tmp[0]; v.y = tmp[1]; v.z = tmp[2]; v.w = tmp[3];
    size_t base = (size_t)row * D_ + t * 4;
    *(float4*)(out + base) = v;
    split_store4(oh, ol, base, v);
}

// ---------------------------------------------------------------------------
// Fused residual + LayerNorm (+ bf16 split)
// ---------------------------------------------------------------------------
__global__ __launch_bounds__(128) void add_ln_kernel(
    const float* __restrict__ A, const float* __restrict__ Bv,
    float* __restrict__ Out, bf16* __restrict__ Oh, bf16* __restrict__ Ol)
{
    const int row = blockIdx.x;
    const int t   = threadIdx.x;
    const size_t base = (size_t)row * D_ + t * 4;
    float4 a = *(const float4*)(A + base);
    float4 b = *(const float4*)(Bv + base);
    float4 vv;
    vv.x = a.x + b.x; vv.y = a.y + b.y; vv.z = a.z + b.z; vv.w = a.w + b.w;

    float s  = vv.x + vv.y + vv.z + vv.w;
    float sq = vv.x * vv.x + vv.y * vv.y + vv.z * vv.z + vv.w * vv.w;
    __shared__ float redS[4], redQ[4];
    #pragma unroll
    for (int off = 16; off > 0; off >>= 1) {
        s  += __shfl_xor_sync(0xffffffffu, s,  off);
        sq += __shfl_xor_sync(0xffffffffu, sq, off);
    }
    const int wid = t >> 5, lane = t & 31;
    if (lane == 0) { redS[wid] = s; redQ[wid] = sq; }
    __syncthreads();
    s  = redS[0] + redS[1] + redS[2] + redS[3];
    sq = redQ[0] + redQ[1] + redQ[2] + redQ[3];
    float mean = s * (1.0f / D_);
    float var  = sq * (1.0f / D_) - mean * mean;
    float inv  = rsqrtf(var + 1e-5f);
    float4 o;
    o.x = (vv.x - mean) * inv; o.y = (vv.y - mean) * inv;
    o.z = (vv.z - mean) * inv; o.w = (vv.w - mean) * inv;
    *(float4*)(Out + base) = o;
    split_store4(Oh, Ol, base, o);
}

// ---------------------------------------------------------------------------
// tcgen05 split-fp32 GEMM, MT=1, 3-stage cp.async pipeline.
// EPI: 0 ->C ; 1 +bias->C ; 3 +bias+relu->hi/lo ; 4 split->hi/lo ;
//      5 split->hi/lo for cols<vsplit, V-transposed hi/lo otherwise
// ---------------------------------------------------------------------------
#define GIDESC    IDESC_N(128)
#define STAGE_B   65536
#define NSTG      3
#define SMEM_GEMM (NSTG * STAGE_B + 1024)

template<int EPI>
__global__ __launch_bounds__(256)
void bgemm(const bf16* __restrict__ Ah, const bf16* __restrict__ Al,
           const bf16* __restrict__ Bh, const bf16* __restrict__ Bl,
           const float* __restrict__ bias, float* __restrict__ C,
           bf16* __restrict__ Ch, bf16* __restrict__ Cl,
           bf16* __restrict__ Vh, bf16* __restrict__ Vl, int vsplit,
           int M, int N, int K)
{
#if HAS_TC
    __shared__ __align__(16) uint32_t s_tptr[4];
    __shared__ __align__(16) uint64_t s_mbar[NSTG];
    extern __shared__ char smem[];
    const uint32_t tiles = (s2u(smem) + 1023u) & ~1023u;
    const uint32_t tptr  = s2u(s_tptr);
    uint32_t mb[NSTG];
    #pragma unroll
    for (int i = 0; i < NSTG; i++) mb[i] = s2u(&s_mbar[i]);

    const int t   = threadIdx.x;
    const int wid = t >> 5;
    const int bm  = blockIdx.y * 128, bn = blockIdx.x * 128;

    if (wid == 0) TC_ALLOC(tptr, 128);
    if (t == 0) {
        #pragma unroll
        for (int i = 0; i < NSTG; i++) mbar_init(mb[i], 1);
    }
    __syncthreads();
    const uint32_t tmem = s_tptr[0];

    const int r  = t >> 3;
    const int ck = t & 7;
    const int nch = K >> 6;
    int use[NSTG];
    #pragma unroll
    for (int i = 0; i < NSTG; i++) use[i] = 0;

    auto load_chunk = [&](int c, int s) {
        const uint32_t base = tiles + s * STAGE_B;
        const uint32_t aH = base, aL = base + 16384;
        const uint32_t bH = base + 32768, bL = base + 49152;
        const int k0 = c << 6;
        #pragma unroll
        for (int it = 0; it < 4; it++) {
            int row = r + it * 32;
            size_t g = (size_t)(bm + row) * K + k0 + ck * 8;
            uint32_t so = swz((uint32_t)(row * 128 + ck * 16));
            cpasync16(aH + so, Ah + g);
            cpasync16(aL + so, Al + g);
        }
        #pragma unroll
        for (int it = 0; it < 4; it++) {
            int row = r + it * 32;
            size_t g = (size_t)(bn + row) * K + k0 + ck * 8;
            uint32_t so = swz((uint32_t)(row * 128 + ck * 16));
            cpasync16(bH + so, Bh + g);
            cpasync16(bL + so, Bl + g);
        }
        CP_COMMIT();
    };

    load_chunk(0, 0);
    for (int c = 0; c < nch; c++) {
        const int s = c % NSTG;
        if (c + 1 < nch) {
            const int s2 = (c + 1) % NSTG;
            if (use[s2] > 0) mbar_wait(mb[s2], (use[s2] - 1) & 1);
            load_chunk(c + 1, s2);
            CP_WAIT1();
        } else {
            CP_WAIT0();
        }
        FENCE_ASYNC();
        __syncthreads();
        if (t == 0) {
            const uint32_t base = tiles + s * STAGE_B;
            uint64_t dah = mkdesc(base),         dal = mkdesc(base + 16384);
            uint64_t dbh = mkdesc(base + 32768), dbl = mkdesc(base + 49152);
            #pragma unroll
            for (int j = 0; j < 4; j++)
                mma_f16_ss(tmem, dah + 2 * j, dbh + 2 * j, GIDESC,
                           (c == 0 && j == 0) ? 0u : 1u);
            #pragma unroll
            for (int j = 0; j < 4; j++)
                mma_f16_ss(tmem, dah + 2 * j, dbl + 2 * j, GIDESC, 1u);
            #pragma unroll
            for (int j = 0; j < 4; j++)
                mma_f16_ss(tmem, dal + 2 * j, dbh + 2 * j, GIDESC, 1u);
            TC_COMMIT(mb[s]);
        }
        use[s]++;
    }
    #pragma unroll
    for (int i = 0; i < NSTG; i++)
        if (use[i] > 0) mbar_wait(mb[i], (use[i] - 1) & 1);
    TC_FENCE_AFTER();

    {
        const int sub = wid & 3, half = wid >> 2, lane = t & 31;
        const int rowg = bm + sub * 32 + lane;
        #pragma unroll
        for (int cc = 0; cc < 2; cc++) {
            const int col0 = half * 64 + cc * 32;
            uint32_t regs[32];
            TCLD32(regs, tmem + col0);
            TC_WAIT_LD();
            const int colbase = bn + col0;
            if (EPI == 0) {
                #pragma unroll
                for (int j = 0; j < 32; j += 4) {
                    float4 v;
                    v.x = __uint_as_float(regs[j]);
                    v.y = __uint_as_float(regs[j + 1]);
                    v.z = __uint_as_float(regs[j + 2]);
                    v.w = __uint_as_float(regs[j + 3]);
                    *(float4*)(C + (size_t)rowg * N + colbase + j) = v;
                }
            } else if (EPI == 1) {
                #pragma unroll
                for (int j = 0; j < 32; j += 4) {
                    float4 bv = *(const float4*)(bias + colbase + j);
                    float4 v;
                    v.x = __uint_as_float(regs[j])     + bv.x;
                    v.y = __uint_as_float(regs[j + 1]) + bv.y;
                    v.z = __uint_as_float(regs[j + 2]) + bv.z;
                    v.w = __uint_as_float(regs[j + 3]) + bv.w;
                    *(float4*)(C + (size_t)rowg * N + colbase + j) = v;
                }
            } else if (EPI == 3) {
                #pragma unroll
                for (int j = 0; j < 32; j += 4) {
                    float4 bv = *(const float4*)(bias + colbase + j);
                    float4 v;
                    v.x = fmaxf(__uint_as_float(regs[j])     + bv.x, 0.f);
                    v.y = fmaxf(__uint_as_float(regs[j + 1]) + bv.y, 0.f);
                    v.z = fmaxf(__uint_as_float(regs[j + 2]) + bv.z, 0.f);
                    v.w = fmaxf(__uint_as_float(regs[j + 3]) + bv.w, 0.f);
                    split_store4(Ch, Cl, (size_t)rowg * N + colbase + j, v);
                }
            } else if (EPI == 4) {
                #pragma unroll
                for (int j = 0; j < 32; j += 4) {
                    float4 v;
                    v.x = __uint_as_float(regs[j]);
                    v.y = __uint_as_float(regs[j + 1]);
                    v.z = __uint_as_float(regs[j + 2]);
                    v.w = __uint_as_float(regs[j + 3]);
                    split_store4(Ch, Cl, (size_t)rowg * N + colbase + j, v);
                }
            } else {  // EPI == 5
                if (colbase < vsplit) {
                    #pragma unroll
                    for (int j = 0; j < 32; j += 4) {
                        float4 v;
                        v.x = __uint_as_float(regs[j]);
                        v.y = __uint_as_float(regs[j + 1]);
                        v.z = __uint_as_float(regs[j + 2]);
                        v.w = __uint_as_float(regs[j + 3]);
                        split_store4(Ch, Cl, (size_t)rowg * N + colbase + j, v);
                    }
                } else {
                    const int vcol = colbase - vsplit;
                    const int z  = (rowg >> 9) * 8 + (vcol >> 6);
                    const int d0 = vcol & 63;
                    const int tok = rowg & 511;
                    const size_t vb = ((size_t)z * 64 + d0) * 512 + tok;
                    #pragma unroll
                    for (int j = 0; j < 32; j++) {
                        float fv = __uint_as_float(regs[j]);
                        bf16 h = __float2bfloat16_rn(fv);
                        bf16 l = __float2bfloat16_rn(fv - __bfloat162float(h));
                        Vh[vb + (size_t)j * 512] = h;
                        Vl[vb + (size_t)j * 512] = l;
                    }
                }
            }
        }
    }
    __syncthreads();
    if (wid == 0) TC_DEALLOC(tmem, 128);
#else
    const int t  = threadIdx.x;
    const int bm = blockIdx.y * 128, bn = blockIdx.x * 128;
    const int r0 = (t >> 4) * 8;
    const int c0 = (t & 15) * 8;
    for (int i = 0; i < 8; i++) {
        int rowg = bm + r0 + i;
        for (int j = 0; j < 8; j++) {
            int col = bn + c0 + j;
            float acc = 0.f;
            for (int k = 0; k < K; k++) {
                float av = __bfloat162float(Ah[(size_t)rowg * K + k])
                         + __bfloat162float(Al[(size_t)rowg * K + k]);
                float bv = __bfloat162float(Bh[(size_t)col * K + k])
                         + __bfloat162float(Bl[(size_t)col * K + k]);
                acc += av * bv;
            }
            if (EPI == 1 || EPI == 3) acc += bias[col];
            if (EPI == 3) acc = fmaxf(acc, 0.f);
            if (EPI == 0 || EPI == 1) {
                C[(size_t)rowg * N + col] = acc;
            } else if (EPI == 3 || EPI == 4 || (EPI == 5 && col < vsplit)) {
                bf16 h = __float2bfloat16_rn(acc);
                Ch[(size_t)rowg * N + col] = h;
                Cl[(size_t)rowg * N + col] =
                    __float2bfloat16_rn(acc - __bfloat162float(h));
            } else {
                int vcol = col - vsplit;
                int z = (rowg >> 9) * 8 + (vcol >> 6);
                int d = vcol & 63, tok = rowg & 511;
                bf16 h = __float2bfloat16_rn(acc);
                Vh[((size_t)z * 64 + d) * 512 + tok] = h;
                Vl[((size_t)z * 64 + d) * 512 + tok] =
                    __float2bfloat16_rn(acc - __bfloat162float(h));
            }
        }
    }
#endif
}

// ---------------------------------------------------------------------------
// bgemm2: MT=2 variant for the logits GEMM. EPI 1 only.
// ---------------------------------------------------------------------------
#define STAGE2_B   98304
#define NSTG2      2
#define SMEM_GEMM2 (NSTG2 * STAGE2_B + 1024)

__global__ __launch_bounds__(256)
void bgemm2(const bf16* __restrict__ Ah, const bf16* __restrict__ Al,
            const bf16* __restrict__ Bh, const bf16* __restrict__ Bl,
            const float* __restrict__ bias, float* __restrict__ C,
            int M, int N, int K)
{
#if HAS_TC
    __shared__ __align__(16) uint32_t s_tptr[4];
    __shared__ __align__(16) uint64_t s_mbar[NSTG2];
    extern __shared__ char smem[];
    const uint32_t tiles = (s2u(smem) + 1023u) & ~1023u;
    const uint32_t tptr  = s2u(s_tptr);
    uint32_t mb[NSTG2];
    #pragma unroll
    for (int i = 0; i < NSTG2; i++) mb[i] = s2u(&s_mbar[i]);

    const int t   = threadIdx.x;
    const int wid = t >> 5;
    const int bm  = blockIdx.y * 256, bn = blockIdx.x * 128;

    if (wid == 0) TC_ALLOC(tptr, 256);
    if (t == 0) {
        #pragma unroll
        for (int i = 0; i < NSTG2; i++) mbar_init(mb[i], 1);
    }
    __syncthreads();
    const uint32_t tmem = s_tptr[0];

    const int r  = t >> 3;
    const int ck = t & 7;
    const int nch = K >> 6;
    int use[NSTG2];
    #pragma unroll
    for (int i = 0; i < NSTG2; i++) use[i] = 0;

    auto load_chunk = [&](int c, int s) {
        const uint32_t base = tiles + s * STAGE2_B;
        const int k0 = c << 6;
        #pragma unroll
        for (int m = 0; m < 2; m++) {
            const uint32_t aH = base + m * 32768, aL = aH + 16384;
            #pragma unroll
            for (int it = 0; it < 4; it++) {
                int row = r + it * 32;
                size_t g = (size_t)(bm + m * 128 + row) * K + k0 + ck * 8;
                uint32_t so = swz((uint32_t)(row * 128 + ck * 16));
                cpasync16(aH + so, Ah + g);
                cpasync16(aL + so, Al + g);
            }
        }
        const uint32_t bH = base + 65536, bL = base + 81920;
        #pragma unroll
        for (int it = 0; it < 4; it++) {
            int row = r + it * 32;
            size_t g = (size_t)(bn + row) * K + k0 + ck * 8;
            uint32_t so = swz((uint32_t)(row * 128 + ck * 16));
            cpasync16(bH + so, Bh + g);
            cpasync16(bL + so, Bl + g);
        }
        CP_COMMIT();
    };

    load_chunk(0, 0);
    for (int c = 0; c < nch; c++) {
        const int s = c % NSTG2;
        if (c + 1 < nch) {
            const int s2 = (c + 1) % NSTG2;
            if (use[s2] > 0) mbar_wait(mb[s2], (use[s2] - 1) & 1);
            load_chunk(c + 1, s2);
            CP_WAIT1();
        } else {
            CP_WAIT0();
        }
        FENCE_ASYNC();
        __syncthreads();
        if (t == 0) {
            const uint32_t base = tiles + s * STAGE2_B;
            uint64_t dbh = mkdesc(base + 65536), dbl = mkdesc(base + 81920);
            #pragma unroll
            for (int m = 0; m < 2; m++) {
                uint64_t dah = mkdesc(base + m * 32768);
                uint64_t dal = mkdesc(base + m * 32768 + 16384);
                const uint32_t acc = tmem + m * 128;
                #pragma unroll
                for (int j = 0; j < 4; j++)
                    mma_f16_ss(acc, dah + 2 * j, dbh + 2 * j, GIDESC,
                               (c == 0 && j == 0) ? 0u : 1u);
                #pragma unroll
                for (int j = 0; j < 4; j++)
                    mma_f16_ss(acc, dah + 2 * j, dbl + 2 * j, GIDESC, 1u);
                #pragma unroll
                for (int j = 0; j < 4; j++)
                    mma_f16_ss(acc, dal + 2 * j, dbh + 2 * j, GIDESC, 1u);
            }
            TC_COMMIT(mb[s]);
        }
        use[s]++;
    }
    #pragma unroll
    for (int i = 0; i < NSTG2; i++)
        if (use[i] > 0) mbar_wait(mb[i], (use[i] - 1) & 1);
    TC_FENCE_AFTER();

    {
        const int m = wid >> 2, sub = wid & 3, lane = t & 31;
        const int rowg = bm + m * 128 + sub * 32 + lane;
        #pragma unroll
        for (int cc = 0; cc < 4; cc++) {
            const int col0 = cc * 32;
            uint32_t regs[32];
            TCLD32(regs, tmem + m * 128 + col0);
            TC_WAIT_LD();
            const int colbase = bn + col0;
            #pragma unroll
            for (int j = 0; j < 32; j += 4) {
                float4 bv = *(const float4*)(bias + colbase + j);
                float4 v;
                v.x = __uint_as_float(regs[j])     + bv.x;
                v.y = __uint_as_float(regs[j + 1]) + bv.y;
                v.z = __uint_as_float(regs[j + 2]) + bv.z;
                v.w = __uint_as_float(regs[j + 3]) + bv.w;
                *(float4*)(C + (size_t)rowg * N + colbase + j) = v;
            }
        }
    }
    __syncthreads();
    if (wid == 0) TC_DEALLOC(tmem, 256);
#else
    const int t  = threadIdx.x;
    const int bm = blockIdx.y * 256, bn = blockIdx.x * 128;
    const int r0 = (t >> 4) * 16;
    const int c0 = (t & 15) * 8;
    for (int i = 0; i < 16; i++) {
        int rowg = bm + r0 + i;
        for (int j = 0; j < 8; j++) {
            int col = bn + c0 + j;
            float acc = 0.f;
            for (int k = 0; k < K; k++) {
                float av = __bfloat162float(Ah[(size_t)rowg * K + k])
                         + __bfloat162float(Al[(size_t)rowg * K + k]);
                float bv = __bfloat162float(Bh[(size_t)col * K + k])
                         + __bfloat162float(Bl[(size_t)col * K + k]);
                acc += av * bv;
            }
            C[(size_t)rowg * N + col] = acc + bias[col];
        }
    }
#endif
}

// ---------------------------------------------------------------------------
// Fused QK^T + masked softmax. One CTA per (q-tile, z): 4 k-tiles, 48 MMAs,
// then two-pass TMEM readback: pass1 row max, pass2 exp + unnormalized P
// (bf16 hi/lo) + rowsum. linv[z*S+q] = 1/rowsum; AV epilogue applies it.
// Grid (4, 32), 256 thr.
// ---------------------------------------------------------------------------
#define QK_SMEM (32768 + 4 * 32768 + 1024)
__global__ __launch_bounds__(256) void qk_softmax(
    const bf16* __restrict__ Qh, const bf16* __restrict__ Ql, int qp,
    const bf16* __restrict__ Kh, const bf16* __restrict__ Kl, int kp,
    const int* __restrict__ kv_tok, int causal,
    bf16* __restrict__ Ph, bf16* __restrict__ Pl, float* __restrict__ linv)
{
    const int z = blockIdx.y, b = z >> 3, h = z & 7;
    const int bm = blockIdx.x * 128;
    const size_t qoff = (size_t)(b * S_) * qp + h * 64;
    const size_t koff = (size_t)(b * S_) * kp + h * 64;
#if HAS_TC
    __shared__ __align__(16) uint32_t s_tptr[4];
    __shared__ __align__(16) uint64_t s_mbar[1];
    __shared__ float s_mask[512];
    __shared__ float s_m[128][2];
    __shared__ float s_l[128][2];
    extern __shared__ char smem[];
    const uint32_t tiles = (s2u(smem) + 1023u) & ~1023u;
    const uint32_t tptr  = s2u(s_tptr);
    const uint32_t mbar  = s2u(&s_mbar[0]);

    const int t   = threadIdx.x;
    const int wid = t >> 5;
    if (wid == 0) TC_ALLOC(tptr, 512);
    if (t == 0) mbar_init(mbar, 1);

    // token mask (additive)
    s_mask[t]       = (kv_tok[b * S_ + t]       == 0) ? NEGV : 0.f;
    s_mask[t + 256] = (kv_tok[b * S_ + t + 256] == 0) ? NEGV : 0.f;
    __syncthreads();
    const uint32_t tmem = s_tptr[0];

    const int r  = t >> 3;
    const int ck = t & 7;
    const uint32_t aH = tiles, aL = tiles + 16384;
    #pragma unroll
    for (int it = 0; it < 4; it++) {
        int row = r + it * 32;
        uint32_t so = swz((uint32_t)(row * 128 + ck * 16));
        cpasync16(aH + so, Qh + qoff + (size_t)(bm + row) * qp + ck * 8);
        cpasync16(aL + so, Ql + qoff + (size_t)(bm + row) * qp + ck * 8);
    }
    #pragma unroll
    for (int kb = 0; kb < 4; kb++) {
        const uint32_t bH = tiles + 32768 + kb * 32768, bL = bH + 16384;
        #pragma unroll
        for (int it = 0; it < 4; it++) {
            int row = r + it * 32;
            uint32_t so = swz((uint32_t)(row * 128 + ck * 16));
            cpasync16(bH + so, Kh + koff + (size_t)(kb * 128 + row) * kp + ck * 8);
            cpasync16(bL + so, Kl + koff + (size_t)(kb * 128 + row) * kp + ck * 8);
        }
    }
    CP_COMMIT(); CP_WAIT0();
    FENCE_ASYNC();
    __syncthreads();
    if (t == 0) {
        uint64_t dah = mkdesc(aH), dal = mkdesc(aL);
        #pragma unroll
        for (int kb = 0; kb < 4; kb++) {
            const uint32_t bH = tiles + 32768 + kb * 32768;
            uint64_t dbh = mkdesc(bH), dbl = mkdesc(bH + 16384);
            const uint32_t acc = tmem + kb * 128;
            #pragma unroll
            for (int j = 0; j < 4; j++)
                mma_f16_ss(acc, dah + 2 * j, dbh + 2 * j, GIDESC, j ? 1u : 0u);
            #pragma unroll
            for (int j = 0; j < 4; j++)
                mma_f16_ss(acc, dah + 2 * j, dbl + 2 * j, GIDESC, 1u);
            #pragma unroll
            for (int j = 0; j < 4; j++)
                mma_f16_ss(acc, dal + 2 * j, dbh + 2 * j, GIDESC, 1u);
        }
        TC_COMMIT(mbar);
    }
    mbar_wait(mbar, 0);
    TC_FENCE_AFTER();

    const int sub = wid & 3, half = wid >> 2, lane = t & 31;
    const int row128 = sub * 32 + lane;        // 0..127
    const int rowg = bm + row128;              // global q
    // ---- pass 1: masked row max over this warp's 256 cols ----
    float mloc = -3.0e38f;
    #pragma unroll
    for (int kb = 0; kb < 4; kb++) {
        #pragma unroll
        for (int cc = 0; cc < 2; cc++) {
            const int col0 = half * 64 + cc * 32;
            uint32_t regs[32];
            TCLD32(regs, tmem + kb * 128 + col0);
            TC_WAIT_LD();
            const int kbase = kb * 128 + col0;
            #pragma unroll
            for (int j = 0; j < 32; j++) {
                int k = kbase + j;
                float v = __uint_as_float(regs[j]) * 0.125f + s_mask[k];
                if (causal && k > rowg) v += NEGV;
                mloc = fmaxf(mloc, v);
            }
        }
    }
    s_m[row128][half] = mloc;
    __syncthreads();
    const float m = fmaxf(s_m[row128][0], s_m[row128][1]);

    // ---- pass 2: exp, store unnormalized P, accumulate rowsum ----
    const size_t pbase = ((size_t)z * S_ + rowg) * S_;
    float lsum = 0.f;
    #pragma unroll
    for (int kb = 0; kb < 4; kb++) {
        #pragma unroll
        for (int cc = 0; cc < 2; cc++) {
            const int col0 = half * 64 + cc * 32;
            uint32_t regs[32];
            TCLD32(regs, tmem + kb * 128 + col0);
            TC_WAIT_LD();
            const int kbase = kb * 128 + col0;
            #pragma unroll
            for (int j = 0; j < 32; j += 4) {
                float4 e;
                float vv[4];
                #pragma unroll
                for (int u = 0; u < 4; u++) {
                    int k = kbase + j + u;
                    float v = __uint_as_float(regs[j + u]) * 0.125f + s_mask[k];
                    if (causal && k > rowg) v += NEGV;
                    vv[u] = __expf(v - m);
                    lsum += vv[u];
                }
                e.x = vv[0]; e.y = vv[1]; e.z = vv[2]; e.w = vv[3];
                split_store4(Ph, Pl, pbase + kbase + j, e);
            }
        }
    }
    s_l[row128][half] = lsum;
    __syncthreads();
    if (half == 0)
        linv[(size_t)z * S_ + rowg] = 1.f / (s_l[row128][0] + s_l[row128][1]);

    __syncthreads();
    if (wid == 0) TC_DEALLOC(tmem, 512);
#else
    const int t = threadIdx.x;
    for (int rr = t; rr < 128; rr += 256) {
        int rowg = bm + rr;
        float m = -3.0e38f;
        float sc[512];
        for (int k = 0; k < 512; k++) {
            float acc = 0.f;
            for (int d = 0; d < 64; d++) {
                float qv = __bfloat162float(Qh[qoff + (size_t)rowg * qp + d])
                         + __bfloat162float(Ql[qoff + (size_t)rowg * qp + d]);
                float kv = __bfloat162float(Kh[koff + (size_t)k * kp + d])
                         + __bfloat162float(Kl[koff + (size_t)k * kp + d]);
                acc += qv * kv;
            }
            acc *= 0.125f;
            if (kv_tok[b * S_ + k] == 0) acc += NEGV;
            if (causal && k > rowg) acc += NEGV;
            sc[k] = acc;
            m = fmaxf(m, acc);
        }
        float l = 0.f;
        for (int k = 0; k < 512; k++) {
            float e = __expf(sc[k] - m);
            l += e;
            size_t idx = ((size_t)z * S_ + rowg) * S_ + k;
            bf16 hh2 = __float2bfloat16_rn(e);
            Ph[idx] = hh2;
            Pl[idx] = __float2bfloat16_rn(e - __bfloat162float(hh2));
        }
        linv[(size_t)z * S_ + rowg] = 1.f / l;
    }
#endif
}

// ---------------------------------------------------------------------------
// AV GEMM: out = (P_unnorm @ V) * linv, grid (1,4,32), 3-stage pipeline
// ---------------------------------------------------------------------------
#define AV_STAGE  49152
#define AV_NSTG   3
#define AV_SMEM   (AV_NSTG * AV_STAGE + 1024)
#define AVIDESC   IDESC_N(64)
__global__ __launch_bounds__(256) void av_gemm(
    const bf16* __restrict__ Ph, const bf16* __restrict__ Pl,
    const bf16* __restrict__ Vth, const bf16* __restrict__ Vtl,
    const float* __restrict__ linv,
    bf16* __restrict__ Oh, bf16* __restrict__ Ol)
{
    const int z = blockIdx.z, b = z >> 3, h = z & 7;
    const int bm = blockIdx.y * 128;
    const bf16* Pzh = Ph  + (size_t)z * S_ * S_;
    const bf16* Pzl = Pl  + (size_t)z * S_ * S_;
    const bf16* Vzh = Vth + (size_t)z * 64 * S_;
    const bf16* Vzl = Vtl + (size_t)z * 64 * S_;
#if HAS_TC
    __shared__ __align__(16) uint32_t s_tptr[4];
    __shared__ __align__(16) uint64_t s_mbar[AV_NSTG];
    extern __shared__ char smem[];
    const uint32_t tiles = (s2u(smem) + 1023u) & ~1023u;
    const uint32_t tptr  = s2u(s_tptr);
    uint32_t mb[AV_NSTG];
    #pragma unroll
    for (int i = 0; i < AV_NSTG; i++) mb[i] = s2u(&s_mbar[i]);

    const int t   = threadIdx.x;
    const int wid = t >> 5;
    if (wid == 0) TC_ALLOC(tptr, 128);
    if (t == 0) {
        #pragma unroll
        for (int i = 0; i < AV_NSTG; i++) mbar_init(mb[i], 1);
    }
    __syncthreads();
    const uint32_t tmem = s_tptr[0];

    const int r  = t >> 3;
    const int ck = t & 7;
    int use[AV_NSTG];
    #pragma unroll
    for (int i = 0; i < AV_NSTG; i++) use[i] = 0;

    auto load_chunk = [&](int c, int s) {
        const uint32_t base = tiles + s * AV_STAGE;
        const uint32_t aH = base, aL = base + 16384;
        const uint32_t bH = base + 32768, bL = base + 40960;
        const int k0 = c << 6;
        #pragma unroll
        for (int it = 0; it < 4; it++) {
            int row = r + it * 32;
            size_t g = (size_t)(bm + row) * S_ + k0 + ck * 8;
            uint32_t so = swz((uint32_t)(row * 128 + ck * 16));
            cpasync16(aH + so, Pzh + g);
            cpasync16(aL + so, Pzl + g);
        }
        #pragma unroll
        for (int it = 0; it < 2; it++) {
            int row = r + it * 32;
            size_t g = (size_t)row * S_ + k0 + ck * 8;
            uint32_t so = swz((uint32_t)(row * 128 + ck * 16));
            cpasync16(bH + so, Vzh + g);
            cpasync16(bL + so, Vzl + g);
        }
        CP_COMMIT();
    };

    const int nch = S_ >> 6;
    load_chunk(0, 0);
    for (int c = 0; c < nch; c++) {
        const int s = c % AV_NSTG;
        if (c + 1 < nch) {
            const int s2 = (c + 1) % AV_NSTG;
            if (use[s2] > 0) mbar_wait(mb[s2], (use[s2] - 1) & 1);
            load_chunk(c + 1, s2);
            CP_WAIT1();
        } else {
            CP_WAIT0();
        }
        FENCE_ASYNC();
        __syncthreads();
        if (t == 0) {
            const uint32_t base = tiles + s * AV_STAGE;
            uint64_t dah = mkdesc(base),         dal = mkdesc(base + 16384);
            uint64_t dbh = mkdesc(base + 32768), dbl = mkdesc(base + 40960);
            #pragma unroll
            for (int j = 0; j < 4; j++)
                mma_f16_ss(tmem, dah + 2 * j, dbh + 2 * j, AVIDESC,
                           (c == 0 && j == 0) ? 0u : 1u);
            #pragma unroll
            for (int j = 0; j < 4; j++)
                mma_f16_ss(tmem, dah + 2 * j, dbl + 2 * j, AVIDESC, 1u);
            #pragma unroll
            for (int j = 0; j < 4; j++)
                mma_f16_ss(tmem, dal + 2 * j, dbh + 2 * j, AVIDESC, 1u);
            TC_COMMIT(mb[s]);
        }
        use[s]++;
    }
    #pragma unroll
    for (int i = 0; i < AV_NSTG; i++)
        if (use[i] > 0) mbar_wait(mb[i], (use[i] - 1) & 1);
    TC_FENCE_AFTER();
    {
        const int sub = wid & 3, half = wid >> 2, lane = t & 31;
        const int rowg = bm + sub * 32 + lane;
        const float sc = linv[(size_t)z * S_ + rowg];
        const int col0 = half * 32;
        uint32_t regs[32];
        TCLD32(regs, tmem + col0);
        TC_WAIT_LD();
        #pragma unroll
        for (int j = 0; j < 32; j += 4) {
            float4 v;
            v.x = __uint_as_float(regs[j])     * sc;
            v.y = __uint_as_float(regs[j + 1]) * sc;
            v.z = __uint_as_float(regs[j + 2]) * sc;
            v.w = __uint_as_float(regs[j + 3]) * sc;
            size_t idx = ((size_t)(b * S_) + rowg) * D_ + h * 64 + col0 + j;
            split_store4(Oh, Ol, idx, v);
        }
    }
    __syncthreads();
    if (wid == 0) TC_DEALLOC(tmem, 128);
#else
    const int t = threadIdx.x;
    for (int idx = t; idx < 128 * 64; idx += 256) {
        int rr = idx >> 6, cc = idx & 63;
        float acc = 0.f;
        for (int k = 0; k < S_; k++) {
            float pv = __bfloat162float(Pzh[(size_t)(bm + rr) * S_ + k])
                     + __bfloat162float(Pzl[(size_t)(bm + rr) * S_ + k]);
            float vv = __bfloat162float(Vzh[(size_t)cc * S_ + k])
                     + __bfloat162float(Vzl[(size_t)cc * S_ + k]);
            acc += pv * vv;
        }
        acc *= linv[(size_t)z * S_ + bm + rr];
        size_t oidx = ((size_t)(b * S_) + bm + rr) * D_ + h * 64 + cc;
        bf16 hh2 = __float2bfloat16_rn(acc);
        Oh[oidx] = hh2;
        Ol[oidx] = __float2bfloat16_rn(acc - __bfloat162float(hh2));
    }
#endif
}

// ---------------------------------------------------------------------------
// Host driver
// ---------------------------------------------------------------------------
static inline void run_bgemm(int epi, const bf16* Ah, const bf16* Al,
                             const bf16* Bh, const bf16* Bl, const float* bias,
                             float* C, bf16* Ch, bf16* Cl,
                             bf16* Vh, bf16* Vl, int vsplit,
                             int M, int N, int K)
{
    dim3 grid(N / 128, M / 128);
    if (epi == 0)
        bgemm<0><<<grid, 256, SMEM_GEMM>>>(Ah, Al, Bh, Bl, bias, C, Ch, Cl, Vh, Vl, vsplit, M, N, K);
    else if (epi == 1)
        bgemm<1><<<grid, 256, SMEM_GEMM>>>(Ah, Al, Bh, Bl, bias, C, Ch, Cl, Vh, Vl, vsplit, M, N, K);
    else if (epi == 3)
        bgemm<3><<<grid, 256, SMEM_GEMM>>>(Ah, Al, Bh, Bl, bias, C, Ch, Cl, Vh, Vl, vsplit, M, N, K);
    else if (epi == 4)
        bgemm<4><<<grid, 256, SMEM_GEMM>>>(Ah, Al, Bh, Bl, bias, C, Ch, Cl, Vh, Vl, vsplit, M, N, K);
    else
        bgemm<5><<<grid, 256, SMEM_GEMM>>>(Ah, Al, Bh, Bl, bias, C, Ch, Cl, Vh, Vl, vsplit, M, N, K);
}

extern "C" void kernel_launch(void* const* d_in, const int* in_sizes, int n_in,
                              void* d_out, int out_size)
{
    const int DDi = D_ * D_;

    int iEWq, iEWk, iEWv, iEWo, iEW1, iEb1, iEW2, iEb2;
    int iDWq1, iDWk1, iDWv1, iDWo1, iDWq2, iDWk2, iDWv2, iDWo2;
    int iDW1, iDb1, iDW2, iDb2, iWout, iBout;
    if (n_in >= 8 && in_sizes[7] == L_ * DDi) {
        iEWq = 3; iEWk = 4; iEWv = 5; iEWo = 6;
        iDWq1 = 7; iDWk1 = 8; iDWv1 = 9; iDWo1 = 10;
        iDWq2 = 11; iDWk2 = 12; iDWv2 = 13; iDWo2 = 14;
        iEW1 = 15; iEb1 = 16; iEW2 = 17; iEb2 = 18;
        iDW1 = 19; iDb1 = 20; iDW2 = 21; iDb2 = 22;
        iWout = 23; iBout = 24;
    } else {
        iEWq = 3; iEWk = 4; iEWv = 5; iEWo = 6;
        iEW1 = 7; iEb1 = 8; iEW2 = 9; iEb2 = 10;
        iDWq1 = 11; iDWk1 = 12; iDWv1 = 13; iDWo1 = 14;
        iDWq2 = 15; iDWk2 = 16; iDWv2 = 17; iDWo2 = 18;
        iDW1 = 19; iDb1 = 20; iDW2 = 21; iDb2 = 22;
        iWout = 23; iBout = 24;
    }

    const int*   src  = (const int*)d_in[0];
    const int*   tgt  = (const int*)d_in[1];
    const float* emb  = (const float*)d_in[2];
    const float* eWq  = (const float*)d_in[iEWq];
    const float* eWk  = (const float*)d_in[iEWk];
    const float* eWv  = (const float*)d_in[iEWv];
    const float* eWo  = (const float*)d_in[iEWo];
    const float* eW1  = (const float*)d_in[iEW1];
    const float* eb1  = (const float*)d_in[iEb1];
    const float* eW2  = (const float*)d_in[iEW2];
    const float* eb2  = (const float*)d_in[iEb2];
    const float* dWq1 = (const float*)d_in[iDWq1];
    const float* dWk1 = (const float*)d_in[iDWk1];
    const float* dWv1 = (const float*)d_in[iDWv1];
    const float* dWo1 = (const float*)d_in[iDWo1];
    const float* dWq2 = (const float*)d_in[iDWq2];
    const float* dWk2 = (const float*)d_in[iDWk2];
    const float* dWv2 = (const float*)d_in[iDWv2];
    const float* dWo2 = (const float*)d_in[iDWo2];
    const float* dW1  = (const float*)d_in[iDW1];
    const float* db1  = (const float*)d_in[iDb1];
    const float* dW2  = (const float*)d_in[iDW2];
    const float* db2  = (const float*)d_in[iDb2];
    const float* Wout = (const float*)d_in[iWout];
    const float* bout = (const float*)d_in[iBout];

    cudaFuncSetAttribute(bgemm<0>, cudaFuncAttributeMaxDynamicSharedMemorySize, SMEM_GEMM);
    cudaFuncSetAttribute(bgemm<1>, cudaFuncAttributeMaxDynamicSharedMemorySize, SMEM_GEMM);
    cudaFuncSetAttribute(bgemm<3>, cudaFuncAttributeMaxDynamicSharedMemorySize, SMEM_GEMM);
    cudaFuncSetAttribute(bgemm<4>, cudaFuncAttributeMaxDynamicSharedMemorySize, SMEM_GEMM);
    cudaFuncSetAttribute(bgemm<5>, cudaFuncAttributeMaxDynamicSharedMemorySize, SMEM_GEMM);
    cudaFuncSetAttribute(bgemm2,   cudaFuncAttributeMaxDynamicSharedMemorySize, SMEM_GEMM2);
    cudaFuncSetAttribute(qk_softmax, cudaFuncAttributeMaxDynamicSharedMemorySize, QK_SMEM);
    cudaFuncSetAttribute(av_gemm,  cudaFuncAttributeMaxDynamicSharedMemorySize, AV_SMEM);

    float *x, *a, *out, *f, *y0, *o, *linv;
    cudaGetSymbolAddress((void**)&x,   g_x);
    cudaGetSymbolAddress((void**)&a,   g_a);
    cudaGetSymbolAddress((void**)&out, g_out);
    cudaGetSymbolAddress((void**)&f,   g_f);
    cudaGetSymbolAddress((void**)&y0,  g_y0);
    cudaGetSymbolAddress((void**)&o,   g_o);
    cudaGetSymbolAddress((void**)&linv, g_linv);

    bf16 *xh, *xl, *outh, *outl, *ath, *atl, *y0h, *y0l, *oh, *ol, *hh, *hl, *wh, *wl;
    bf16 *qkvh, *qkvl, *kv2h, *kv2l, *q2h, *q2l, *ph, *pl, *vth, *vtl;
    cudaGetSymbolAddress((void**)&xh,   g_xh);
    cudaGetSymbolAddress((void**)&xl,   g_xl);
    cudaGetSymbolAddress((void**)&outh, g_outh);
    cudaGetSymbolAddress((void**)&outl, g_outl);
    cudaGetSymbolAddress((void**)&ath,  g_ath);
    cudaGetSymbolAddress((void**)&atl,  g_atl);
    cudaGetSymbolAddress((void**)&y0h,  g_y0h);
    cudaGetSymbolAddress((void**)&y0l,  g_y0l);
    cudaGetSymbolAddress((void**)&oh,   g_oh);
    cudaGetSymbolAddress((void**)&ol,   g_ol);
    cudaGetSymbolAddress((void**)&hh,   g_hh);
    cudaGetSymbolAddress((void**)&hl,   g_hl);
    cudaGetSymbolAddress((void**)&wh,   g_wh);
    cudaGetSymbolAddress((void**)&wl,   g_wl);
    cudaGetSymbolAddress((void**)&qkvh, g_qkvh);
    cudaGetSymbolAddress((void**)&qkvl, g_qkvl);
    cudaGetSymbolAddress((void**)&kv2h, g_kv2h);
    cudaGetSymbolAddress((void**)&kv2l, g_kv2l);
    cudaGetSymbolAddress((void**)&q2h,  g_q2h);
    cudaGetSymbolAddress((void**)&q2l,  g_q2l);
    cudaGetSymbolAddress((void**)&ph,   g_ph);
    cudaGetSymbolAddress((void**)&pl,   g_pl);
    cudaGetSymbolAddress((void**)&vth,  g_vth);
    cudaGetSymbolAddress((void**)&vtl,  g_vtl);

    // ---- Weight conversion: ONE launch ----
    {
        const int li = L_ - 1;
        WcvTable tab;
        int ts = 0, ne = 0;
        auto add = [&](const float* s, unsigned long long dst,
                       unsigned long long ls, int K, int N, int nz) {
            WcvEntry& E = tab.e[ne++];
            E.src = s; E.dst = dst; E.lstride = ls;
            E.K = K; E.N = N; E.ntx = N / 32; E.nty = K / 32; E.nz = nz;
            E.tstart = ts;
            ts += (N / 32) * (K / 32) * nz;
        };
        add(eWq, O_EQKV,          3 * DD, D_, D_, 6);
        add(eWk, O_EQKV + DD,     3 * DD, D_, D_, 6);
        add(eWv, O_EQKV + 2 * DD, 3 * DD, D_, D_, 6);
        add(eWo, O_EWO, DD,  D_, D_, 6);
        add(eW1, O_EW1, DDF, D_, DFF_, 6);
        add(eW2, O_EW2, DDF, DFF_, D_, 6);
        add(dWq1 + (size_t)li * DDi, O_DQKV1,          0, D_, D_, 1);
        add(dWk1 + (size_t)li * DDi, O_DQKV1 + DD,     0, D_, D_, 1);
        add(dWv1 + (size_t)li * DDi, O_DQKV1 + 2 * DD, 0, D_, D_, 1);
        add(dWo1 + (size_t)li * DDi, O_DWO1, 0, D_, D_, 1);
        add(dWq2 + (size_t)li * DDi, O_DWQ2, 0, D_, D_, 1);
        add(dWk2 + (size_t)li * DDi, O_DKV2,      0, D_, D_, 1);
        add(dWv2 + (size_t)li * DDi, O_DKV2 + DD, 0, D_, D_, 1);
        add(dWo2 + (size_t)li * DDi, O_DWO2, 0, D_, D_, 1);
        add(dW1 + (size_t)li * (D_ * DFF_), O_DW1, 0, D_, DFF_, 1);
        add(dW2 + (size_t)li * (D_ * DFF_), O_DW2, 0, DFF_, D_, 1);
        add(Wout, O_WOUT, 0, D_, V_, 1);
        wconv_all<<<ts, dim3(32, 8)>>>(tab, ne, wh, wl);
    }

    const dim3 qkGrid(4, 32), avGrid(1, 4, 32);
    const int li = L_ - 1;

    // ---------------- Encoder ----------------
    embed_kernel<<<BS_, 128>>>(src, emb, x, xh, xl);
    for (int i = 0; i < L_; i++) {
        run_bgemm(5, xh, xl, wh + O_EQKV + (size_t)i * 3 * DD, wl + O_EQKV + (size_t)i * 3 * DD,
                  nullptr, nullptr, qkvh, qkvl, vth, vtl, 1024, BS_, 3 * D_, D_);
        qk_softmax<<<qkGrid, 256, QK_SMEM>>>(qkvh, qkvl, 3 * D_,
                                             qkvh + D_, qkvl + D_, 3 * D_,
                                             src, 0, ph, pl, linv);
        av_gemm<<<avGrid, 256, AV_SMEM>>>(ph, pl, vth, vtl, linv, ath, atl);
        run_bgemm(0, ath, atl, wh + O_EWO + (size_t)i * DD, wl + O_EWO + (size_t)i * DD,
                  nullptr, a, nullptr, nullptr, nullptr, nullptr, 0, BS_, D_, D_);
        add_ln_kernel<<<BS_, 128>>>(x, a, out, outh, outl);
        run_bgemm(3, outh, outl, wh + O_EW1 + (size_t)i * DDF, wl + O_EW1 + (size_t)i * DDF,
                  eb1 + (size_t)i * DFF_, nullptr, hh, hl, nullptr, nullptr, 0, BS_, DFF_, D_);
        run_bgemm(1, hh, hl, wh + O_EW2 + (size_t)i * DDF, wl + O_EW2 + (size_t)i * DDF,
                  eb2 + (size_t)i * D_, f, nullptr, nullptr, nullptr, nullptr, 0, BS_, D_, DFF_);
        add_ln_kernel<<<BS_, 128>>>(a, f, x, xh, xl);
    }

    // ---------------- Decoder (last layer only) ----------------
    embed_kernel<<<BS_, 128>>>(tgt, emb, y0, y0h, y0l);
    {
        run_bgemm(5, y0h, y0l, wh + O_DQKV1, wl + O_DQKV1, nullptr, nullptr,
                  qkvh, qkvl, vth, vtl, 1024, BS_, 3 * D_, D_);
        qk_softmax<<<qkGrid, 256, QK_SMEM>>>(qkvh, qkvl, 3 * D_,
                                             qkvh + D_, qkvl + D_, 3 * D_,
                                             tgt, 1, ph, pl, linv);
        av_gemm<<<avGrid, 256, AV_SMEM>>>(ph, pl, vth, vtl, linv, ath, atl);
        run_bgemm(0, ath, atl, wh + O_DWO1, wl + O_DWO1, nullptr, a,
                  nullptr, nullptr, nullptr, nullptr, 0, BS_, D_, D_);
        add_ln_kernel<<<BS_, 128>>>(y0, a, o, oh, ol);

        run_bgemm(4, oh, ol, wh + O_DWQ2, wl + O_DWQ2, nullptr, nullptr,
                  q2h, q2l, nullptr, nullptr, 0, BS_, D_, D_);
        run_bgemm(5, xh, xl, wh + O_DKV2, wl + O_DKV2, nullptr, nullptr,
                  kv2h, kv2l, vth, vtl, 512, BS_, 2 * D_, D_);
        qk_softmax<<<qkGrid, 256, QK_SMEM>>>(q2h, q2l, D_, kv2h, kv2l, 2 * D_,
                                             src, 0, ph, pl, linv);
        av_gemm<<<avGrid, 256, AV_SMEM>>>(ph, pl, vth, vtl, linv, ath, atl);
        run_bgemm(0, ath, atl, wh + O_DWO2, wl + O_DWO2, nullptr, a,
                  nullptr, nullptr, nullptr, nullptr, 0, BS_, D_, D_);
        add_ln_kernel<<<BS_, 128>>>(o, a, o, oh, ol);

        run_bgemm(3, oh, ol, wh + O_DW1, wl + O_DW1, db1 + (size_t)li * DFF_,
                  nullptr, hh, hl, nullptr, nullptr, 0, BS_, DFF_, D_);
        run_bgemm(1, hh, hl, wh + O_DW2, wl + O_DW2, db2 + (size_t)li * D_,
                  f, nullptr, nullptr, nullptr, nullptr, 0, BS_, D_, DFF_);
        add_ln_kernel<<<BS_, 128>>>(o, f, o, oh, ol);
    }

    // ---------------- Logits (MT=2) ----------------
    bgemm2<<<dim3(V_ / 128, BS_ / 256), 256, SMEM_GEMM2>>>(
        oh, ol, wh + O_WOUT, wl + O_WOUT, bout, (float*)d_out, BS_, V_, D_);
}

// round 13
// speedup vs baseline: 1.1103x; 1.1103x over previous
#include <cuda_runtime.h>
#include <cuda_bf16.h>
#include <math.h>
#include <stdint.h>

#define D_    512
#define S_    512
#define B_    4
#define H_    8
#define L_    6
#define DFF_  2048
#define V_    32000
#define BS_   (B_ * S_)
#define NEGV  (-1e10f)

#if defined(__CUDA_ARCH_FEAT_SM103_ALL) || defined(__CUDA_ARCH_FEAT_SM100_ALL) || defined(__CUDA_ARCH_FEAT_SM101_ALL)
#define HAS_TC 1
#else
#define HAS_TC 0
#endif

typedef __nv_bfloat16  bf16;
typedef __nv_bfloat162 bf162;

// ---------------------------------------------------------------------------
// Scratch (device globals)
// ---------------------------------------------------------------------------
__device__ float g_x[BS_ * D_];
__device__ float g_a[BS_ * D_];
__device__ float g_out[BS_ * D_];
__device__ float g_f[BS_ * D_];
__device__ float g_y0[BS_ * D_];
__device__ float g_o[BS_ * D_];

__device__ bf16 g_xh[BS_ * D_],   g_xl[BS_ * D_];
__device__ bf16 g_outh[BS_ * D_], g_outl[BS_ * D_];
__device__ bf16 g_ath[BS_ * D_],  g_atl[BS_ * D_];
__device__ bf16 g_y0h[BS_ * D_],  g_y0l[BS_ * D_];
__device__ bf16 g_oh[BS_ * D_],   g_ol[BS_ * D_];
__device__ bf16 g_hh[BS_ * DFF_], g_hl[BS_ * DFF_];

// Attention scratch
__device__ bf16  g_qkvh[BS_ * 3 * D_], g_qkvl[BS_ * 3 * D_];
__device__ bf16  g_kv2h[BS_ * 2 * D_], g_kv2l[BS_ * 2 * D_];
__device__ bf16  g_q2h[BS_ * D_],      g_q2l[BS_ * D_];
__device__ float g_scores[32ull * S_ * S_];
__device__ bf16  g_ph[32ull * S_ * S_], g_pl[32ull * S_ * S_];
__device__ bf16  g_vth[32ull * 64 * S_], g_vtl[32ull * 64 * S_];

// Transposed+split weights arena (element offsets). Per-layer-contiguous QKV.
#define DD      (512ull * 512ull)
#define DDF     (512ull * 2048ull)
#define O_EQKV  0ull
#define O_EWO   4718592ull
#define O_EW1   6291456ull
#define O_EW2   12582912ull
#define O_DQKV1 18874368ull
#define O_DWO1  19660800ull
#define O_DWQ2  19922944ull
#define O_DKV2  20185088ull
#define O_DWO2  20709376ull
#define O_DW1   20971520ull
#define O_DW2   22020096ull
#define O_WOUT  23068672ull
#define NWTOT   39452672ull
__device__ bf16 g_wh[NWTOT];
__device__ bf16 g_wl[NWTOT];

// ---------------------------------------------------------------------------
// PTX helpers
// ---------------------------------------------------------------------------
__device__ __forceinline__ uint32_t s2u(const void* p) {
    uint32_t a;
    asm("{ .reg .u64 t; cvta.to.shared.u64 t, %1; cvt.u32.u64 %0, t; }"
        : "=r"(a) : "l"(p));
    return a;
}
__device__ __forceinline__ uint32_t swz(uint32_t o) { return o ^ ((o >> 3) & 0x70u); }

__device__ __forceinline__ void mbar_init(uint32_t a, uint32_t c) {
    asm volatile("mbarrier.init.shared.b64 [%0], %1;" :: "r"(a), "r"(c) : "memory");
}
__device__ __forceinline__ void mbar_wait(uint32_t a, uint32_t ph) {
    uint32_t done;
    asm volatile(
        "{\n\t.reg .pred p;\n\t"
        "mbarrier.try_wait.parity.acquire.cta.shared::cta.b64 p, [%1], %2;\n\t"
        "selp.b32 %0,1,0,p;\n\t}"
        : "=r"(done) : "r"(a), "r"(ph) : "memory");
    if (!done) {
        asm volatile(
            "{\n\t.reg .pred P1;\n\t"
            "WAIT_LOOP_%=:\n\t"
            "mbarrier.try_wait.parity.acquire.cta.shared::cta.b64 P1, [%0], %1, 0x989680;\n\t"
            "@P1 bra.uni WAIT_DONE_%=;\n\t"
            "bra.uni WAIT_LOOP_%=;\n\t"
            "WAIT_DONE_%=:\n\t}"
            :: "r"(a), "r"(ph) : "memory");
    }
}
#define FENCE_ASYNC() asm volatile("fence.proxy.async.shared::cta;" ::: "memory")

__device__ __forceinline__ void cpasync16(uint32_t saddr, const void* g) {
    asm volatile("cp.async.cg.shared.global [%0], [%1], 16;"
                 :: "r"(saddr), "l"(g));
}
#define CP_COMMIT() asm volatile("cp.async.commit_group;" ::: "memory")
#define CP_WAIT1()  asm volatile("cp.async.wait_group 1;" ::: "memory")
#define CP_WAIT0()  asm volatile("cp.async.wait_group 0;" ::: "memory")

#if HAS_TC
__device__ __forceinline__ uint64_t mkdesc(uint32_t addr) {
    const uint64_t base = (2ull << 61) | (1ull << 46) | (64ull << 32) | (1ull << 16);
    return base | ((uint64_t)(addr >> 4) & 0x3FFFull);
}
__device__ __forceinline__ void mma_f16_ss(uint32_t d, uint64_t ad, uint64_t bd,
                                           uint32_t idesc, uint32_t en) {
    asm volatile(
        "{\n\t.reg .pred p;\n\tsetp.ne.u32 p, %5, 0;\n\t"
        "tcgen05.mma.cta_group::1.kind::f16 [%0], %1, %2, %3, {%4,%4,%4,%4}, p;\n\t}"
        :: "r"(d), "l"(ad), "l"(bd), "r"(idesc), "r"(0u), "r"(en) : "memory");
}
#define TC_ALLOC(sa, n)  asm volatile("tcgen05.alloc.cta_group::1.sync.aligned.shared::cta.b32 [%0], %1;" :: "r"(sa), "r"(n) : "memory")
#define TC_DEALLOC(t, n) asm volatile("tcgen05.dealloc.cta_group::1.sync.aligned.b32 %0, %1;" :: "r"(t), "r"(n))
#define TC_COMMIT(mb)    asm volatile("tcgen05.commit.cta_group::1.mbarrier::arrive::one.shared::cluster.b64 [%0];" :: "r"(mb) : "memory")
#define TC_FENCE_AFTER() asm volatile("tcgen05.fence::after_thread_sync;" ::: "memory")
#define TC_WAIT_LD()     asm volatile("tcgen05.wait::ld.sync.aligned;" ::: "memory")

#define TCLD32(r, a) \
    asm volatile( \
        "tcgen05.ld.sync.aligned.32x32b.x32.b32 " \
        "{%0, %1, %2, %3, %4, %5, %6, %7, " \
        " %8, %9, %10, %11, %12, %13, %14, %15, " \
        " %16, %17, %18, %19, %20, %21, %22, %23, " \
        " %24, %25, %26, %27, %28, %29, %30, %31}, [%32];" \
        : "=r"((r)[0]),  "=r"((r)[1]),  "=r"((r)[2]),  "=r"((r)[3]), \
          "=r"((r)[4]),  "=r"((r)[5]),  "=r"((r)[6]),  "=r"((r)[7]), \
          "=r"((r)[8]),  "=r"((r)[9]),  "=r"((r)[10]), "=r"((r)[11]), \
          "=r"((r)[12]), "=r"((r)[13]), "=r"((r)[14]), "=r"((r)[15]), \
          "=r"((r)[16]), "=r"((r)[17]), "=r"((r)[18]), "=r"((r)[19]), \
          "=r"((r)[20]), "=r"((r)[21]), "=r"((r)[22]), "=r"((r)[23]), \
          "=r"((r)[24]), "=r"((r)[25]), "=r"((r)[26]), "=r"((r)[27]), \
          "=r"((r)[28]), "=r"((r)[29]), "=r"((r)[30]), "=r"((r)[31]) \
        : "r"(a))
#endif  // HAS_TC

#define IDESC_N(n) ((1u<<4)|(1u<<7)|(1u<<10)|(((n)/8u)<<17)|(8u<<24))

__device__ __forceinline__ void split_store4(bf16* __restrict__ Hh,
                                             bf16* __restrict__ Hl,
                                             size_t idx, float4 v) {
    bf16 hx = __float2bfloat16_rn(v.x), hy = __float2bfloat16_rn(v.y);
    bf16 hz = __float2bfloat16_rn(v.z), hw = __float2bfloat16_rn(v.w);
    bf16 lx = __float2bfloat16_rn(v.x - __bfloat162float(hx));
    bf16 ly = __float2bfloat16_rn(v.y - __bfloat162float(hy));
    bf16 lz = __float2bfloat16_rn(v.z - __bfloat162float(hz));
    bf16 lw = __float2bfloat16_rn(v.w - __bfloat162float(hw));
    bf162 p;
    p.x = hx; p.y = hy; *(bf162*)(Hh + idx)     = p;
    p.x = hz; p.y = hw; *(bf162*)(Hh + idx + 2) = p;
    p.x = lx; p.y = ly; *(bf162*)(Hl + idx)     = p;
    p.x = lz; p.y = lw; *(bf162*)(Hl + idx + 2) = p;
}

// ---------------------------------------------------------------------------
// Mega weight-conversion kernel
// ---------------------------------------------------------------------------
struct WcvEntry {
    const float* src;
    unsigned long long dst;
    unsigned long long lstride;
    int K, N, ntx, nty, nz, tstart;
};
struct WcvTable { WcvEntry e[17]; };

__global__ __launch_bounds__(256) void wconv_all(
    WcvTable tab, int nent, bf16* __restrict__ oh, bf16* __restrict__ ol)
{
    __shared__ float tile[32][33];
    int tid = blockIdx.x;
    int i = 0;
    while (i + 1 < nent && tid >= tab.e[i + 1].tstart) i++;
    const WcvEntry E = tab.e[i];
    int t = tid - E.tstart;
    int per_z = E.ntx * E.nty;
    int z  = t / per_z;
    int rm = t - z * per_z;
    int txb = rm % E.ntx, tyb = rm / E.ntx;
    const int n0 = txb * 32, k0 = tyb * 32;
    const int K = E.K, N = E.N;
    const float* Wb = E.src + (size_t)z * K * N;
    bf16* ohb = oh + E.dst + (size_t)z * E.lstride;
    bf16* olb = ol + E.dst + (size_t)z * E.lstride;

    const int tx = threadIdx.x, ty = threadIdx.y;
    #pragma unroll
    for (int ii = 0; ii < 4; ii++)
        tile[ty + 8 * ii][tx] = Wb[(size_t)(k0 + ty + 8 * ii) * N + n0 + tx];
    __syncthreads();
    #pragma unroll
    for (int ii = 0; ii < 4; ii++) {
        float v = tile[tx][ty + 8 * ii];
        int n = n0 + ty + 8 * ii, k = k0 + tx;
        size_t idx = (size_t)n * K + k;
        bf16 h = __float2bfloat16_rn(v);
        ohb[idx] = h;
        olb[idx] = __float2bfloat16_rn(v - __bfloat162float(h));
    }
}

// ---------------------------------------------------------------------------
// Embedding + positional encoding (+ bf16 split)
// ---------------------------------------------------------------------------
__global__ __launch_bounds__(128) void embed_kernel(
    const int* __restrict__ ids, const float* __restrict__ emb,
    float* __restrict__ out, bf16* __restrict__ oh, bf16* __restrict__ ol)
{
    const int row = blockIdx.x;
    const int s   = row & (S_ - 1);
    const int tok = ids[row];
    const int t   = threadIdx.x;
    const float c = -logf(10000.0f) / (float)D_;
    float4 v;
    float tmp[4];
    #pragma unroll
    for (int j = 0; j < 4; j++) {
        int d  = t * 4 + j;
        int tj = d >> 1;
        float div = expf((float)(2 * tj) * c);
        float ang = (float)s * div;
        float pe  = (d & 1) ? cosf(ang) : sinf(ang);
        tmp[j] = emb[(size_t)tok * D_ + d] + pe;
    }
    v.x = tmp[0]; v.y = tmp[1]; v.z = tmp[2]; v.w = tmp[3];
    size_t base = (size_t)row * D_ + t * 4;
    *(float4*)(out + base) = v;
    split_store4(oh, ol, base, v);
}

// ---------------------------------------------------------------------------
// Fused residual + LayerNorm (+ bf16 split)
// ---------------------------------------------------------------------------
__global__ __launch_bounds__(128) void add_ln_kernel(
    const float* __restrict__ A, const float* __restrict__ Bv,
    float* __restrict__ Out, bf16* __restrict__ Oh, bf16* __restrict__ Ol)
{
    const int row = blockIdx.x;
    const int t   = threadIdx.x;
    const size_t base = (size_t)row * D_ + t * 4;
    float4 a = *(const float4*)(A + base);
    float4 b = *(const float4*)(Bv + base);
    float4 vv;
    vv.x = a.x + b.x; vv.y = a.y + b.y; vv.z = a.z + b.z; vv.w = a.w + b.w;

    float s  = vv.x + vv.y + vv.z + vv.w;
    float sq = vv.x * vv.x + vv.y * vv.y + vv.z * vv.z + vv.w * vv.w;
    __shared__ float redS[4], redQ[4];
    #pragma unroll
    for (int off = 16; off > 0; off >>= 1) {
        s  += __shfl_xor_sync(0xffffffffu, s,  off);
        sq += __shfl_xor_sync(0xffffffffu, sq, off);
    }
    const int wid = t >> 5, lane = t & 31;
    if (lane == 0) { redS[wid] = s; redQ[wid] = sq; }
    __syncthreads();
    s  = redS[0] + redS[1] + redS[2] + redS[3];
    sq = redQ[0] + redQ[1] + redQ[2] + redQ[3];
    float mean = s * (1.0f / D_);
    float var  = sq * (1.0f / D_) - mean * mean;
    float inv  = rsqrtf(var + 1e-5f);
    float4 o;
    o.x = (vv.x - mean) * inv; o.y = (vv.y - mean) * inv;
    o.z = (vv.z - mean) * inv; o.w = (vv.w - mean) * inv;
    *(float4*)(Out + base) = o;
    split_store4(Oh, Ol, base, o);
}

// ---------------------------------------------------------------------------
// tcgen05 split-fp32 GEMM, MT=1, 3-stage cp.async pipeline.
// EPI: 0 ->C ; 1 +bias->C ; 3 +bias+relu->hi/lo ; 4 split->hi/lo ;
//      5 split->hi/lo for cols<vsplit, V-transposed hi/lo otherwise
// ---------------------------------------------------------------------------
#define GIDESC    IDESC_N(128)
#define STAGE_B   65536
#define NSTG      3
#define SMEM_GEMM (NSTG * STAGE_B + 1024)

template<int EPI>
__global__ __launch_bounds__(256)
void bgemm(const bf16* __restrict__ Ah, const bf16* __restrict__ Al,
           const bf16* __restrict__ Bh, const bf16* __restrict__ Bl,
           const float* __restrict__ bias, float* __restrict__ C,
           bf16* __restrict__ Ch, bf16* __restrict__ Cl,
           bf16* __restrict__ Vh, bf16* __restrict__ Vl, int vsplit,
           int M, int N, int K)
{
#if HAS_TC
    __shared__ __align__(16) uint32_t s_tptr[4];
    __shared__ __align__(16) uint64_t s_mbar[NSTG];
    extern __shared__ char smem[];
    const uint32_t tiles = (s2u(smem) + 1023u) & ~1023u;
    const uint32_t tptr  = s2u(s_tptr);
    uint32_t mb[NSTG];
    #pragma unroll
    for (int i = 0; i < NSTG; i++) mb[i] = s2u(&s_mbar[i]);

    const int t   = threadIdx.x;
    const int wid = t >> 5;
    const int bm  = blockIdx.y * 128, bn = blockIdx.x * 128;

    if (wid == 0) TC_ALLOC(tptr, 128);
    if (t == 0) {
        #pragma unroll
        for (int i = 0; i < NSTG; i++) mbar_init(mb[i], 1);
    }
    __syncthreads();
    const uint32_t tmem = s_tptr[0];

    const int r  = t >> 3;
    const int ck = t & 7;
    const int nch = K >> 6;
    int use[NSTG];
    #pragma unroll
    for (int i = 0; i < NSTG; i++) use[i] = 0;

    auto load_chunk = [&](int c, int s) {
        const uint32_t base = tiles + s * STAGE_B;
        const uint32_t aH = base, aL = base + 16384;
        const uint32_t bH = base + 32768, bL = base + 49152;
        const int k0 = c << 6;
        #pragma unroll
        for (int it = 0; it < 4; it++) {
            int row = r + it * 32;
            size_t g = (size_t)(bm + row) * K + k0 + ck * 8;
            uint32_t so = swz((uint32_t)(row * 128 + ck * 16));
            cpasync16(aH + so, Ah + g);
            cpasync16(aL + so, Al + g);
        }
        #pragma unroll
        for (int it = 0; it < 4; it++) {
            int row = r + it * 32;
            size_t g = (size_t)(bn + row) * K + k0 + ck * 8;
            uint32_t so = swz((uint32_t)(row * 128 + ck * 16));
            cpasync16(bH + so, Bh + g);
            cpasync16(bL + so, Bl + g);
        }
        CP_COMMIT();
    };

    load_chunk(0, 0);
    for (int c = 0; c < nch; c++) {
        const int s = c % NSTG;
        if (c + 1 < nch) {
            const int s2 = (c + 1) % NSTG;
            if (use[s2] > 0) mbar_wait(mb[s2], (use[s2] - 1) & 1);
            load_chunk(c + 1, s2);
            CP_WAIT1();
        } else {
            CP_WAIT0();
        }
        FENCE_ASYNC();
        __syncthreads();
        if (t == 0) {
            const uint32_t base = tiles + s * STAGE_B;
            uint64_t dah = mkdesc(base),         dal = mkdesc(base + 16384);
            uint64_t dbh = mkdesc(base + 32768), dbl = mkdesc(base + 49152);
            #pragma unroll
            for (int j = 0; j < 4; j++)
                mma_f16_ss(tmem, dah + 2 * j, dbh + 2 * j, GIDESC,
                           (c == 0 && j == 0) ? 0u : 1u);
            #pragma unroll
            for (int j = 0; j < 4; j++)
                mma_f16_ss(tmem, dah + 2 * j, dbl + 2 * j, GIDESC, 1u);
            #pragma unroll
            for (int j = 0; j < 4; j++)
                mma_f16_ss(tmem, dal + 2 * j, dbh + 2 * j, GIDESC, 1u);
            TC_COMMIT(mb[s]);
        }
        use[s]++;
    }
    #pragma unroll
    for (int i = 0; i < NSTG; i++)
        if (use[i] > 0) mbar_wait(mb[i], (use[i] - 1) & 1);
    TC_FENCE_AFTER();

    {
        const int sub = wid & 3, half = wid >> 2, lane = t & 31;
        const int rowg = bm + sub * 32 + lane;
        #pragma unroll
        for (int cc = 0; cc < 2; cc++) {
            const int col0 = half * 64 + cc * 32;
            uint32_t regs[32];
            TCLD32(regs, tmem + col0);
            TC_WAIT_LD();
            const int colbase = bn + col0;
            if (EPI == 0) {
                #pragma unroll
                for (int j = 0; j < 32; j += 4) {
                    float4 v;
                    v.x = __uint_as_float(regs[j]);
                    v.y = __uint_as_float(regs[j + 1]);
                    v.z = __uint_as_float(regs[j + 2]);
                    v.w = __uint_as_float(regs[j + 3]);
                    *(float4*)(C + (size_t)rowg * N + colbase + j) = v;
                }
            } else if (EPI == 1) {
                #pragma unroll
                for (int j = 0; j < 32; j += 4) {
                    float4 bv = *(const float4*)(bias + colbase + j);
                    float4 v;
                    v.x = __uint_as_float(regs[j])     + bv.x;
                    v.y = __uint_as_float(regs[j + 1]) + bv.y;
                    v.z = __uint_as_float(regs[j + 2]) + bv.z;
                    v.w = __uint_as_float(regs[j + 3]) + bv.w;
                    *(float4*)(C + (size_t)rowg * N + colbase + j) = v;
                }
            } else if (EPI == 3) {
                #pragma unroll
                for (int j = 0; j < 32; j += 4) {
                    float4 bv = *(const float4*)(bias + colbase + j);
                    float4 v;
                    v.x = fmaxf(__uint_as_float(regs[j])     + bv.x, 0.f);
                    v.y = fmaxf(__uint_as_float(regs[j + 1]) + bv.y, 0.f);
                    v.z = fmaxf(__uint_as_float(regs[j + 2]) + bv.z, 0.f);
                    v.w = fmaxf(__uint_as_float(regs[j + 3]) + bv.w, 0.f);
                    split_store4(Ch, Cl, (size_t)rowg * N + colbase + j, v);
                }
            } else if (EPI == 4) {
                #pragma unroll
                for (int j = 0; j < 32; j += 4) {
                    float4 v;
                    v.x = __uint_as_float(regs[j]);
                    v.y = __uint_as_float(regs[j + 1]);
                    v.z = __uint_as_float(regs[j + 2]);
                    v.w = __uint_as_float(regs[j + 3]);
                    split_store4(Ch, Cl, (size_t)rowg * N + colbase + j, v);
                }
            } else {  // EPI == 5
                if (colbase < vsplit) {
                    #pragma unroll
                    for (int j = 0; j < 32; j += 4) {
                        float4 v;
                        v.x = __uint_as_float(regs[j]);
                        v.y = __uint_as_float(regs[j + 1]);
                        v.z = __uint_as_float(regs[j + 2]);
                        v.w = __uint_as_float(regs[j + 3]);
                        split_store4(Ch, Cl, (size_t)rowg * N + colbase + j, v);
                    }
                } else {
                    const int vcol = colbase - vsplit;
                    const int z  = (rowg >> 9) * 8 + (vcol >> 6);
                    const int d0 = vcol & 63;
                    const int tok = rowg & 511;
                    const size_t vb = ((size_t)z * 64 + d0) * 512 + tok;
                    #pragma unroll
                    for (int j = 0; j < 32; j++) {
                        float fv = __uint_as_float(regs[j]);
                        bf16 h = __float2bfloat16_rn(fv);
                        bf16 l = __float2bfloat16_rn(fv - __bfloat162float(h));
                        Vh[vb + (size_t)j * 512] = h;
                        Vl[vb + (size_t)j * 512] = l;
                    }
                }
            }
        }
    }
    __syncthreads();
    if (wid == 0) TC_DEALLOC(tmem, 128);
#else
    const int t  = threadIdx.x;
    const int bm = blockIdx.y * 128, bn = blockIdx.x * 128;
    const int r0 = (t >> 4) * 8;
    const int c0 = (t & 15) * 8;
    for (int i = 0; i < 8; i++) {
        int rowg = bm + r0 + i;
        for (int j = 0; j < 8; j++) {
            int col = bn + c0 + j;
            float acc = 0.f;
            for (int k = 0; k < K; k++) {
                float av = __bfloat162float(Ah[(size_t)rowg * K + k])
                         + __bfloat162float(Al[(size_t)rowg * K + k]);
                float bv = __bfloat162float(Bh[(size_t)col * K + k])
                         + __bfloat162float(Bl[(size_t)col * K + k]);
                acc += av * bv;
            }
            if (EPI == 1 || EPI == 3) acc += bias[col];
            if (EPI == 3) acc = fmaxf(acc, 0.f);
            if (EPI == 0 || EPI == 1) {
                C[(size_t)rowg * N + col] = acc;
            } else if (EPI == 3 || EPI == 4 || (EPI == 5 && col < vsplit)) {
                bf16 h = __float2bfloat16_rn(acc);
                Ch[(size_t)rowg * N + col] = h;
                Cl[(size_t)rowg * N + col] =
                    __float2bfloat16_rn(acc - __bfloat162float(h));
            } else {
                int vcol = col - vsplit;
                int z = (rowg >> 9) * 8 + (vcol >> 6);
                int d = vcol & 63, tok = rowg & 511;
                bf16 h = __float2bfloat16_rn(acc);
                Vh[((size_t)z * 64 + d) * 512 + tok] = h;
                Vl[((size_t)z * 64 + d) * 512 + tok] =
                    __float2bfloat16_rn(acc - __bfloat162float(h));
            }
        }
    }
#endif
}

// ---------------------------------------------------------------------------
// bgemm2: MT=2 variant for the logits GEMM. EPI 1 only.
// ---------------------------------------------------------------------------
#define STAGE2_B   98304
#define NSTG2      2
#define SMEM_GEMM2 (NSTG2 * STAGE2_B + 1024)

__global__ __launch_bounds__(256)
void bgemm2(const bf16* __restrict__ Ah, const bf16* __restrict__ Al,
            const bf16* __restrict__ Bh, const bf16* __restrict__ Bl,
            const float* __restrict__ bias, float* __restrict__ C,
            int M, int N, int K)
{
#if HAS_TC
    __shared__ __align__(16) uint32_t s_tptr[4];
    __shared__ __align__(16) uint64_t s_mbar[NSTG2];
    extern __shared__ char smem[];
    const uint32_t tiles = (s2u(smem) + 1023u) & ~1023u;
    const uint32_t tptr  = s2u(s_tptr);
    uint32_t mb[NSTG2];
    #pragma unroll
    for (int i = 0; i < NSTG2; i++) mb[i] = s2u(&s_mbar[i]);

    const int t   = threadIdx.x;
    const int wid = t >> 5;
    const int bm  = blockIdx.y * 256, bn = blockIdx.x * 128;

    if (wid == 0) TC_ALLOC(tptr, 256);
    if (t == 0) {
        #pragma unroll
        for (int i = 0; i < NSTG2; i++) mbar_init(mb[i], 1);
    }
    __syncthreads();
    const uint32_t tmem = s_tptr[0];

    const int r  = t >> 3;
    const int ck = t & 7;
    const int nch = K >> 6;
    int use[NSTG2];
    #pragma unroll
    for (int i = 0; i < NSTG2; i++) use[i] = 0;

    auto load_chunk = [&](int c, int s) {
        const uint32_t base = tiles + s * STAGE2_B;
        const int k0 = c << 6;
        #pragma unroll
        for (int m = 0; m < 2; m++) {
            const uint32_t aH = base + m * 32768, aL = aH + 16384;
            #pragma unroll
            for (int it = 0; it < 4; it++) {
                int row = r + it * 32;
                size_t g = (size_t)(bm + m * 128 + row) * K + k0 + ck * 8;
                uint32_t so = swz((uint32_t)(row * 128 + ck * 16));
                cpasync16(aH + so, Ah + g);
                cpasync16(aL + so, Al + g);
            }
        }
        const uint32_t bH = base + 65536, bL = base + 81920;
        #pragma unroll
        for (int it = 0; it < 4; it++) {
            int row = r + it * 32;
            size_t g = (size_t)(bn + row) * K + k0 + ck * 8;
            uint32_t so = swz((uint32_t)(row * 128 + ck * 16));
            cpasync16(bH + so, Bh + g);
            cpasync16(bL + so, Bl + g);
        }
        CP_COMMIT();
    };

    load_chunk(0, 0);
    for (int c = 0; c < nch; c++) {
        const int s = c % NSTG2;
        if (c + 1 < nch) {
            const int s2 = (c + 1) % NSTG2;
            if (use[s2] > 0) mbar_wait(mb[s2], (use[s2] - 1) & 1);
            load_chunk(c + 1, s2);
            CP_WAIT1();
        } else {
            CP_WAIT0();
        }
        FENCE_ASYNC();
        __syncthreads();
        if (t == 0) {
            const uint32_t base = tiles + s * STAGE2_B;
            uint64_t dbh = mkdesc(base + 65536), dbl = mkdesc(base + 81920);
            #pragma unroll
            for (int m = 0; m < 2; m++) {
                uint64_t dah = mkdesc(base + m * 32768);
                uint64_t dal = mkdesc(base + m * 32768 + 16384);
                const uint32_t acc = tmem + m * 128;
                #pragma unroll
                for (int j = 0; j < 4; j++)
                    mma_f16_ss(acc, dah + 2 * j, dbh + 2 * j, GIDESC,
                               (c == 0 && j == 0) ? 0u : 1u);
                #pragma unroll
                for (int j = 0; j < 4; j++)
                    mma_f16_ss(acc, dah + 2 * j, dbl + 2 * j, GIDESC, 1u);
                #pragma unroll
                for (int j = 0; j < 4; j++)
                    mma_f16_ss(acc, dal + 2 * j, dbh + 2 * j, GIDESC, 1u);
            }
            TC_COMMIT(mb[s]);
        }
        use[s]++;
    }
    #pragma unroll
    for (int i = 0; i < NSTG2; i++)
        if (use[i] > 0) mbar_wait(mb[i], (use[i] - 1) & 1);
    TC_FENCE_AFTER();

    {
        const int m = wid >> 2, sub = wid & 3, lane = t & 31;
        const int rowg = bm + m * 128 + sub * 32 + lane;
        #pragma unroll
        for (int cc = 0; cc < 4; cc++) {
            const int col0 = cc * 32;
            uint32_t regs[32];
            TCLD32(regs, tmem + m * 128 + col0);
            TC_WAIT_LD();
            const int colbase = bn + col0;
            #pragma unroll
            for (int j = 0; j < 32; j += 4) {
                float4 bv = *(const float4*)(bias + colbase + j);
                float4 v;
                v.x = __uint_as_float(regs[j])     + bv.x;
                v.y = __uint_as_float(regs[j + 1]) + bv.y;
                v.z = __uint_as_float(regs[j + 2]) + bv.z;
                v.w = __uint_as_float(regs[j + 3]) + bv.w;
                *(float4*)(C + (size_t)rowg * N + colbase + j) = v;
            }
        }
    }
    __syncthreads();
    if (wid == 0) TC_DEALLOC(tmem, 256);
#else
    const int t  = threadIdx.x;
    const int bm = blockIdx.y * 256, bn = blockIdx.x * 128;
    const int r0 = (t >> 4) * 16;
    const int c0 = (t & 15) * 8;
    for (int i = 0; i < 16; i++) {
        int rowg = bm + r0 + i;
        for (int j = 0; j < 8; j++) {
            int col = bn + c0 + j;
            float acc = 0.f;
            for (int k = 0; k < K; k++) {
                float av = __bfloat162float(Ah[(size_t)rowg * K + k])
                         + __bfloat162float(Al[(size_t)rowg * K + k]);
                float bv = __bfloat162float(Bh[(size_t)col * K + k])
                         + __bfloat162float(Bl[(size_t)col * K + k]);
                acc += av * bv;
            }
            C[(size_t)rowg * N + col] = acc + bias[col];
        }
    }
#endif
}

// ---------------------------------------------------------------------------
// QK^T GEMM: one CTA per (k-pair, q-tile, z): 2 k-tiles, 24 MMAs, 256 TMEM
// cols, 96KB smem -> 2 CTAs/SM for latency overlap. Grid (2, 4, 32).
// ---------------------------------------------------------------------------
#define QK_SMEM (3 * 32768 + 1024)
__global__ __launch_bounds__(256) void qk_gemm(
    const bf16* __restrict__ Qh, const bf16* __restrict__ Ql, int qp,
    const bf16* __restrict__ Kh, const bf16* __restrict__ Kl, int kp,
    float* __restrict__ scores)
{
    const int z = blockIdx.z, b = z >> 3, h = z & 7;
    const int bm = blockIdx.y * 128;
    const int kp0 = blockIdx.x * 256;     // this CTA's 2 k-tiles
    const size_t qoff = (size_t)(b * S_) * qp + h * 64;
    const size_t koff = (size_t)(b * S_) * kp + h * 64;
#if HAS_TC
    __shared__ __align__(16) uint32_t s_tptr[4];
    __shared__ __align__(16) uint64_t s_mbar[1];
    extern __shared__ char smem[];
    const uint32_t tiles = (s2u(smem) + 1023u) & ~1023u;
    const uint32_t tptr  = s2u(s_tptr);
    const uint32_t mb    = s2u(&s_mbar[0]);

    const int t   = threadIdx.x;
    const int wid = t >> 5;
    if (wid == 0) TC_ALLOC(tptr, 256);
    if (t == 0) mbar_init(mb, 1);
    __syncthreads();
    const uint32_t tmem = s_tptr[0];

    const int r  = t >> 3;
    const int ck = t & 7;
    const uint32_t aH = tiles, aL = tiles + 16384;
    #pragma unroll
    for (int it = 0; it < 4; it++) {
        int row = r + it * 32;
        uint32_t so = swz((uint32_t)(row * 128 + ck * 16));
        cpasync16(aH + so, Qh + qoff + (size_t)(bm + row) * qp + ck * 8);
        cpasync16(aL + so, Ql + qoff + (size_t)(bm + row) * qp + ck * 8);
    }
    #pragma unroll
    for (int kb = 0; kb < 2; kb++) {
        const uint32_t bH = tiles + 32768 + kb * 32768, bL = bH + 16384;
        #pragma unroll
        for (int it = 0; it < 4; it++) {
            int row = r + it * 32;
            uint32_t so = swz((uint32_t)(row * 128 + ck * 16));
            cpasync16(bH + so, Kh + koff + (size_t)(kp0 + kb * 128 + row) * kp + ck * 8);
            cpasync16(bL + so, Kl + koff + (size_t)(kp0 + kb * 128 + row) * kp + ck * 8);
        }
    }
    CP_COMMIT(); CP_WAIT0();
    FENCE_ASYNC();
    __syncthreads();
    if (t == 0) {
        uint64_t dah = mkdesc(aH), dal = mkdesc(aL);
        #pragma unroll
        for (int kb = 0; kb < 2; kb++) {
            const uint32_t bH = tiles + 32768 + kb * 32768;
            uint64_t dbh = mkdesc(bH), dbl = mkdesc(bH + 16384);
            const uint32_t acc = tmem + kb * 128;
            #pragma unroll
            for (int j = 0; j < 4; j++)
                mma_f16_ss(acc, dah + 2 * j, dbh + 2 * j, GIDESC, j ? 1u : 0u);
            #pragma unroll
            for (int j = 0; j < 4; j++)
                mma_f16_ss(acc, dah + 2 * j, dbl + 2 * j, GIDESC, 1u);
            #pragma unroll
            for (int j = 0; j < 4; j++)
                mma_f16_ss(acc, dal + 2 * j, dbh + 2 * j, GIDESC, 1u);
        }
        TC_COMMIT(mb);
    }
    mbar_wait(mb, 0);
    TC_FENCE_AFTER();
    {
        const int sub = wid & 3, half = wid >> 2, lane = t & 31;
        const int rowg = bm + sub * 32 + lane;
        float* out = scores + ((size_t)z * S_ + rowg) * S_ + kp0;
        #pragma unroll
        for (int kb = 0; kb < 2; kb++) {
            #pragma unroll
            for (int cc = 0; cc < 2; cc++) {
                const int col0 = half * 64 + cc * 32;
                uint32_t regs[32];
                TCLD32(regs, tmem + kb * 128 + col0);
                TC_WAIT_LD();
                #pragma unroll
                for (int j = 0; j < 32; j += 4) {
                    float4 v;
                    v.x = __uint_as_float(regs[j])     * 0.125f;
                    v.y = __uint_as_float(regs[j + 1]) * 0.125f;
                    v.z = __uint_as_float(regs[j + 2]) * 0.125f;
                    v.w = __uint_as_float(regs[j + 3]) * 0.125f;
                    *(float4*)(out + kb * 128 + col0 + j) = v;
                }
            }
        }
    }
    __syncthreads();
    if (wid == 0) TC_DEALLOC(tmem, 256);
#else
    const int t = threadIdx.x;
    for (int idx = t; idx < 128 * 256; idx += 256) {
        int rr = idx >> 8, cc = (idx & 255) + kp0;
        float acc = 0.f;
        for (int k = 0; k < 64; k++) {
            float qv = __bfloat162float(Qh[qoff + (size_t)(bm + rr) * qp + k])
                     + __bfloat162float(Ql[qoff + (size_t)(bm + rr) * qp + k]);
            float kv = __bfloat162float(Kh[koff + (size_t)cc * kp + k])
                     + __bfloat162float(Kl[koff + (size_t)cc * kp + k]);
            acc += qv * kv;
        }
        scores[((size_t)z * S_ + bm + rr) * S_ + cc] = acc * 0.125f;
    }
#endif
}

// ---------------------------------------------------------------------------
// Masked softmax -> P hi/lo (normalized)
// ---------------------------------------------------------------------------
__global__ __launch_bounds__(128) void softmax_kernel(
    const float* __restrict__ scores, const int* __restrict__ kv_tok,
    bf16* __restrict__ Ph, bf16* __restrict__ Pl, int causal)
{
    const int q = blockIdx.x, z = blockIdx.y, b = z >> 3;
    const int t = threadIdx.x;
    const size_t base = ((size_t)z * S_ + q) * S_;
    float4 s = *(const float4*)(scores + base + t * 4);
    float vals[4] = {s.x, s.y, s.z, s.w};
    #pragma unroll
    for (int j = 0; j < 4; j++) {
        int k = t * 4 + j;
        if (kv_tok[b * S_ + k] == 0) vals[j] += NEGV;
        if (causal && k > q)         vals[j] += NEGV;
    }
    float m = fmaxf(fmaxf(vals[0], vals[1]), fmaxf(vals[2], vals[3]));
    __shared__ float redM[4], redS[4];
    #pragma unroll
    for (int off = 16; off > 0; off >>= 1)
        m = fmaxf(m, __shfl_xor_sync(0xffffffffu, m, off));
    const int wid = t >> 5, lane = t & 31;
    if (lane == 0) redM[wid] = m;
    __syncthreads();
    m = fmaxf(fmaxf(redM[0], redM[1]), fmaxf(redM[2], redM[3]));

    float e[4], ssum = 0.f;
    #pragma unroll
    for (int j = 0; j < 4; j++) { e[j] = __expf(vals[j] - m); ssum += e[j]; }
    #pragma unroll
    for (int off = 16; off > 0; off >>= 1)
        ssum += __shfl_xor_sync(0xffffffffu, ssum, off);
    if (lane == 0) redS[wid] = ssum;
    __syncthreads();
    ssum = redS[0] + redS[1] + redS[2] + redS[3];
    float inv = 1.f / ssum;
    float4 p = make_float4(e[0] * inv, e[1] * inv, e[2] * inv, e[3] * inv);
    split_store4(Ph, Pl, base + t * 4, p);
}

// ---------------------------------------------------------------------------
// AV GEMM: out = P @ V via V^T, grid (1,4,32), 2-stage pipeline (97KB smem
// -> 2 CTAs/SM)
// ---------------------------------------------------------------------------
#define AV_STAGE  49152
#define AV_NSTG   2
#define AV_SMEM   (AV_NSTG * AV_STAGE + 1024)
#define AVIDESC   IDESC_N(64)
__global__ __launch_bounds__(256) void av_gemm(
    const bf16* __restrict__ Ph, const bf16* __restrict__ Pl,
    const bf16* __restrict__ Vth, const bf16* __restrict__ Vtl,
    bf16* __restrict__ Oh, bf16* __restrict__ Ol)
{
    const int z = blockIdx.z, b = z >> 3, h = z & 7;
    const int bm = blockIdx.y * 128;
    const bf16* Pzh = Ph  + (size_t)z * S_ * S_;
    const bf16* Pzl = Pl  + (size_t)z * S_ * S_;
    const bf16* Vzh = Vth + (size_t)z * 64 * S_;
    const bf16* Vzl = Vtl + (size_t)z * 64 * S_;
#if HAS_TC
    __shared__ __align__(16) uint32_t s_tptr[4];
    __shared__ __align__(16) uint64_t s_mbar[AV_NSTG];
    extern __shared__ char smem[];
    const uint32_t tiles = (s2u(smem) + 1023u) & ~1023u;
    const uint32_t tptr  = s2u(s_tptr);
    uint32_t mb[AV_NSTG];
    #pragma unroll
    for (int i = 0; i < AV_NSTG; i++) mb[i] = s2u(&s_mbar[i]);

    const int t   = threadIdx.x;
    const int wid = t >> 5;
    if (wid == 0) TC_ALLOC(tptr, 128);
    if (t == 0) {
        #pragma unroll
        for (int i = 0; i < AV_NSTG; i++) mbar_init(mb[i], 1);
    }
    __syncthreads();
    const uint32_t tmem = s_tptr[0];

    const int r  = t >> 3;
    const int ck = t & 7;
    int use[AV_NSTG];
    #pragma unroll
    for (int i = 0; i < AV_NSTG; i++) use[i] = 0;

    auto load_chunk = [&](int c, int s) {
        const uint32_t base = tiles + s * AV_STAGE;
        const uint32_t aH = base, aL = base + 16384;
        const uint32_t bH = base + 32768, bL = base + 40960;
        const int k0 = c << 6;
        #pragma unroll
        for (int it = 0; it < 4; it++) {
            int row = r + it * 32;
            size_t g = (size_t)(bm + row) * S_ + k0 + ck * 8;
            uint32_t so = swz((uint32_t)(row * 128 + ck * 16));
            cpasync16(aH + so, Pzh + g);
            cpasync16(aL + so, Pzl + g);
        }
        #pragma unroll
        for (int it = 0; it < 2; it++) {
            int row = r + it * 32;
            size_t g = (size_t)row * S_ + k0 + ck * 8;
            uint32_t so = swz((uint32_t)(row * 128 + ck * 16));
            cpasync16(bH + so, Vzh + g);
            cpasync16(bL + so, Vzl + g);
        }
        CP_COMMIT();
    };

    const int nch = S_ >> 6;
    load_chunk(0, 0);
    for (int c = 0; c < nch; c++) {
        const int s = c % AV_NSTG;
        if (c + 1 < nch) {
            const int s2 = (c + 1) % AV_NSTG;
            if (use[s2] > 0) mbar_wait(mb[s2], (use[s2] - 1) & 1);
            load_chunk(c + 1, s2);
            CP_WAIT1();
        } else {
            CP_WAIT0();
        }
        FENCE_ASYNC();
        __syncthreads();
        if (t == 0) {
            const uint32_t base = tiles + s * AV_STAGE;
            uint64_t dah = mkdesc(base),         dal = mkdesc(base + 16384);
            uint64_t dbh = mkdesc(base + 32768), dbl = mkdesc(base + 40960);
            #pragma unroll
            for (int j = 0; j < 4; j++)
                mma_f16_ss(tmem, dah + 2 * j, dbh + 2 * j, AVIDESC,
                           (c == 0 && j == 0) ? 0u : 1u);
            #pragma unroll
            for (int j = 0; j < 4; j++)
                mma_f16_ss(tmem, dah + 2 * j, dbl + 2 * j, AVIDESC, 1u);
            #pragma unroll
            for (int j = 0; j < 4; j++)
                mma_f16_ss(tmem, dal + 2 * j, dbh + 2 * j, AVIDESC, 1u);
            TC_COMMIT(mb[s]);
        }
        use[s]++;
    }
    #pragma unroll
    for (int i = 0; i < AV_NSTG; i++)
        if (use[i] > 0) mbar_wait(mb[i], (use[i] - 1) & 1);
    TC_FENCE_AFTER();
    {
        const int sub = wid & 3, half = wid >> 2, lane = t & 31;
        const int rowg = bm + sub * 32 + lane;
        const int col0 = half * 32;
        uint32_t regs[32];
        TCLD32(regs, tmem + col0);
        TC_WAIT_LD();
        #pragma unroll
        for (int j = 0; j < 32; j += 4) {
            float4 v;
            v.x = __uint_as_float(regs[j]);
            v.y = __uint_as_float(regs[j + 1]);
            v.z = __uint_as_float(regs[j + 2]);
            v.w = __uint_as_float(regs[j + 3]);
            size_t idx = ((size_t)(b * S_) + rowg) * D_ + h * 64 + col0 + j;
            split_store4(Oh, Ol, idx, v);
        }
    }
    __syncthreads();
    if (wid == 0) TC_DEALLOC(tmem, 128);
#else
    const int t = threadIdx.x;
    for (int idx = t; idx < 128 * 64; idx += 256) {
        int rr = idx >> 6, cc = idx & 63;
        float acc = 0.f;
        for (int k = 0; k < S_; k++) {
            float pv = __bfloat162float(Pzh[(size_t)(bm + rr) * S_ + k])
                     + __bfloat162float(Pzl[(size_t)(bm + rr) * S_ + k]);
            float vv = __bfloat162float(Vzh[(size_t)cc * S_ + k])
                     + __bfloat162float(Vzl[(size_t)cc * S_ + k]);
            acc += pv * vv;
        }
        size_t oidx = ((size_t)(b * S_) + bm + rr) * D_ + h * 64 + cc;
        bf16 hh2 = __float2bfloat16_rn(acc);
        Oh[oidx] = hh2;
        Ol[oidx] = __float2bfloat16_rn(acc - __bfloat162float(hh2));
    }
#endif
}

// ---------------------------------------------------------------------------
// Host driver
// ---------------------------------------------------------------------------
static inline void run_bgemm(int epi, const bf16* Ah, const bf16* Al,
                             const bf16* Bh, const bf16* Bl, const float* bias,
                             float* C, bf16* Ch, bf16* Cl,
                             bf16* Vh, bf16* Vl, int vsplit,
                             int M, int N, int K)
{
    dim3 grid(N / 128, M / 128);
    if (epi == 0)
        bgemm<0><<<grid, 256, SMEM_GEMM>>>(Ah, Al, Bh, Bl, bias, C, Ch, Cl, Vh, Vl, vsplit, M, N, K);
    else if (epi == 1)
        bgemm<1><<<grid, 256, SMEM_GEMM>>>(Ah, Al, Bh, Bl, bias, C, Ch, Cl, Vh, Vl, vsplit, M, N, K);
    else if (epi == 3)
        bgemm<3><<<grid, 256, SMEM_GEMM>>>(Ah, Al, Bh, Bl, bias, C, Ch, Cl, Vh, Vl, vsplit, M, N, K);
    else if (epi == 4)
        bgemm<4><<<grid, 256, SMEM_GEMM>>>(Ah, Al, Bh, Bl, bias, C, Ch, Cl, Vh, Vl, vsplit, M, N, K);
    else
        bgemm<5><<<grid, 256, SMEM_GEMM>>>(Ah, Al, Bh, Bl, bias, C, Ch, Cl, Vh, Vl, vsplit, M, N, K);
}

extern "C" void kernel_launch(void* const* d_in, const int* in_sizes, int n_in,
                              void* d_out, int out_size)
{
    const int DDi = D_ * D_;

    int iEWq, iEWk, iEWv, iEWo, iEW1, iEb1, iEW2, iEb2;
    int iDWq1, iDWk1, iDWv1, iDWo1, iDWq2, iDWk2, iDWv2, iDWo2;
    int iDW1, iDb1, iDW2, iDb2, iWout, iBout;
    if (n_in >= 8 && in_sizes[7] == L_ * DDi) {
        iEWq = 3; iEWk = 4; iEWv = 5; iEWo = 6;
        iDWq1 = 7; iDWk1 = 8; iDWv1 = 9; iDWo1 = 10;
        iDWq2 = 11; iDWk2 = 12; iDWv2 = 13; iDWo2 = 14;
        iEW1 = 15; iEb1 = 16; iEW2 = 17; iEb2 = 18;
        iDW1 = 19; iDb1 = 20; iDW2 = 21; iDb2 = 22;
        iWout = 23; iBout = 24;
    } else {
        iEWq = 3; iEWk = 4; iEWv = 5; iEWo = 6;
        iEW1 = 7; iEb1 = 8; iEW2 = 9; iEb2 = 10;
        iDWq1 = 11; iDWk1 = 12; iDWv1 = 13; iDWo1 = 14;
        iDWq2 = 15; iDWk2 = 16; iDWv2 = 17; iDWo2 = 18;
        iDW1 = 19; iDb1 = 20; iDW2 = 21; iDb2 = 22;
        iWout = 23; iBout = 24;
    }

    const int*   src  = (const int*)d_in[0];
    const int*   tgt  = (const int*)d_in[1];
    const float* emb  = (const float*)d_in[2];
    const float* eWq  = (const float*)d_in[iEWq];
    const float* eWk  = (const float*)d_in[iEWk];
    const float* eWv  = (const float*)d_in[iEWv];
    const float* eWo  = (const float*)d_in[iEWo];
    const float* eW1  = (const float*)d_in[iEW1];
    const float* eb1  = (const float*)d_in[iEb1];
    const float* eW2  = (const float*)d_in[iEW2];
    const float* eb2  = (const float*)d_in[iEb2];
    const float* dWq1 = (const float*)d_in[iDWq1];
    const float* dWk1 = (const float*)d_in[iDWk1];
    const float* dWv1 = (const float*)d_in[iDWv1];
    const float* dWo1 = (const float*)d_in[iDWo1];
    const float* dWq2 = (const float*)d_in[iDWq2];
    const float* dWk2 = (const float*)d_in[iDWk2];
    const float* dWv2 = (const float*)d_in[iDWv2];
    const float* dWo2 = (const float*)d_in[iDWo2];
    const float* dW1  = (const float*)d_in[iDW1];
    const float* db1  = (const float*)d_in[iDb1];
    const float* dW2  = (const float*)d_in[iDW2];
    const float* db2  = (const float*)d_in[iDb2];
    const float* Wout = (const float*)d_in[iWout];
    const float* bout = (const float*)d_in[iBout];

    cudaFuncSetAttribute(bgemm<0>, cudaFuncAttributeMaxDynamicSharedMemorySize, SMEM_GEMM);
    cudaFuncSetAttribute(bgemm<1>, cudaFuncAttributeMaxDynamicSharedMemorySize, SMEM_GEMM);
    cudaFuncSetAttribute(bgemm<3>, cudaFuncAttributeMaxDynamicSharedMemorySize, SMEM_GEMM);
    cudaFuncSetAttribute(bgemm<4>, cudaFuncAttributeMaxDynamicSharedMemorySize, SMEM_GEMM);
    cudaFuncSetAttribute(bgemm<5>, cudaFuncAttributeMaxDynamicSharedMemorySize, SMEM_GEMM);
    cudaFuncSetAttribute(bgemm2,   cudaFuncAttributeMaxDynamicSharedMemorySize, SMEM_GEMM2);
    cudaFuncSetAttribute(qk_gemm,  cudaFuncAttributeMaxDynamicSharedMemorySize, QK_SMEM);
    cudaFuncSetAttribute(av_gemm,  cudaFuncAttributeMaxDynamicSharedMemorySize, AV_SMEM);

    float *x, *a, *out, *f, *y0, *o, *scores;
    cudaGetSymbolAddress((void**)&x,   g_x);
    cudaGetSymbolAddress((void**)&a,   g_a);
    cudaGetSymbolAddress((void**)&out, g_out);
    cudaGetSymbolAddress((void**)&f,   g_f);
    cudaGetSymbolAddress((void**)&y0,  g_y0);
    cudaGetSymbolAddress((void**)&o,   g_o);
    cudaGetSymbolAddress((void**)&scores, g_scores);

    bf16 *xh, *xl, *outh, *outl, *ath, *atl, *y0h, *y0l, *oh, *ol, *hh, *hl, *wh, *wl;
    bf16 *qkvh, *qkvl, *kv2h, *kv2l, *q2h, *q2l, *ph, *pl, *vth, *vtl;
    cudaGetSymbolAddress((void**)&xh,   g_xh);
    cudaGetSymbolAddress((void**)&xl,   g_xl);
    cudaGetSymbolAddress((void**)&outh, g_outh);
    cudaGetSymbolAddress((void**)&outl, g_outl);
    cudaGetSymbolAddress((void**)&ath,  g_ath);
    cudaGetSymbolAddress((void**)&atl,  g_atl);
    cudaGetSymbolAddress((void**)&y0h,  g_y0h);
    cudaGetSymbolAddress((void**)&y0l,  g_y0l);
    cudaGetSymbolAddress((void**)&oh,   g_oh);
    cudaGetSymbolAddress((void**)&ol,   g_ol);
    cudaGetSymbolAddress((void**)&hh,   g_hh);
    cudaGetSymbolAddress((void**)&hl,   g_hl);
    cudaGetSymbolAddress((void**)&wh,   g_wh);
    cudaGetSymbolAddress((void**)&wl,   g_wl);
    cudaGetSymbolAddress((void**)&qkvh, g_qkvh);
    cudaGetSymbolAddress((void**)&qkvl, g_qkvl);
    cudaGetSymbolAddress((void**)&kv2h, g_kv2h);
    cudaGetSymbolAddress((void**)&kv2l, g_kv2l);
    cudaGetSymbolAddress((void**)&q2h,  g_q2h);
    cudaGetSymbolAddress((void**)&q2l,  g_q2l);
    cudaGetSymbolAddress((void**)&ph,   g_ph);
    cudaGetSymbolAddress((void**)&pl,   g_pl);
    cudaGetSymbolAddress((void**)&vth,  g_vth);
    cudaGetSymbolAddress((void**)&vtl,  g_vtl);

    // ---- Weight conversion: ONE launch ----
    {
        const int li = L_ - 1;
        WcvTable tab;
        int ts = 0, ne = 0;
        auto add = [&](const float* s, unsigned long long dst,
                       unsigned long long ls, int K, int N, int nz) {
            WcvEntry& E = tab.e[ne++];
            E.src = s; E.dst = dst; E.lstride = ls;
            E.K = K; E.N = N; E.ntx = N / 32; E.nty = K / 32; E.nz = nz;
            E.tstart = ts;
            ts += (N / 32) * (K / 32) * nz;
        };
        add(eWq, O_EQKV,          3 * DD, D_, D_, 6);
        add(eWk, O_EQKV + DD,     3 * DD, D_, D_, 6);
        add(eWv, O_EQKV + 2 * DD, 3 * DD, D_, D_, 6);
        add(eWo, O_EWO, DD,  D_, D_, 6);
        add(eW1, O_EW1, DDF, D_, DFF_, 6);
        add(eW2, O_EW2, DDF, DFF_, D_, 6);
        add(dWq1 + (size_t)li * DDi, O_DQKV1,          0, D_, D_, 1);
        add(dWk1 + (size_t)li * DDi, O_DQKV1 + DD,     0, D_, D_, 1);
        add(dWv1 + (size_t)li * DDi, O_DQKV1 + 2 * DD, 0, D_, D_, 1);
        add(dWo1 + (size_t)li * DDi, O_DWO1, 0, D_, D_, 1);
        add(dWq2 + (size_t)li * DDi, O_DWQ2, 0, D_, D_, 1);
        add(dWk2 + (size_t)li * DDi, O_DKV2,      0, D_, D_, 1);
        add(dWv2 + (size_t)li * DDi, O_DKV2 + DD, 0, D_, D_, 1);
        add(dWo2 + (size_t)li * DDi, O_DWO2, 0, D_, D_, 1);
        add(dW1 + (size_t)li * (D_ * DFF_), O_DW1, 0, D_, DFF_, 1);
        add(dW2 + (size_t)li * (D_ * DFF_), O_DW2, 0, DFF_, D_, 1);
        add(Wout, O_WOUT, 0, D_, V_, 1);
        wconv_all<<<ts, dim3(32, 8)>>>(tab, ne, wh, wl);
    }

    const dim3 qkGrid(2, 4, 32), smGrid(S_, 32), avGrid(1, 4, 32);
    const int li = L_ - 1;

    // ---------------- Encoder ----------------
    embed_kernel<<<BS_, 128>>>(src, emb, x, xh, xl);
    for (int i = 0; i < L_; i++) {
        run_bgemm(5, xh, xl, wh + O_EQKV + (size_t)i * 3 * DD, wl + O_EQKV + (size_t)i * 3 * DD,
                  nullptr, nullptr, qkvh, qkvl, vth, vtl, 1024, BS_, 3 * D_, D_);
        qk_gemm<<<qkGrid, 256, QK_SMEM>>>(qkvh, qkvl, 3 * D_,
                                          qkvh + D_, qkvl + D_, 3 * D_, scores);
        softmax_kernel<<<smGrid, 128>>>(scores, src, ph, pl, 0);
        av_gemm<<<avGrid, 256, AV_SMEM>>>(ph, pl, vth, vtl, ath, atl);
        run_bgemm(0, ath, atl, wh + O_EWO + (size_t)i * DD, wl + O_EWO + (size_t)i * DD,
                  nullptr, a, nullptr, nullptr, nullptr, nullptr, 0, BS_, D_, D_);
        add_ln_kernel<<<BS_, 128>>>(x, a, out, outh, outl);
        run_bgemm(3, outh, outl, wh + O_EW1 + (size_t)i * DDF, wl + O_EW1 + (size_t)i * DDF,
                  eb1 + (size_t)i * DFF_, nullptr, hh, hl, nullptr, nullptr, 0, BS_, DFF_, D_);
        run_bgemm(1, hh, hl, wh + O_EW2 + (size_t)i * DDF, wl + O_EW2 + (size_t)i * DDF,
                  eb2 + (size_t)i * D_, f, nullptr, nullptr, nullptr, nullptr, 0, BS_, D_, DFF_);
        add_ln_kernel<<<BS_, 128>>>(a, f, x, xh, xl);
    }

    // ---------------- Decoder (last layer only) ----------------
    embed_kernel<<<BS_, 128>>>(tgt, emb, y0, y0h, y0l);
    {
        run_bgemm(5, y0h, y0l, wh + O_DQKV1, wl + O_DQKV1, nullptr, nullptr,
                  qkvh, qkvl, vth, vtl, 1024, BS_, 3 * D_, D_);
        qk_gemm<<<qkGrid, 256, QK_SMEM>>>(qkvh, qkvl, 3 * D_,
                                          qkvh + D_, qkvl + D_, 3 * D_, scores);
        softmax_kernel<<<smGrid, 128>>>(scores, tgt, ph, pl, 1);
        av_gemm<<<avGrid, 256, AV_SMEM>>>(ph, pl, vth, vtl, ath, atl);
        run_bgemm(0, ath, atl, wh + O_DWO1, wl + O_DWO1, nullptr, a,
                  nullptr, nullptr, nullptr, nullptr, 0, BS_, D_, D_);
        add_ln_kernel<<<BS_, 128>>>(y0, a, o, oh, ol);

        run_bgemm(4, oh, ol, wh + O_DWQ2, wl + O_DWQ2, nullptr, nullptr,
                  q2h, q2l, nullptr, nullptr, 0, BS_, D_, D_);
        run_bgemm(5, xh, xl, wh + O_DKV2, wl + O_DKV2, nullptr, nullptr,
                  kv2h, kv2l, vth, vtl, 512, BS_, 2 * D_, D_);
        qk_gemm<<<qkGrid, 256, QK_SMEM>>>(q2h, q2l, D_, kv2h, kv2l, 2 * D_, scores);
        softmax_kernel<<<smGrid, 128>>>(scores, src, ph, pl, 0);
        av_gemm<<<avGrid, 256, AV_SMEM>>>(ph, pl, vth, vtl, ath, atl);
        run_bgemm(0, ath, atl, wh + O_DWO2, wl + O_DWO2, nullptr, a,
                  nullptr, nullptr, nullptr, nullptr, 0, BS_, D_, D_);
        add_ln_kernel<<<BS_, 128>>>(o, a, o, oh, ol);

        run_bgemm(3, oh, ol, wh + O_DW1, wl + O_DW1, db1 + (size_t)li * DFF_,
                  nullptr, hh, hl, nullptr, nullptr, 0, BS_, DFF_, D_);
        run_bgemm(1, hh, hl, wh + O_DW2, wl + O_DW2, db2 + (size_t)li * D_,
                  f, nullptr, nullptr, nullptr, nullptr, 0, BS_, D_, DFF_);
        add_ln_kernel<<<BS_, 128>>>(o, f, o, oh, ol);
    }

    // ---------------- Logits (MT=2) ----------------
    bgemm2<<<dim3(V_ / 128, BS_ / 256), 256, SMEM_GEMM2>>>(
        oh, ol, wh + O_WOUT, wl + O_WOUT, bout, (float*)d_out, BS_, V_, D_);
}

// round 14
// speedup vs baseline: 1.1107x; 1.0004x over previous
#include <cuda_runtime.h>
#include <cuda_bf16.h>
#include <math.h>
#include <stdint.h>

#define D_    512
#define S_    512
#define B_    4
#define H_    8
#define L_    6
#define DFF_  2048
#define V_    32000
#define BS_   (B_ * S_)
#define NEGV  (-1e10f)

#if defined(__CUDA_ARCH_FEAT_SM103_ALL) || defined(__CUDA_ARCH_FEAT_SM100_ALL) || defined(__CUDA_ARCH_FEAT_SM101_ALL)
#define HAS_TC 1
#else
#define HAS_TC 0
#endif

typedef __nv_bfloat16  bf16;
typedef __nv_bfloat162 bf162;

// ---------------------------------------------------------------------------
// Scratch (device globals)
// ---------------------------------------------------------------------------
__device__ float g_x[BS_ * D_];
__device__ float g_a[BS_ * D_];
__device__ float g_out[BS_ * D_];
__device__ float g_f[BS_ * D_];
__device__ float g_y0[BS_ * D_];
__device__ float g_o[BS_ * D_];

__device__ bf16 g_xh[BS_ * D_],   g_xl[BS_ * D_];
__device__ bf16 g_outh[BS_ * D_], g_outl[BS_ * D_];
__device__ bf16 g_ath[BS_ * D_],  g_atl[BS_ * D_];
__device__ bf16 g_y0h[BS_ * D_],  g_y0l[BS_ * D_];
__device__ bf16 g_oh[BS_ * D_],   g_ol[BS_ * D_];
__device__ bf16 g_hh[BS_ * DFF_], g_hl[BS_ * DFF_];

// Attention scratch
__device__ bf16  g_qkvh[BS_ * 3 * D_], g_qkvl[BS_ * 3 * D_];
__device__ bf16  g_kv2h[BS_ * 2 * D_], g_kv2l[BS_ * 2 * D_];
__device__ bf16  g_q2h[BS_ * D_],      g_q2l[BS_ * D_];
__device__ float g_scores[32ull * S_ * S_];
__device__ bf16  g_ph[32ull * S_ * S_], g_pl[32ull * S_ * S_];
__device__ bf16  g_vth[32ull * 64 * S_], g_vtl[32ull * 64 * S_];

// Transposed+split weights arena (element offsets). Per-layer-contiguous QKV.
#define DD      (512ull * 512ull)
#define DDF     (512ull * 2048ull)
#define O_EQKV  0ull
#define O_EWO   4718592ull
#define O_EW1   6291456ull
#define O_EW2   12582912ull
#define O_DQKV1 18874368ull
#define O_DWO1  19660800ull
#define O_DWQ2  19922944ull
#define O_DKV2  20185088ull
#define O_DWO2  20709376ull
#define O_DW1   20971520ull
#define O_DW2   22020096ull
#define O_WOUT  23068672ull
#define NWTOT   39452672ull
__device__ bf16 g_wh[NWTOT];
__device__ bf16 g_wl[NWTOT];

// ---------------------------------------------------------------------------
// PTX helpers
// ---------------------------------------------------------------------------
__device__ __forceinline__ uint32_t s2u(const void* p) {
    uint32_t a;
    asm("{ .reg .u64 t; cvta.to.shared.u64 t, %1; cvt.u32.u64 %0, t; }"
        : "=r"(a) : "l"(p));
    return a;
}
__device__ __forceinline__ uint32_t swz(uint32_t o) { return o ^ ((o >> 3) & 0x70u); }

__device__ __forceinline__ void mbar_init(uint32_t a, uint32_t c) {
    asm volatile("mbarrier.init.shared.b64 [%0], %1;" :: "r"(a), "r"(c) : "memory");
}
__device__ __forceinline__ void mbar_wait(uint32_t a, uint32_t ph) {
    uint32_t done;
    asm volatile(
        "{\n\t.reg .pred p;\n\t"
        "mbarrier.try_wait.parity.acquire.cta.shared::cta.b64 p, [%1], %2;\n\t"
        "selp.b32 %0,1,0,p;\n\t}"
        : "=r"(done) : "r"(a), "r"(ph) : "memory");
    if (!done) {
        asm volatile(
            "{\n\t.reg .pred P1;\n\t"
            "WAIT_LOOP_%=:\n\t"
            "mbarrier.try_wait.parity.acquire.cta.shared::cta.b64 P1, [%0], %1, 0x989680;\n\t"
            "@P1 bra.uni WAIT_DONE_%=;\n\t"
            "bra.uni WAIT_LOOP_%=;\n\t"
            "WAIT_DONE_%=:\n\t}"
            :: "r"(a), "r"(ph) : "memory");
    }
}
#define FENCE_ASYNC() asm volatile("fence.proxy.async.shared::cta;" ::: "memory")

__device__ __forceinline__ void cpasync16(uint32_t saddr, const void* g) {
    asm volatile("cp.async.cg.shared.global [%0], [%1], 16;"
                 :: "r"(saddr), "l"(g));
}
#define CP_COMMIT() asm volatile("cp.async.commit_group;" ::: "memory")
#define CP_WAIT1()  asm volatile("cp.async.wait_group 1;" ::: "memory")
#define CP_WAIT0()  asm volatile("cp.async.wait_group 0;" ::: "memory")

#if HAS_TC
__device__ __forceinline__ uint64_t mkdesc(uint32_t addr) {
    const uint64_t base = (2ull << 61) | (1ull << 46) | (64ull << 32) | (1ull << 16);
    return base | ((uint64_t)(addr >> 4) & 0x3FFFull);
}
__device__ __forceinline__ void mma_f16_ss(uint32_t d, uint64_t ad, uint64_t bd,
                                           uint32_t idesc, uint32_t en) {
    asm volatile(
        "{\n\t.reg .pred p;\n\tsetp.ne.u32 p, %5, 0;\n\t"
        "tcgen05.mma.cta_group::1.kind::f16 [%0], %1, %2, %3, {%4,%4,%4,%4}, p;\n\t}"
        :: "r"(d), "l"(ad), "l"(bd), "r"(idesc), "r"(0u), "r"(en) : "memory");
}
#define TC_ALLOC(sa, n)  asm volatile("tcgen05.alloc.cta_group::1.sync.aligned.shared::cta.b32 [%0], %1;" :: "r"(sa), "r"(n) : "memory")
#define TC_DEALLOC(t, n) asm volatile("tcgen05.dealloc.cta_group::1.sync.aligned.b32 %0, %1;" :: "r"(t), "r"(n))
#define TC_COMMIT(mb)    asm volatile("tcgen05.commit.cta_group::1.mbarrier::arrive::one.shared::cluster.b64 [%0];" :: "r"(mb) : "memory")
#define TC_FENCE_AFTER() asm volatile("tcgen05.fence::after_thread_sync;" ::: "memory")
#define TC_WAIT_LD()     asm volatile("tcgen05.wait::ld.sync.aligned;" ::: "memory")

#define TCLD32(r, a) \
    asm volatile( \
        "tcgen05.ld.sync.aligned.32x32b.x32.b32 " \
        "{%0, %1, %2, %3, %4, %5, %6, %7, " \
        " %8, %9, %10, %11, %12, %13, %14, %15, " \
        " %16, %17, %18, %19, %20, %21, %22, %23, " \
        " %24, %25, %26, %27, %28, %29, %30, %31}, [%32];" \
        : "=r"((r)[0]),  "=r"((r)[1]),  "=r"((r)[2]),  "=r"((r)[3]), \
          "=r"((r)[4]),  "=r"((r)[5]),  "=r"((r)[6]),  "=r"((r)[7]), \
          "=r"((r)[8]),  "=r"((r)[9]),  "=r"((r)[10]), "=r"((r)[11]), \
          "=r"((r)[12]), "=r"((r)[13]), "=r"((r)[14]), "=r"((r)[15]), \
          "=r"((r)[16]), "=r"((r)[17]), "=r"((r)[18]), "=r"((r)[19]), \
          "=r"((r)[20]), "=r"((r)[21]), "=r"((r)[22]), "=r"((r)[23]), \
          "=r"((r)[24]), "=r"((r)[25]), "=r"((r)[26]), "=r"((r)[27]), \
          "=r"((r)[28]), "=r"((r)[29]), "=r"((r)[30]), "=r"((r)[31]) \
        : "r"(a))
#endif  // HAS_TC

#define IDESC_N(n) ((1u<<4)|(1u<<7)|(1u<<10)|(((n)/8u)<<17)|(8u<<24))

__device__ __forceinline__ void split_store4(bf16* __restrict__ Hh,
                                             bf16* __restrict__ Hl,
                                             size_t idx, float4 v) {
    bf16 hx = __float2bfloat16_rn(v.x), hy = __float2bfloat16_rn(v.y);
    bf16 hz = __float2bfloat16_rn(v.z), hw = __float2bfloat16_rn(v.w);
    bf16 lx = __float2bfloat16_rn(v.x - __bfloat162float(hx));
    bf16 ly = __float2bfloat16_rn(v.y - __bfloat162float(hy));
    bf16 lz = __float2bfloat16_rn(v.z - __bfloat162float(hz));
    bf16 lw = __float2bfloat16_rn(v.w - __bfloat162float(hw));
    bf162 p;
    p.x = hx; p.y = hy; *(bf162*)(Hh + idx)     = p;
    p.x = hz; p.y = hw; *(bf162*)(Hh + idx + 2) = p;
    p.x = lx; p.y = ly; *(bf162*)(Hl + idx)     = p;
    p.x = lz; p.y = lw; *(bf162*)(Hl + idx + 2) = p;
}

// ---------------------------------------------------------------------------
// Mega weight-conversion kernel
// ---------------------------------------------------------------------------
struct WcvEntry {
    const float* src;
    unsigned long long dst;
    unsigned long long lstride;
    int K, N, ntx, nty, nz, tstart;
};
struct WcvTable { WcvEntry e[17]; };

__global__ __launch_bounds__(256) void wconv_all(
    WcvTable tab, int nent, bf16* __restrict__ oh, bf16* __restrict__ ol)
{
    __shared__ float tile[32][33];
    int tid = blockIdx.x;
    int i = 0;
    while (i + 1 < nent && tid >= tab.e[i + 1].tstart) i++;
    const WcvEntry E = tab.e[i];
    int t = tid - E.tstart;
    int per_z = E.ntx * E.nty;
    int z  = t / per_z;
    int rm = t - z * per_z;
    int txb = rm % E.ntx, tyb = rm / E.ntx;
    const int n0 = txb * 32, k0 = tyb * 32;
    const int K = E.K, N = E.N;
    const float* Wb = E.src + (size_t)z * K * N;
    bf16* ohb = oh + E.dst + (size_t)z * E.lstride;
    bf16* olb = ol + E.dst + (size_t)z * E.lstride;

    const int tx = threadIdx.x, ty = threadIdx.y;
    #pragma unroll
    for (int ii = 0; ii < 4; ii++)
        tile[ty + 8 * ii][tx] = Wb[(size_t)(k0 + ty + 8 * ii) * N + n0 + tx];
    __syncthreads();
    #pragma unroll
    for (int ii = 0; ii < 4; ii++) {
        float v = tile[tx][ty + 8 * ii];
        int n = n0 + ty + 8 * ii, k = k0 + tx;
        size_t idx = (size_t)n * K + k;
        bf16 h = __float2bfloat16_rn(v);
        ohb[idx] = h;
        olb[idx] = __float2bfloat16_rn(v - __bfloat162float(h));
    }
}

// ---------------------------------------------------------------------------
// Embedding + positional encoding (+ bf16 split)
// ---------------------------------------------------------------------------
__global__ __launch_bounds__(128) void embed_kernel(
    const int* __restrict__ ids, const float* __restrict__ emb,
    float* __restrict__ out, bf16* __restrict__ oh, bf16* __restrict__ ol)
{
    const int row = blockIdx.x;
    const int s   = row & (S_ - 1);
    const int tok = ids[row];
    const int t   = threadIdx.x;
    const float c = -logf(10000.0f) / (float)D_;
    float4 v;
    float tmp[4];
    #pragma unroll
    for (int j = 0; j < 4; j++) {
        int d  = t * 4 + j;
        int tj = d >> 1;
        float div = expf((float)(2 * tj) * c);
        float ang = (float)s * div;
        float pe  = (d & 1) ? cosf(ang) : sinf(ang);
        tmp[j] = emb[(size_t)tok * D_ + d] + pe;
    }
    v.x = tmp[0]; v.y = tmp[1]; v.z = tmp[2]; v.w = tmp[3];
    size_t base = (size_t)row * D_ + t * 4;
    *(float4*)(out + base) = v;
    split_store4(oh, ol, base, v);
}

// ---------------------------------------------------------------------------
// Fused residual + LayerNorm (+ bf16 split)
// ---------------------------------------------------------------------------
__global__ __launch_bounds__(128) void add_ln_kernel(
    const float* __restrict__ A, const float* __restrict__ Bv,
    float* __restrict__ Out, bf16* __restrict__ Oh, bf16* __restrict__ Ol)
{
    const int row = blockIdx.x;
    const int t   = threadIdx.x;
    const size_t base = (size_t)row * D_ + t * 4;
    float4 a = *(const float4*)(A + base);
    float4 b = *(const float4*)(Bv + base);
    float4 vv;
    vv.x = a.x + b.x; vv.y = a.y + b.y; vv.z = a.z + b.z; vv.w = a.w + b.w;

    float s  = vv.x + vv.y + vv.z + vv.w;
    float sq = vv.x * vv.x + vv.y * vv.y + vv.z * vv.z + vv.w * vv.w;
    __shared__ float redS[4], redQ[4];
    #pragma unroll
    for (int off = 16; off > 0; off >>= 1) {
        s  += __shfl_xor_sync(0xffffffffu, s,  off);
        sq += __shfl_xor_sync(0xffffffffu, sq, off);
    }
    const int wid = t >> 5, lane = t & 31;
    if (lane == 0) { redS[wid] = s; redQ[wid] = sq; }
    __syncthreads();
    s  = redS[0] + redS[1] + redS[2] + redS[3];
    sq = redQ[0] + redQ[1] + redQ[2] + redQ[3];
    float mean = s * (1.0f / D_);
    float var  = sq * (1.0f / D_) - mean * mean;
    float inv  = rsqrtf(var + 1e-5f);
    float4 o;
    o.x = (vv.x - mean) * inv; o.y = (vv.y - mean) * inv;
    o.z = (vv.z - mean) * inv; o.w = (vv.w - mean) * inv;
    *(float4*)(Out + base) = o;
    split_store4(Oh, Ol, base, o);
}

// ---------------------------------------------------------------------------
// tcgen05 split-fp32 GEMM, MT=1, 3-stage cp.async pipeline.
// EPI: 0 ->C ; 1 +bias->C ; 3 +bias+relu->hi/lo ; 4 split->hi/lo ;
//      5 split->hi/lo for cols<vsplit, V-transposed hi/lo otherwise
// ---------------------------------------------------------------------------
#define GIDESC    IDESC_N(128)
#define STAGE_B   65536
#define NSTG      3
#define SMEM_GEMM (NSTG * STAGE_B + 1024)

template<int EPI>
__global__ __launch_bounds__(256)
void bgemm(const bf16* __restrict__ Ah, const bf16* __restrict__ Al,
           const bf16* __restrict__ Bh, const bf16* __restrict__ Bl,
           const float* __restrict__ bias, float* __restrict__ C,
           bf16* __restrict__ Ch, bf16* __restrict__ Cl,
           bf16* __restrict__ Vh, bf16* __restrict__ Vl, int vsplit,
           int M, int N, int K)
{
#if HAS_TC
    __shared__ __align__(16) uint32_t s_tptr[4];
    __shared__ __align__(16) uint64_t s_mbar[NSTG];
    extern __shared__ char smem[];
    const uint32_t tiles = (s2u(smem) + 1023u) & ~1023u;
    const uint32_t tptr  = s2u(s_tptr);
    uint32_t mb[NSTG];
    #pragma unroll
    for (int i = 0; i < NSTG; i++) mb[i] = s2u(&s_mbar[i]);

    const int t   = threadIdx.x;
    const int wid = t >> 5;
    const int bm  = blockIdx.y * 128, bn = blockIdx.x * 128;

    if (wid == 0) TC_ALLOC(tptr, 128);
    if (t == 0) {
        #pragma unroll
        for (int i = 0; i < NSTG; i++) mbar_init(mb[i], 1);
    }
    __syncthreads();
    const uint32_t tmem = s_tptr[0];

    const int r  = t >> 3;
    const int ck = t & 7;
    const int nch = K >> 6;
    int use[NSTG];
    #pragma unroll
    for (int i = 0; i < NSTG; i++) use[i] = 0;

    auto load_chunk = [&](int c, int s) {
        const uint32_t base = tiles + s * STAGE_B;
        const uint32_t aH = base, aL = base + 16384;
        const uint32_t bH = base + 32768, bL = base + 49152;
        const int k0 = c << 6;
        #pragma unroll
        for (int it = 0; it < 4; it++) {
            int row = r + it * 32;
            size_t g = (size_t)(bm + row) * K + k0 + ck * 8;
            uint32_t so = swz((uint32_t)(row * 128 + ck * 16));
            cpasync16(aH + so, Ah + g);
            cpasync16(aL + so, Al + g);
        }
        #pragma unroll
        for (int it = 0; it < 4; it++) {
            int row = r + it * 32;
            size_t g = (size_t)(bn + row) * K + k0 + ck * 8;
            uint32_t so = swz((uint32_t)(row * 128 + ck * 16));
            cpasync16(bH + so, Bh + g);
            cpasync16(bL + so, Bl + g);
        }
        CP_COMMIT();
    };

    load_chunk(0, 0);
    for (int c = 0; c < nch; c++) {
        const int s = c % NSTG;
        if (c + 1 < nch) {
            const int s2 = (c + 1) % NSTG;
            if (use[s2] > 0) mbar_wait(mb[s2], (use[s2] - 1) & 1);
            load_chunk(c + 1, s2);
            CP_WAIT1();
        } else {
            CP_WAIT0();
        }
        FENCE_ASYNC();
        __syncthreads();
        if (t == 0) {
            const uint32_t base = tiles + s * STAGE_B;
            uint64_t dah = mkdesc(base),         dal = mkdesc(base + 16384);
            uint64_t dbh = mkdesc(base + 32768), dbl = mkdesc(base + 49152);
            #pragma unroll
            for (int j = 0; j < 4; j++)
                mma_f16_ss(tmem, dah + 2 * j, dbh + 2 * j, GIDESC,
                           (c == 0 && j == 0) ? 0u : 1u);
            #pragma unroll
            for (int j = 0; j < 4; j++)
                mma_f16_ss(tmem, dah + 2 * j, dbl + 2 * j, GIDESC, 1u);
            #pragma unroll
            for (int j = 0; j < 4; j++)
                mma_f16_ss(tmem, dal + 2 * j, dbh + 2 * j, GIDESC, 1u);
            TC_COMMIT(mb[s]);
        }
        use[s]++;
    }
    #pragma unroll
    for (int i = 0; i < NSTG; i++)
        if (use[i] > 0) mbar_wait(mb[i], (use[i] - 1) & 1);
    TC_FENCE_AFTER();

    {
        const int sub = wid & 3, half = wid >> 2, lane = t & 31;
        const int rowg = bm + sub * 32 + lane;
        #pragma unroll
        for (int cc = 0; cc < 2; cc++) {
            const int col0 = half * 64 + cc * 32;
            uint32_t regs[32];
            TCLD32(regs, tmem + col0);
            TC_WAIT_LD();
            const int colbase = bn + col0;
            if (EPI == 0) {
                #pragma unroll
                for (int j = 0; j < 32; j += 4) {
                    float4 v;
                    v.x = __uint_as_float(regs[j]);
                    v.y = __uint_as_float(regs[j + 1]);
                    v.z = __uint_as_float(regs[j + 2]);
                    v.w = __uint_as_float(regs[j + 3]);
                    *(float4*)(C + (size_t)rowg * N + colbase + j) = v;
                }
            } else if (EPI == 1) {
                #pragma unroll
                for (int j = 0; j < 32; j += 4) {
                    float4 bv = *(const float4*)(bias + colbase + j);
                    float4 v;
                    v.x = __uint_as_float(regs[j])     + bv.x;
                    v.y = __uint_as_float(regs[j + 1]) + bv.y;
                    v.z = __uint_as_float(regs[j + 2]) + bv.z;
                    v.w = __uint_as_float(regs[j + 3]) + bv.w;
                    *(float4*)(C + (size_t)rowg * N + colbase + j) = v;
                }
            } else if (EPI == 3) {
                #pragma unroll
                for (int j = 0; j < 32; j += 4) {
                    float4 bv = *(const float4*)(bias + colbase + j);
                    float4 v;
                    v.x = fmaxf(__uint_as_float(regs[j])     + bv.x, 0.f);
                    v.y = fmaxf(__uint_as_float(regs[j + 1]) + bv.y, 0.f);
                    v.z = fmaxf(__uint_as_float(regs[j + 2]) + bv.z, 0.f);
                    v.w = fmaxf(__uint_as_float(regs[j + 3]) + bv.w, 0.f);
                    split_store4(Ch, Cl, (size_t)rowg * N + colbase + j, v);
                }
            } else if (EPI == 4) {
                #pragma unroll
                for (int j = 0; j < 32; j += 4) {
                    float4 v;
                    v.x = __uint_as_float(regs[j]);
                    v.y = __uint_as_float(regs[j + 1]);
                    v.z = __uint_as_float(regs[j + 2]);
                    v.w = __uint_as_float(regs[j + 3]);
                    split_store4(Ch, Cl, (size_t)rowg * N + colbase + j, v);
                }
            } else {  // EPI == 5
                if (colbase < vsplit) {
                    #pragma unroll
                    for (int j = 0; j < 32; j += 4) {
                        float4 v;
                        v.x = __uint_as_float(regs[j]);
                        v.y = __uint_as_float(regs[j + 1]);
                        v.z = __uint_as_float(regs[j + 2]);
                        v.w = __uint_as_float(regs[j + 3]);
                        split_store4(Ch, Cl, (size_t)rowg * N + colbase + j, v);
                    }
                } else {
                    const int vcol = colbase - vsplit;
                    const int z  = (rowg >> 9) * 8 + (vcol >> 6);
                    const int d0 = vcol & 63;
                    const int tok = rowg & 511;
                    const size_t vb = ((size_t)z * 64 + d0) * 512 + tok;
                    #pragma unroll
                    for (int j = 0; j < 32; j++) {
                        float fv = __uint_as_float(regs[j]);
                        bf16 h = __float2bfloat16_rn(fv);
                        bf16 l = __float2bfloat16_rn(fv - __bfloat162float(h));
                        Vh[vb + (size_t)j * 512] = h;
                        Vl[vb + (size_t)j * 512] = l;
                    }
                }
            }
        }
    }
    __syncthreads();
    if (wid == 0) TC_DEALLOC(tmem, 128);
#else
    const int t  = threadIdx.x;
    const int bm = blockIdx.y * 128, bn = blockIdx.x * 128;
    const int r0 = (t >> 4) * 8;
    const int c0 = (t & 15) * 8;
    for (int i = 0; i < 8; i++) {
        int rowg = bm + r0 + i;
        for (int j = 0; j < 8; j++) {
            int col = bn + c0 + j;
            float acc = 0.f;
            for (int k = 0; k < K; k++) {
                float av = __bfloat162float(Ah[(size_t)rowg * K + k])
                         + __bfloat162float(Al[(size_t)rowg * K + k]);
                float bv = __bfloat162float(Bh[(size_t)col * K + k])
                         + __bfloat162float(Bl[(size_t)col * K + k]);
                acc += av * bv;
            }
            if (EPI == 1 || EPI == 3) acc += bias[col];
            if (EPI == 3) acc = fmaxf(acc, 0.f);
            if (EPI == 0 || EPI == 1) {
                C[(size_t)rowg * N + col] = acc;
            } else if (EPI == 3 || EPI == 4 || (EPI == 5 && col < vsplit)) {
                bf16 h = __float2bfloat16_rn(acc);
                Ch[(size_t)rowg * N + col] = h;
                Cl[(size_t)rowg * N + col] =
                    __float2bfloat16_rn(acc - __bfloat162float(h));
            } else {
                int vcol = col - vsplit;
                int z = (rowg >> 9) * 8 + (vcol >> 6);
                int d = vcol & 63, tok = rowg & 511;
                bf16 h = __float2bfloat16_rn(acc);
                Vh[((size_t)z * 64 + d) * 512 + tok] = h;
                Vl[((size_t)z * 64 + d) * 512 + tok] =
                    __float2bfloat16_rn(acc - __bfloat162float(h));
            }
        }
    }
#endif
}

// ---------------------------------------------------------------------------
// bgemm2: MT=2 for the logits GEMM, grid (M/256, N/128) with x = M so each
// wave covers all 8 m-tiles of consecutive n-tiles: every Wout block is
// loaded from DRAM once and reused by the co-resident m-tiles through L2.
// ---------------------------------------------------------------------------
#define STAGE2_B   98304
#define NSTG2      2
#define SMEM_GEMM2 (NSTG2 * STAGE2_B + 1024)

__global__ __launch_bounds__(256)
void bgemm2(const bf16* __restrict__ Ah, const bf16* __restrict__ Al,
            const bf16* __restrict__ Bh, const bf16* __restrict__ Bl,
            const float* __restrict__ bias, float* __restrict__ C,
            int M, int N, int K)
{
#if HAS_TC
    __shared__ __align__(16) uint32_t s_tptr[4];
    __shared__ __align__(16) uint64_t s_mbar[NSTG2];
    extern __shared__ char smem[];
    const uint32_t tiles = (s2u(smem) + 1023u) & ~1023u;
    const uint32_t tptr  = s2u(s_tptr);
    uint32_t mb[NSTG2];
    #pragma unroll
    for (int i = 0; i < NSTG2; i++) mb[i] = s2u(&s_mbar[i]);

    const int t   = threadIdx.x;
    const int wid = t >> 5;
    const int bm  = blockIdx.x * 256, bn = blockIdx.y * 128;   // x = M (fast)

    if (wid == 0) TC_ALLOC(tptr, 256);
    if (t == 0) {
        #pragma unroll
        for (int i = 0; i < NSTG2; i++) mbar_init(mb[i], 1);
    }
    __syncthreads();
    const uint32_t tmem = s_tptr[0];

    const int r  = t >> 3;
    const int ck = t & 7;
    const int nch = K >> 6;
    int use[NSTG2];
    #pragma unroll
    for (int i = 0; i < NSTG2; i++) use[i] = 0;

    auto load_chunk = [&](int c, int s) {
        const uint32_t base = tiles + s * STAGE2_B;
        const int k0 = c << 6;
        #pragma unroll
        for (int m = 0; m < 2; m++) {
            const uint32_t aH = base + m * 32768, aL = aH + 16384;
            #pragma unroll
            for (int it = 0; it < 4; it++) {
                int row = r + it * 32;
                size_t g = (size_t)(bm + m * 128 + row) * K + k0 + ck * 8;
                uint32_t so = swz((uint32_t)(row * 128 + ck * 16));
                cpasync16(aH + so, Ah + g);
                cpasync16(aL + so, Al + g);
            }
        }
        const uint32_t bH = base + 65536, bL = base + 81920;
        #pragma unroll
        for (int it = 0; it < 4; it++) {
            int row = r + it * 32;
            size_t g = (size_t)(bn + row) * K + k0 + ck * 8;
            uint32_t so = swz((uint32_t)(row * 128 + ck * 16));
            cpasync16(bH + so, Bh + g);
            cpasync16(bL + so, Bl + g);
        }
        CP_COMMIT();
    };

    load_chunk(0, 0);
    for (int c = 0; c < nch; c++) {
        const int s = c % NSTG2;
        if (c + 1 < nch) {
            const int s2 = (c + 1) % NSTG2;
            if (use[s2] > 0) mbar_wait(mb[s2], (use[s2] - 1) & 1);
            load_chunk(c + 1, s2);
            CP_WAIT1();
        } else {
            CP_WAIT0();
        }
        FENCE_ASYNC();
        __syncthreads();
        if (t == 0) {
            const uint32_t base = tiles + s * STAGE2_B;
            uint64_t dbh = mkdesc(base + 65536), dbl = mkdesc(base + 81920);
            #pragma unroll
            for (int m = 0; m < 2; m++) {
                uint64_t dah = mkdesc(base + m * 32768);
                uint64_t dal = mkdesc(base + m * 32768 + 16384);
                const uint32_t acc = tmem + m * 128;
                #pragma unroll
                for (int j = 0; j < 4; j++)
                    mma_f16_ss(acc, dah + 2 * j, dbh + 2 * j, GIDESC,
                               (c == 0 && j == 0) ? 0u : 1u);
                #pragma unroll
                for (int j = 0; j < 4; j++)
                    mma_f16_ss(acc, dah + 2 * j, dbl + 2 * j, GIDESC, 1u);
                #pragma unroll
                for (int j = 0; j < 4; j++)
                    mma_f16_ss(acc, dal + 2 * j, dbh + 2 * j, GIDESC, 1u);
            }
            TC_COMMIT(mb[s]);
        }
        use[s]++;
    }
    #pragma unroll
    for (int i = 0; i < NSTG2; i++)
        if (use[i] > 0) mbar_wait(mb[i], (use[i] - 1) & 1);
    TC_FENCE_AFTER();

    {
        const int m = wid >> 2, sub = wid & 3, lane = t & 31;
        const int rowg = bm + m * 128 + sub * 32 + lane;
        #pragma unroll
        for (int cc = 0; cc < 4; cc++) {
            const int col0 = cc * 32;
            uint32_t regs[32];
            TCLD32(regs, tmem + m * 128 + col0);
            TC_WAIT_LD();
            const int colbase = bn + col0;
            #pragma unroll
            for (int j = 0; j < 32; j += 4) {
                float4 bv = *(const float4*)(bias + colbase + j);
                float4 v;
                v.x = __uint_as_float(regs[j])     + bv.x;
                v.y = __uint_as_float(regs[j + 1]) + bv.y;
                v.z = __uint_as_float(regs[j + 2]) + bv.z;
                v.w = __uint_as_float(regs[j + 3]) + bv.w;
                *(float4*)(C + (size_t)rowg * N + colbase + j) = v;
            }
        }
    }
    __syncthreads();
    if (wid == 0) TC_DEALLOC(tmem, 256);
#else
    const int t  = threadIdx.x;
    const int bm = blockIdx.x * 256, bn = blockIdx.y * 128;
    const int r0 = (t >> 4) * 16;
    const int c0 = (t & 15) * 8;
    for (int i = 0; i < 16; i++) {
        int rowg = bm + r0 + i;
        for (int j = 0; j < 8; j++) {
            int col = bn + c0 + j;
            float acc = 0.f;
            for (int k = 0; k < K; k++) {
                float av = __bfloat162float(Ah[(size_t)rowg * K + k])
                         + __bfloat162float(Al[(size_t)rowg * K + k]);
                float bv = __bfloat162float(Bh[(size_t)col * K + k])
                         + __bfloat162float(Bl[(size_t)col * K + k]);
                acc += av * bv;
            }
            C[(size_t)rowg * N + col] = acc + bias[col];
        }
    }
#endif
}

// ---------------------------------------------------------------------------
// QK^T GEMM (round-11 proven): one CTA per (q-tile, z) computes all 4
// k-tiles. A once (32KB), 4 B tiles (128KB), 48 MMAs into 512-col TMEM,
// one commit/wait. Grid (4, 32).
// ---------------------------------------------------------------------------
#define QK_SMEM (32768 + 4 * 32768 + 1024)
__global__ __launch_bounds__(256) void qk_gemm(
    const bf16* __restrict__ Qh, const bf16* __restrict__ Ql, int qp,
    const bf16* __restrict__ Kh, const bf16* __restrict__ Kl, int kp,
    float* __restrict__ scores)
{
    const int z = blockIdx.y, b = z >> 3, h = z & 7;
    const int bm = blockIdx.x * 128;
    const size_t qoff = (size_t)(b * S_) * qp + h * 64;
    const size_t koff = (size_t)(b * S_) * kp + h * 64;
#if HAS_TC
    __shared__ __align__(16) uint32_t s_tptr[4];
    __shared__ __align__(16) uint64_t s_mbar[1];
    extern __shared__ char smem[];
    const uint32_t tiles = (s2u(smem) + 1023u) & ~1023u;
    const uint32_t tptr  = s2u(s_tptr);
    const uint32_t mb    = s2u(&s_mbar[0]);

    const int t   = threadIdx.x;
    const int wid = t >> 5;
    if (wid == 0) TC_ALLOC(tptr, 512);
    if (t == 0) mbar_init(mb, 1);
    __syncthreads();
    const uint32_t tmem = s_tptr[0];

    const int r  = t >> 3;
    const int ck = t & 7;
    const uint32_t aH = tiles, aL = tiles + 16384;
    #pragma unroll
    for (int it = 0; it < 4; it++) {
        int row = r + it * 32;
        uint32_t so = swz((uint32_t)(row * 128 + ck * 16));
        cpasync16(aH + so, Qh + qoff + (size_t)(bm + row) * qp + ck * 8);
        cpasync16(aL + so, Ql + qoff + (size_t)(bm + row) * qp + ck * 8);
    }
    #pragma unroll
    for (int kb = 0; kb < 4; kb++) {
        const uint32_t bH = tiles + 32768 + kb * 32768, bL = bH + 16384;
        #pragma unroll
        for (int it = 0; it < 4; it++) {
            int row = r + it * 32;
            uint32_t so = swz((uint32_t)(row * 128 + ck * 16));
            cpasync16(bH + so, Kh + koff + (size_t)(kb * 128 + row) * kp + ck * 8);
            cpasync16(bL + so, Kl + koff + (size_t)(kb * 128 + row) * kp + ck * 8);
        }
    }
    CP_COMMIT(); CP_WAIT0();
    FENCE_ASYNC();
    __syncthreads();
    if (t == 0) {
        uint64_t dah = mkdesc(aH), dal = mkdesc(aL);
        #pragma unroll
        for (int kb = 0; kb < 4; kb++) {
            const uint32_t bH = tiles + 32768 + kb * 32768;
            uint64_t dbh = mkdesc(bH), dbl = mkdesc(bH + 16384);
            const uint32_t acc = tmem + kb * 128;
            #pragma unroll
            for (int j = 0; j < 4; j++)
                mma_f16_ss(acc, dah + 2 * j, dbh + 2 * j, GIDESC, j ? 1u : 0u);
            #pragma unroll
            for (int j = 0; j < 4; j++)
                mma_f16_ss(acc, dah + 2 * j, dbl + 2 * j, GIDESC, 1u);
            #pragma unroll
            for (int j = 0; j < 4; j++)
                mma_f16_ss(acc, dal + 2 * j, dbh + 2 * j, GIDESC, 1u);
        }
        TC_COMMIT(mb);
    }
    mbar_wait(mb, 0);
    TC_FENCE_AFTER();
    {
        const int sub = wid & 3, half = wid >> 2, lane = t & 31;
        const int rowg = bm + sub * 32 + lane;
        float* out = scores + ((size_t)z * S_ + rowg) * S_;
        #pragma unroll
        for (int kb = 0; kb < 4; kb++) {
            #pragma unroll
            for (int cc = 0; cc < 2; cc++) {
                const int col0 = half * 64 + cc * 32;
                uint32_t regs[32];
                TCLD32(regs, tmem + kb * 128 + col0);
                TC_WAIT_LD();
                #pragma unroll
                for (int j = 0; j < 32; j += 4) {
                    float4 v;
                    v.x = __uint_as_float(regs[j])     * 0.125f;
                    v.y = __uint_as_float(regs[j + 1]) * 0.125f;
                    v.z = __uint_as_float(regs[j + 2]) * 0.125f;
                    v.w = __uint_as_float(regs[j + 3]) * 0.125f;
                    *(float4*)(out + kb * 128 + col0 + j) = v;
                }
            }
        }
    }
    __syncthreads();
    if (wid == 0) TC_DEALLOC(tmem, 512);
#else
    const int t = threadIdx.x;
    for (int idx = t; idx < 128 * 512; idx += 256) {
        int rr = idx >> 9, cc = idx & 511;
        float acc = 0.f;
        for (int k = 0; k < 64; k++) {
            float qv = __bfloat162float(Qh[qoff + (size_t)(bm + rr) * qp + k])
                     + __bfloat162float(Ql[qoff + (size_t)(bm + rr) * qp + k]);
            float kv = __bfloat162float(Kh[koff + (size_t)cc * kp + k])
                     + __bfloat162float(Kl[koff + (size_t)cc * kp + k]);
            acc += qv * kv;
        }
        scores[((size_t)z * S_ + bm + rr) * S_ + cc] = acc * 0.125f;
    }
#endif
}

// ---------------------------------------------------------------------------
// Masked softmax -> P hi/lo (normalized)
// ---------------------------------------------------------------------------
__global__ __launch_bounds__(128) void softmax_kernel(
    const float* __restrict__ scores, const int* __restrict__ kv_tok,
    bf16* __restrict__ Ph, bf16* __restrict__ Pl, int causal)
{
    const int q = blockIdx.x, z = blockIdx.y, b = z >> 3;
    const int t = threadIdx.x;
    const size_t base = ((size_t)z * S_ + q) * S_;
    float4 s = *(const float4*)(scores + base + t * 4);
    float vals[4] = {s.x, s.y, s.z, s.w};
    #pragma unroll
    for (int j = 0; j < 4; j++) {
        int k = t * 4 + j;
        if (kv_tok[b * S_ + k] == 0) vals[j] += NEGV;
        if (causal && k > q)         vals[j] += NEGV;
    }
    float m = fmaxf(fmaxf(vals[0], vals[1]), fmaxf(vals[2], vals[3]));
    __shared__ float redM[4], redS[4];
    #pragma unroll
    for (int off = 16; off > 0; off >>= 1)
        m = fmaxf(m, __shfl_xor_sync(0xffffffffu, m, off));
    const int wid = t >> 5, lane = t & 31;
    if (lane == 0) redM[wid] = m;
    __syncthreads();
    m = fmaxf(fmaxf(redM[0], redM[1]), fmaxf(redM[2], redM[3]));

    float e[4], ssum = 0.f;
    #pragma unroll
    for (int j = 0; j < 4; j++) { e[j] = __expf(vals[j] - m); ssum += e[j]; }
    #pragma unroll
    for (int off = 16; off > 0; off >>= 1)
        ssum += __shfl_xor_sync(0xffffffffu, ssum, off);
    if (lane == 0) redS[wid] = ssum;
    __syncthreads();
    ssum = redS[0] + redS[1] + redS[2] + redS[3];
    float inv = 1.f / ssum;
    float4 p = make_float4(e[0] * inv, e[1] * inv, e[2] * inv, e[3] * inv);
    split_store4(Ph, Pl, base + t * 4, p);
}

// ---------------------------------------------------------------------------
// AV GEMM: out = P @ V via V^T, grid (1,4,32), 3-stage pipeline
// ---------------------------------------------------------------------------
#define AV_STAGE  49152
#define AV_NSTG   3
#define AV_SMEM   (AV_NSTG * AV_STAGE + 1024)
#define AVIDESC   IDESC_N(64)
__global__ __launch_bounds__(256) void av_gemm(
    const bf16* __restrict__ Ph, const bf16* __restrict__ Pl,
    const bf16* __restrict__ Vth, const bf16* __restrict__ Vtl,
    bf16* __restrict__ Oh, bf16* __restrict__ Ol)
{
    const int z = blockIdx.z, b = z >> 3, h = z & 7;
    const int bm = blockIdx.y * 128;
    const bf16* Pzh = Ph  + (size_t)z * S_ * S_;
    const bf16* Pzl = Pl  + (size_t)z * S_ * S_;
    const bf16* Vzh = Vth + (size_t)z * 64 * S_;
    const bf16* Vzl = Vtl + (size_t)z * 64 * S_;
#if HAS_TC
    __shared__ __align__(16) uint32_t s_tptr[4];
    __shared__ __align__(16) uint64_t s_mbar[AV_NSTG];
    extern __shared__ char smem[];
    const uint32_t tiles = (s2u(smem) + 1023u) & ~1023u;
    const uint32_t tptr  = s2u(s_tptr);
    uint32_t mb[AV_NSTG];
    #pragma unroll
    for (int i = 0; i < AV_NSTG; i++) mb[i] = s2u(&s_mbar[i]);

    const int t   = threadIdx.x;
    const int wid = t >> 5;
    if (wid == 0) TC_ALLOC(tptr, 128);
    if (t == 0) {
        #pragma unroll
        for (int i = 0; i < AV_NSTG; i++) mbar_init(mb[i], 1);
    }
    __syncthreads();
    const uint32_t tmem = s_tptr[0];

    const int r  = t >> 3;
    const int ck = t & 7;
    int use[AV_NSTG];
    #pragma unroll
    for (int i = 0; i < AV_NSTG; i++) use[i] = 0;

    auto load_chunk = [&](int c, int s) {
        const uint32_t base = tiles + s * AV_STAGE;
        const uint32_t aH = base, aL = base + 16384;
        const uint32_t bH = base + 32768, bL = base + 40960;
        const int k0 = c << 6;
        #pragma unroll
        for (int it = 0; it < 4; it++) {
            int row = r + it * 32;
            size_t g = (size_t)(bm + row) * S_ + k0 + ck * 8;
            uint32_t so = swz((uint32_t)(row * 128 + ck * 16));
            cpasync16(aH + so, Pzh + g);
            cpasync16(aL + so, Pzl + g);
        }
        #pragma unroll
        for (int it = 0; it < 2; it++) {
            int row = r + it * 32;
            size_t g = (size_t)row * S_ + k0 + ck * 8;
            uint32_t so = swz((uint32_t)(row * 128 + ck * 16));
            cpasync16(bH + so, Vzh + g);
            cpasync16(bL + so, Vzl + g);
        }
        CP_COMMIT();
    };

    const int nch = S_ >> 6;
    load_chunk(0, 0);
    for (int c = 0; c < nch; c++) {
        const int s = c % AV_NSTG;
        if (c + 1 < nch) {
            const int s2 = (c + 1) % AV_NSTG;
            if (use[s2] > 0) mbar_wait(mb[s2], (use[s2] - 1) & 1);
            load_chunk(c + 1, s2);
            CP_WAIT1();
        } else {
            CP_WAIT0();
        }
        FENCE_ASYNC();
        __syncthreads();
        if (t == 0) {
            const uint32_t base = tiles + s * AV_STAGE;
            uint64_t dah = mkdesc(base),         dal = mkdesc(base + 16384);
            uint64_t dbh = mkdesc(base + 32768), dbl = mkdesc(base + 40960);
            #pragma unroll
            for (int j = 0; j < 4; j++)
                mma_f16_ss(tmem, dah + 2 * j, dbh + 2 * j, AVIDESC,
                           (c == 0 && j == 0) ? 0u : 1u);
            #pragma unroll
            for (int j = 0; j < 4; j++)
                mma_f16_ss(tmem, dah + 2 * j, dbl + 2 * j, AVIDESC, 1u);
            #pragma unroll
            for (int j = 0; j < 4; j++)
                mma_f16_ss(tmem, dal + 2 * j, dbh + 2 * j, AVIDESC, 1u);
            TC_COMMIT(mb[s]);
        }
        use[s]++;
    }
    #pragma unroll
    for (int i = 0; i < AV_NSTG; i++)
        if (use[i] > 0) mbar_wait(mb[i], (use[i] - 1) & 1);
    TC_FENCE_AFTER();
    {
        const int sub = wid & 3, half = wid >> 2, lane = t & 31;
        const int rowg = bm + sub * 32 + lane;
        const int col0 = half * 32;
        uint32_t regs[32];
        TCLD32(regs, tmem + col0);
        TC_WAIT_LD();
        #pragma unroll
        for (int j = 0; j < 32; j += 4) {
            float4 v;
            v.x = __uint_as_float(regs[j]);
            v.y = __uint_as_float(regs[j + 1]);
            v.z = __uint_as_float(regs[j + 2]);
            v.w = __uint_as_float(regs[j + 3]);
            size_t idx = ((size_t)(b * S_) + rowg) * D_ + h * 64 + col0 + j;
            split_store4(Oh, Ol, idx, v);
        }
    }
    __syncthreads();
    if (wid == 0) TC_DEALLOC(tmem, 128);
#else
    const int t = threadIdx.x;
    for (int idx = t; idx < 128 * 64; idx += 256) {
        int rr = idx >> 6, cc = idx & 63;
        float acc = 0.f;
        for (int k = 0; k < S_; k++) {
            float pv = __bfloat162float(Pzh[(size_t)(bm + rr) * S_ + k])
                     + __bfloat162float(Pzl[(size_t)(bm + rr) * S_ + k]);
            float vv = __bfloat162float(Vzh[(size_t)cc * S_ + k])
                     + __bfloat162float(Vzl[(size_t)cc * S_ + k]);
            acc += pv * vv;
        }
        size_t oidx = ((size_t)(b * S_) + bm + rr) * D_ + h * 64 + cc;
        bf16 hh2 = __float2bfloat16_rn(acc);
        Oh[oidx] = hh2;
        Ol[oidx] = __float2bfloat16_rn(acc - __bfloat162float(hh2));
    }
#endif
}

// ---------------------------------------------------------------------------
// Host driver
// ---------------------------------------------------------------------------
static inline void run_bgemm(int epi, const bf16* Ah, const bf16* Al,
                             const bf16* Bh, const bf16* Bl, const float* bias,
                             float* C, bf16* Ch, bf16* Cl,
                             bf16* Vh, bf16* Vl, int vsplit,
                             int M, int N, int K)
{
    dim3 grid(N / 128, M / 128);
    if (epi == 0)
        bgemm<0><<<grid, 256, SMEM_GEMM>>>(Ah, Al, Bh, Bl, bias, C, Ch, Cl, Vh, Vl, vsplit, M, N, K);
    else if (epi == 1)
        bgemm<1><<<grid, 256, SMEM_GEMM>>>(Ah, Al, Bh, Bl, bias, C, Ch, Cl, Vh, Vl, vsplit, M, N, K);
    else if (epi == 3)
        bgemm<3><<<grid, 256, SMEM_GEMM>>>(Ah, Al, Bh, Bl, bias, C, Ch, Cl, Vh, Vl, vsplit, M, N, K);
    else if (epi == 4)
        bgemm<4><<<grid, 256, SMEM_GEMM>>>(Ah, Al, Bh, Bl, bias, C, Ch, Cl, Vh, Vl, vsplit, M, N, K);
    else
        bgemm<5><<<grid, 256, SMEM_GEMM>>>(Ah, Al, Bh, Bl, bias, C, Ch, Cl, Vh, Vl, vsplit, M, N, K);
}

extern "C" void kernel_launch(void* const* d_in, const int* in_sizes, int n_in,
                              void* d_out, int out_size)
{
    const int DDi = D_ * D_;

    int iEWq, iEWk, iEWv, iEWo, iEW1, iEb1, iEW2, iEb2;
    int iDWq1, iDWk1, iDWv1, iDWo1, iDWq2, iDWk2, iDWv2, iDWo2;
    int iDW1, iDb1, iDW2, iDb2, iWout, iBout;
    if (n_in >= 8 && in_sizes[7] == L_ * DDi) {
        iEWq = 3; iEWk = 4; iEWv = 5; iEWo = 6;
        iDWq1 = 7; iDWk1 = 8; iDWv1 = 9; iDWo1 = 10;
        iDWq2 = 11; iDWk2 = 12; iDWv2 = 13; iDWo2 = 14;
        iEW1 = 15; iEb1 = 16; iEW2 = 17; iEb2 = 18;
        iDW1 = 19; iDb1 = 20; iDW2 = 21; iDb2 = 22;
        iWout = 23; iBout = 24;
    } else {
        iEWq = 3; iEWk = 4; iEWv = 5; iEWo = 6;
        iEW1 = 7; iEb1 = 8; iEW2 = 9; iEb2 = 10;
        iDWq1 = 11; iDWk1 = 12; iDWv1 = 13; iDWo1 = 14;
        iDWq2 = 15; iDWk2 = 16; iDWv2 = 17; iDWo2 = 18;
        iDW1 = 19; iDb1 = 20; iDW2 = 21; iDb2 = 22;
        iWout = 23; iBout = 24;
    }

    const int*   src  = (const int*)d_in[0];
    const int*   tgt  = (const int*)d_in[1];
    const float* emb  = (const float*)d_in[2];
    const float* eWq  = (const float*)d_in[iEWq];
    const float* eWk  = (const float*)d_in[iEWk];
    const float* eWv  = (const float*)d_in[iEWv];
    const float* eWo  = (const float*)d_in[iEWo];
    const float* eW1  = (const float*)d_in[iEW1];
    const float* eb1  = (const float*)d_in[iEb1];
    const float* eW2  = (const float*)d_in[iEW2];
    const float* eb2  = (const float*)d_in[iEb2];
    const float* dWq1 = (const float*)d_in[iDWq1];
    const float* dWk1 = (const float*)d_in[iDWk1];
    const float* dWv1 = (const float*)d_in[iDWv1];
    const float* dWo1 = (const float*)d_in[iDWo1];
    const float* dWq2 = (const float*)d_in[iDWq2];
    const float* dWk2 = (const float*)d_in[iDWk2];
    const float* dWv2 = (const float*)d_in[iDWv2];
    const float* dWo2 = (const float*)d_in[iDWo2];
    const float* dW1  = (const float*)d_in[iDW1];
    const float* db1  = (const float*)d_in[iDb1];
    const float* dW2  = (const float*)d_in[iDW2];
    const float* db2  = (const float*)d_in[iDb2];
    const float* Wout = (const float*)d_in[iWout];
    const float* bout = (const float*)d_in[iBout];

    cudaFuncSetAttribute(bgemm<0>, cudaFuncAttributeMaxDynamicSharedMemorySize, SMEM_GEMM);
    cudaFuncSetAttribute(bgemm<1>, cudaFuncAttributeMaxDynamicSharedMemorySize, SMEM_GEMM);
    cudaFuncSetAttribute(bgemm<3>, cudaFuncAttributeMaxDynamicSharedMemorySize, SMEM_GEMM);
    cudaFuncSetAttribute(bgemm<4>, cudaFuncAttributeMaxDynamicSharedMemorySize, SMEM_GEMM);
    cudaFuncSetAttribute(bgemm<5>, cudaFuncAttributeMaxDynamicSharedMemorySize, SMEM_GEMM);
    cudaFuncSetAttribute(bgemm2,   cudaFuncAttributeMaxDynamicSharedMemorySize, SMEM_GEMM2);
    cudaFuncSetAttribute(qk_gemm,  cudaFuncAttributeMaxDynamicSharedMemorySize, QK_SMEM);
    cudaFuncSetAttribute(av_gemm,  cudaFuncAttributeMaxDynamicSharedMemorySize, AV_SMEM);

    float *x, *a, *out, *f, *y0, *o, *scores;
    cudaGetSymbolAddress((void**)&x,   g_x);
    cudaGetSymbolAddress((void**)&a,   g_a);
    cudaGetSymbolAddress((void**)&out, g_out);
    cudaGetSymbolAddress((void**)&f,   g_f);
    cudaGetSymbolAddress((void**)&y0,  g_y0);
    cudaGetSymbolAddress((void**)&o,   g_o);
    cudaGetSymbolAddress((void**)&scores, g_scores);

    bf16 *xh, *xl, *outh, *outl, *ath, *atl, *y0h, *y0l, *oh, *ol, *hh, *hl, *wh, *wl;
    bf16 *qkvh, *qkvl, *kv2h, *kv2l, *q2h, *q2l, *ph, *pl, *vth, *vtl;
    cudaGetSymbolAddress((void**)&xh,   g_xh);
    cudaGetSymbolAddress((void**)&xl,   g_xl);
    cudaGetSymbolAddress((void**)&outh, g_outh);
    cudaGetSymbolAddress((void**)&outl, g_outl);
    cudaGetSymbolAddress((void**)&ath,  g_ath);
    cudaGetSymbolAddress((void**)&atl,  g_atl);
    cudaGetSymbolAddress((void**)&y0h,  g_y0h);
    cudaGetSymbolAddress((void**)&y0l,  g_y0l);
    cudaGetSymbolAddress((void**)&oh,   g_oh);
    cudaGetSymbolAddress((void**)&ol,   g_ol);
    cudaGetSymbolAddress((void**)&hh,   g_hh);
    cudaGetSymbolAddress((void**)&hl,   g_hl);
    cudaGetSymbolAddress((void**)&wh,   g_wh);
    cudaGetSymbolAddress((void**)&wl,   g_wl);
    cudaGetSymbolAddress((void**)&qkvh, g_qkvh);
    cudaGetSymbolAddress((void**)&qkvl, g_qkvl);
    cudaGetSymbolAddress((void**)&kv2h, g_kv2h);
    cudaGetSymbolAddress((void**)&kv2l, g_kv2l);
    cudaGetSymbolAddress((void**)&q2h,  g_q2h);
    cudaGetSymbolAddress((void**)&q2l,  g_q2l);
    cudaGetSymbolAddress((void**)&ph,   g_ph);
    cudaGetSymbolAddress((void**)&pl,   g_pl);
    cudaGetSymbolAddress((void**)&vth,  g_vth);
    cudaGetSymbolAddress((void**)&vtl,  g_vtl);

    // ---- Weight conversion: ONE launch ----
    {
        const int li = L_ - 1;
        WcvTable tab;
        int ts = 0, ne = 0;
        auto add = [&](const float* s, unsigned long long dst,
                       unsigned long long ls, int K, int N, int nz) {
            WcvEntry& E = tab.e[ne++];
            E.src = s; E.dst = dst; E.lstride = ls;
            E.K = K; E.N = N; E.ntx = N / 32; E.nty = K / 32; E.nz = nz;
            E.tstart = ts;
            ts += (N / 32) * (K / 32) * nz;
        };
        add(eWq, O_EQKV,          3 * DD, D_, D_, 6);
        add(eWk, O_EQKV + DD,     3 * DD, D_, D_, 6);
        add(eWv, O_EQKV + 2 * DD, 3 * DD, D_, D_, 6);
        add(eWo, O_EWO, DD,  D_, D_, 6);
        add(eW1, O_EW1, DDF, D_, DFF_, 6);
        add(eW2, O_EW2, DDF, DFF_, D_, 6);
        add(dWq1 + (size_t)li * DDi, O_DQKV1,          0, D_, D_, 1);
        add(dWk1 + (size_t)li * DDi, O_DQKV1 + DD,     0, D_, D_, 1);
        add(dWv1 + (size_t)li * DDi, O_DQKV1 + 2 * DD, 0, D_, D_, 1);
        add(dWo1 + (size_t)li * DDi, O_DWO1, 0, D_, D_, 1);
        add(dWq2 + (size_t)li * DDi, O_DWQ2, 0, D_, D_, 1);
        add(dWk2 + (size_t)li * DDi, O_DKV2,      0, D_, D_, 1);
        add(dWv2 + (size_t)li * DDi, O_DKV2 + DD, 0, D_, D_, 1);
        add(dWo2 + (size_t)li * DDi, O_DWO2, 0, D_, D_, 1);
        add(dW1 + (size_t)li * (D_ * DFF_), O_DW1, 0, D_, DFF_, 1);
        add(dW2 + (size_t)li * (D_ * DFF_), O_DW2, 0, DFF_, D_, 1);
        add(Wout, O_WOUT, 0, D_, V_, 1);
        wconv_all<<<ts, dim3(32, 8)>>>(tab, ne, wh, wl);
    }

    const dim3 qkGrid(4, 32), smGrid(S_, 32), avGrid(1, 4, 32);
    const int li = L_ - 1;

    // ---------------- Encoder ----------------
    embed_kernel<<<BS_, 128>>>(src, emb, x, xh, xl);
    for (int i = 0; i < L_; i++) {
        run_bgemm(5, xh, xl, wh + O_EQKV + (size_t)i * 3 * DD, wl + O_EQKV + (size_t)i * 3 * DD,
                  nullptr, nullptr, qkvh, qkvl, vth, vtl, 1024, BS_, 3 * D_, D_);
        qk_gemm<<<qkGrid, 256, QK_SMEM>>>(qkvh, qkvl, 3 * D_,
                                          qkvh + D_, qkvl + D_, 3 * D_, scores);
        softmax_kernel<<<smGrid, 128>>>(scores, src, ph, pl, 0);
        av_gemm<<<avGrid, 256, AV_SMEM>>>(ph, pl, vth, vtl, ath, atl);
        run_bgemm(0, ath, atl, wh + O_EWO + (size_t)i * DD, wl + O_EWO + (size_t)i * DD,
                  nullptr, a, nullptr, nullptr, nullptr, nullptr, 0, BS_, D_, D_);
        add_ln_kernel<<<BS_, 128>>>(x, a, out, outh, outl);
        run_bgemm(3, outh, outl, wh + O_EW1 + (size_t)i * DDF, wl + O_EW1 + (size_t)i * DDF,
                  eb1 + (size_t)i * DFF_, nullptr, hh, hl, nullptr, nullptr, 0, BS_, DFF_, D_);
        run_bgemm(1, hh, hl, wh + O_EW2 + (size_t)i * DDF, wl + O_EW2 + (size_t)i * DDF,
                  eb2 + (size_t)i * D_, f, nullptr, nullptr, nullptr, nullptr, 0, BS_, D_, DFF_);
        add_ln_kernel<<<BS_, 128>>>(a, f, x, xh, xl);
    }

    // ---------------- Decoder (last layer only) ----------------
    embed_kernel<<<BS_, 128>>>(tgt, emb, y0, y0h, y0l);
    {
        run_bgemm(5, y0h, y0l, wh + O_DQKV1, wl + O_DQKV1, nullptr, nullptr,
                  qkvh, qkvl, vth, vtl, 1024, BS_, 3 * D_, D_);
        qk_gemm<<<qkGrid, 256, QK_SMEM>>>(qkvh, qkvl, 3 * D_,
                                          qkvh + D_, qkvl + D_, 3 * D_, scores);
        softmax_kernel<<<smGrid, 128>>>(scores, tgt, ph, pl, 1);
        av_gemm<<<avGrid, 256, AV_SMEM>>>(ph, pl, vth, vtl, ath, atl);
        run_bgemm(0, ath, atl, wh + O_DWO1, wl + O_DWO1, nullptr, a,
                  nullptr, nullptr, nullptr, nullptr, 0, BS_, D_, D_);
        add_ln_kernel<<<BS_, 128>>>(y0, a, o, oh, ol);

        run_bgemm(4, oh, ol, wh + O_DWQ2, wl + O_DWQ2, nullptr, nullptr,
                  q2h, q2l, nullptr, nullptr, 0, BS_, D_, D_);
        run_bgemm(5, xh, xl, wh + O_DKV2, wl + O_DKV2, nullptr, nullptr,
                  kv2h, kv2l, vth, vtl, 512, BS_, 2 * D_, D_);
        qk_gemm<<<qkGrid, 256, QK_SMEM>>>(q2h, q2l, D_, kv2h, kv2l, 2 * D_, scores);
        softmax_kernel<<<smGrid, 128>>>(scores, src, ph, pl, 0);
        av_gemm<<<avGrid, 256, AV_SMEM>>>(ph, pl, vth, vtl, ath, atl);
        run_bgemm(0, ath, atl, wh + O_DWO2, wl + O_DWO2, nullptr, a,
                  nullptr, nullptr, nullptr, nullptr, 0, BS_, D_, D_);
        add_ln_kernel<<<BS_, 128>>>(o, a, o, oh, ol);

        run_bgemm(3, oh, ol, wh + O_DW1, wl + O_DW1, db1 + (size_t)li * DFF_,
                  nullptr, hh, hl, nullptr, nullptr, 0, BS_, DFF_, D_);
        run_bgemm(1, hh, hl, wh + O_DW2, wl + O_DW2, db2 + (size_t)li * D_,
                  f, nullptr, nullptr, nullptr, nullptr, 0, BS_, D_, DFF_);
        add_ln_kernel<<<BS_, 128>>>(o, f, o, oh, ol);
    }

    // ---------------- Logits (MT=2, M-fast grid for B reuse in L2) --------
    bgemm2<<<dim3(BS_ / 256, V_ / 128), 256, SMEM_GEMM2>>>(
        oh, ol, wh + O_WOUT, wl + O_WOUT, bout, (float*)d_out, BS_, V_, D_);
}

// round 15
// speedup vs baseline: 1.1568x; 1.0415x over previous
#include <cuda_runtime.h>
#include <cuda_bf16.h>
#include <math.h>
#include <stdint.h>

#define D_    512
#define S_    512
#define B_    4
#define H_    8
#define L_    6
#define DFF_  2048
#define V_    32000
#define BS_   (B_ * S_)
#define NEGV  (-1e10f)

#if defined(__CUDA_ARCH_FEAT_SM103_ALL) || defined(__CUDA_ARCH_FEAT_SM100_ALL) || defined(__CUDA_ARCH_FEAT_SM101_ALL)
#define HAS_TC 1
#else
#define HAS_TC 0
#endif

typedef __nv_bfloat16  bf16;
typedef __nv_bfloat162 bf162;

// ---------------------------------------------------------------------------
// Scratch (device globals)
// ---------------------------------------------------------------------------
__device__ float g_x[BS_ * D_];
__device__ float g_a[BS_ * D_];
__device__ float g_out[BS_ * D_];
__device__ float g_f[BS_ * D_];
__device__ float g_y0[BS_ * D_];
__device__ float g_o[BS_ * D_];

__device__ bf16 g_xh[BS_ * D_],   g_xl[BS_ * D_];
__device__ bf16 g_outh[BS_ * D_], g_outl[BS_ * D_];
__device__ bf16 g_ath[BS_ * D_],  g_atl[BS_ * D_];
__device__ bf16 g_y0h[BS_ * D_],  g_y0l[BS_ * D_];
__device__ bf16 g_oh[BS_ * D_],   g_ol[BS_ * D_];
__device__ bf16 g_hh[BS_ * DFF_], g_hl[BS_ * DFF_];

// Attention scratch
__device__ bf16  g_qkvh[BS_ * 3 * D_], g_qkvl[BS_ * 3 * D_];
__device__ bf16  g_kv2h[BS_ * 2 * D_], g_kv2l[BS_ * 2 * D_];
__device__ bf16  g_q2h[BS_ * D_],      g_q2l[BS_ * D_];
__device__ float g_scores[32ull * S_ * S_];
__device__ bf16  g_ph[32ull * S_ * S_], g_pl[32ull * S_ * S_];
__device__ bf16  g_vth[32ull * 64 * S_], g_vtl[32ull * 64 * S_];

// Transposed+split weights arena (element offsets). Per-layer-contiguous QKV.
#define DD      (512ull * 512ull)
#define DDF     (512ull * 2048ull)
#define O_EQKV  0ull
#define O_EWO   4718592ull
#define O_EW1   6291456ull
#define O_EW2   12582912ull
#define O_DQKV1 18874368ull
#define O_DWO1  19660800ull
#define O_DWQ2  19922944ull
#define O_DKV2  20185088ull
#define O_DWO2  20709376ull
#define O_DW1   20971520ull
#define O_DW2   22020096ull
#define O_WOUT  23068672ull
#define NWTOT   39452672ull
__device__ bf16 g_wh[NWTOT];
__device__ bf16 g_wl[NWTOT];

// ---------------------------------------------------------------------------
// PTX helpers
// ---------------------------------------------------------------------------
__device__ __forceinline__ uint32_t s2u(const void* p) {
    uint32_t a;
    asm("{ .reg .u64 t; cvta.to.shared.u64 t, %1; cvt.u32.u64 %0, t; }"
        : "=r"(a) : "l"(p));
    return a;
}
__device__ __forceinline__ uint32_t swz(uint32_t o) { return o ^ ((o >> 3) & 0x70u); }

__device__ __forceinline__ void mbar_init(uint32_t a, uint32_t c) {
    asm volatile("mbarrier.init.shared.b64 [%0], %1;" :: "r"(a), "r"(c) : "memory");
}
__device__ __forceinline__ void mbar_wait(uint32_t a, uint32_t ph) {
    uint32_t done;
    asm volatile(
        "{\n\t.reg .pred p;\n\t"
        "mbarrier.try_wait.parity.acquire.cta.shared::cta.b64 p, [%1], %2;\n\t"
        "selp.b32 %0,1,0,p;\n\t}"
        : "=r"(done) : "r"(a), "r"(ph) : "memory");
    if (!done) {
        asm volatile(
            "{\n\t.reg .pred P1;\n\t"
            "WAIT_LOOP_%=:\n\t"
            "mbarrier.try_wait.parity.acquire.cta.shared::cta.b64 P1, [%0], %1, 0x989680;\n\t"
            "@P1 bra.uni WAIT_DONE_%=;\n\t"
            "bra.uni WAIT_LOOP_%=;\n\t"
            "WAIT_DONE_%=:\n\t}"
            :: "r"(a), "r"(ph) : "memory");
    }
}
#define FENCE_ASYNC() asm volatile("fence.proxy.async.shared::cta;" ::: "memory")

__device__ __forceinline__ void cpasync16(uint32_t saddr, const void* g) {
    asm volatile("cp.async.cg.shared.global [%0], [%1], 16;"
                 :: "r"(saddr), "l"(g));
}
#define CP_COMMIT() asm volatile("cp.async.commit_group;" ::: "memory")
#define CP_WAIT1()  asm volatile("cp.async.wait_group 1;" ::: "memory")
#define CP_WAIT0()  asm volatile("cp.async.wait_group 0;" ::: "memory")

#if HAS_TC
__device__ __forceinline__ uint64_t mkdesc(uint32_t addr) {
    const uint64_t base = (2ull << 61) | (1ull << 46) | (64ull << 32) | (1ull << 16);
    return base | ((uint64_t)(addr >> 4) & 0x3FFFull);
}
__device__ __forceinline__ void mma_f16_ss(uint32_t d, uint64_t ad, uint64_t bd,
                                           uint32_t idesc, uint32_t en) {
    asm volatile(
        "{\n\t.reg .pred p;\n\tsetp.ne.u32 p, %5, 0;\n\t"
        "tcgen05.mma.cta_group::1.kind::f16 [%0], %1, %2, %3, {%4,%4,%4,%4}, p;\n\t}"
        :: "r"(d), "l"(ad), "l"(bd), "r"(idesc), "r"(0u), "r"(en) : "memory");
}
#define TC_ALLOC(sa, n)  asm volatile("tcgen05.alloc.cta_group::1.sync.aligned.shared::cta.b32 [%0], %1;" :: "r"(sa), "r"(n) : "memory")
#define TC_DEALLOC(t, n) asm volatile("tcgen05.dealloc.cta_group::1.sync.aligned.b32 %0, %1;" :: "r"(t), "r"(n))
#define TC_COMMIT(mb)    asm volatile("tcgen05.commit.cta_group::1.mbarrier::arrive::one.shared::cluster.b64 [%0];" :: "r"(mb) : "memory")
#define TC_FENCE_AFTER() asm volatile("tcgen05.fence::after_thread_sync;" ::: "memory")
#define TC_WAIT_LD()     asm volatile("tcgen05.wait::ld.sync.aligned;" ::: "memory")

#define TCLD32(r, a) \
    asm volatile( \
        "tcgen05.ld.sync.aligned.32x32b.x32.b32 " \
        "{%0, %1, %2, %3, %4, %5, %6, %7, " \
        " %8, %9, %10, %11, %12, %13, %14, %15, " \
        " %16, %17, %18, %19, %20, %21, %22, %23, " \
        " %24, %25, %26, %27, %28, %29, %30, %31}, [%32];" \
        : "=r"((r)[0]),  "=r"((r)[1]),  "=r"((r)[2]),  "=r"((r)[3]), \
          "=r"((r)[4]),  "=r"((r)[5]),  "=r"((r)[6]),  "=r"((r)[7]), \
          "=r"((r)[8]),  "=r"((r)[9]),  "=r"((r)[10]), "=r"((r)[11]), \
          "=r"((r)[12]), "=r"((r)[13]), "=r"((r)[14]), "=r"((r)[15]), \
          "=r"((r)[16]), "=r"((r)[17]), "=r"((r)[18]), "=r"((r)[19]), \
          "=r"((r)[20]), "=r"((r)[21]), "=r"((r)[22]), "=r"((r)[23]), \
          "=r"((r)[24]), "=r"((r)[25]), "=r"((r)[26]), "=r"((r)[27]), \
          "=r"((r)[28]), "=r"((r)[29]), "=r"((r)[30]), "=r"((r)[31]) \
        : "r"(a))
#endif  // HAS_TC

#define IDESC_N(n) ((1u<<4)|(1u<<7)|(1u<<10)|(((n)/8u)<<17)|(8u<<24))

__device__ __forceinline__ void split_store4(bf16* __restrict__ Hh,
                                             bf16* __restrict__ Hl,
                                             size_t idx, float4 v) {
    bf16 hx = __float2bfloat16_rn(v.x), hy = __float2bfloat16_rn(v.y);
    bf16 hz = __float2bfloat16_rn(v.z), hw = __float2bfloat16_rn(v.w);
    bf16 lx = __float2bfloat16_rn(v.x - __bfloat162float(hx));
    bf16 ly = __float2bfloat16_rn(v.y - __bfloat162float(hy));
    bf16 lz = __float2bfloat16_rn(v.z - __bfloat162float(hz));
    bf16 lw = __float2bfloat16_rn(v.w - __bfloat162float(hw));
    bf162 p;
    p.x = hx; p.y = hy; *(bf162*)(Hh + idx)     = p;
    p.x = hz; p.y = hw; *(bf162*)(Hh + idx + 2) = p;
    p.x = lx; p.y = ly; *(bf162*)(Hl + idx)     = p;
    p.x = lz; p.y = lw; *(bf162*)(Hl + idx + 2) = p;
}

// ---------------------------------------------------------------------------
// Mega weight-conversion kernel
// ---------------------------------------------------------------------------
struct WcvEntry {
    const float* src;
    unsigned long long dst;
    unsigned long long lstride;
    int K, N, ntx, nty, nz, tstart;
};
struct WcvTable { WcvEntry e[17]; };

__global__ __launch_bounds__(256) void wconv_all(
    WcvTable tab, int nent, bf16* __restrict__ oh, bf16* __restrict__ ol)
{
    __shared__ float tile[32][33];
    int tid = blockIdx.x;
    int i = 0;
    while (i + 1 < nent && tid >= tab.e[i + 1].tstart) i++;
    const WcvEntry E = tab.e[i];
    int t = tid - E.tstart;
    int per_z = E.ntx * E.nty;
    int z  = t / per_z;
    int rm = t - z * per_z;
    int txb = rm % E.ntx, tyb = rm / E.ntx;
    const int n0 = txb * 32, k0 = tyb * 32;
    const int K = E.K, N = E.N;
    const float* Wb = E.src + (size_t)z * K * N;
    bf16* ohb = oh + E.dst + (size_t)z * E.lstride;
    bf16* olb = ol + E.dst + (size_t)z * E.lstride;

    const int tx = threadIdx.x, ty = threadIdx.y;
    #pragma unroll
    for (int ii = 0; ii < 4; ii++)
        tile[ty + 8 * ii][tx] = Wb[(size_t)(k0 + ty + 8 * ii) * N + n0 + tx];
    __syncthreads();
    #pragma unroll
    for (int ii = 0; ii < 4; ii++) {
        float v = tile[tx][ty + 8 * ii];
        int n = n0 + ty + 8 * ii, k = k0 + tx;
        size_t idx = (size_t)n * K + k;
        bf16 h = __float2bfloat16_rn(v);
        ohb[idx] = h;
        olb[idx] = __float2bfloat16_rn(v - __bfloat162float(h));
    }
}

// ---------------------------------------------------------------------------
// Embedding + positional encoding (+ bf16 split)
// ---------------------------------------------------------------------------
__global__ __launch_bounds__(128) void embed_kernel(
    const int* __restrict__ ids, const float* __restrict__ emb,
    float* __restrict__ out, bf16* __restrict__ oh, bf16* __restrict__ ol)
{
    const int row = blockIdx.x;
    const int s   = row & (S_ - 1);
    const int tok = ids[row];
    const int t   = threadIdx.x;
    const float c = -logf(10000.0f) / (float)D_;
    float4 v;
    float tmp[4];
    #pragma unroll
    for (int j = 0; j < 4; j++) {
        int d  = t * 4 + j;
        int tj = d >> 1;
        float div = expf((float)(2 * tj) * c);
        float ang = (float)s * div;
        float pe  = (d & 1) ? cosf(ang) : sinf(ang);
        tmp[j] = emb[(size_t)tok * D_ + d] + pe;
    }
    v.x = tmp[0]; v.y = tmp[1]; v.z = tmp[2]; v.w = tmp[3];
    size_t base = (size_t)row * D_ + t * 4;
    *(float4*)(out + base) = v;
    split_store4(oh, ol, base, v);
}

// ---------------------------------------------------------------------------
// Fused residual + LayerNorm (+ bf16 split)
// ---------------------------------------------------------------------------
__global__ __launch_bounds__(128) void add_ln_kernel(
    const float* __restrict__ A, const float* __restrict__ Bv,
    float* __restrict__ Out, bf16* __restrict__ Oh, bf16* __restrict__ Ol)
{
    const int row = blockIdx.x;
    const int t   = threadIdx.x;
    const size_t base = (size_t)row * D_ + t * 4;
    float4 a = *(const float4*)(A + base);
    float4 b = *(const float4*)(Bv + base);
    float4 vv;
    vv.x = a.x + b.x; vv.y = a.y + b.y; vv.z = a.z + b.z; vv.w = a.w + b.w;

    float s  = vv.x + vv.y + vv.z + vv.w;
    float sq = vv.x * vv.x + vv.y * vv.y + vv.z * vv.z + vv.w * vv.w;
    __shared__ float redS[4], redQ[4];
    #pragma unroll
    for (int off = 16; off > 0; off >>= 1) {
        s  += __shfl_xor_sync(0xffffffffu, s,  off);
        sq += __shfl_xor_sync(0xffffffffu, sq, off);
    }
    const int wid = t >> 5, lane = t & 31;
    if (lane == 0) { redS[wid] = s; redQ[wid] = sq; }
    __syncthreads();
    s  = redS[0] + redS[1] + redS[2] + redS[3];
    sq = redQ[0] + redQ[1] + redQ[2] + redQ[3];
    float mean = s * (1.0f / D_);
    float var  = sq * (1.0f / D_) - mean * mean;
    float inv  = rsqrtf(var + 1e-5f);
    float4 o;
    o.x = (vv.x - mean) * inv; o.y = (vv.y - mean) * inv;
    o.z = (vv.z - mean) * inv; o.w = (vv.w - mean) * inv;
    *(float4*)(Out + base) = o;
    split_store4(Oh, Ol, base, o);
}

// ---------------------------------------------------------------------------
// tcgen05 split-fp32 GEMM, MT=1, 3-stage cp.async pipeline.
// EPI: 0 ->C ; 1 +bias->C ; 3 +bias+relu->hi/lo ; 4 split->hi/lo ;
//      5 split->hi/lo for cols<vsplit, V-transposed hi/lo otherwise
// ---------------------------------------------------------------------------
#define GIDESC    IDESC_N(128)
#define STAGE_B   65536
#define NSTG      3
#define SMEM_GEMM (NSTG * STAGE_B + 1024)

template<int EPI>
__global__ __launch_bounds__(256)
void bgemm(const bf16* __restrict__ Ah, const bf16* __restrict__ Al,
           const bf16* __restrict__ Bh, const bf16* __restrict__ Bl,
           const float* __restrict__ bias, float* __restrict__ C,
           bf16* __restrict__ Ch, bf16* __restrict__ Cl,
           bf16* __restrict__ Vh, bf16* __restrict__ Vl, int vsplit,
           int M, int N, int K)
{
#if HAS_TC
    __shared__ __align__(16) uint32_t s_tptr[4];
    __shared__ __align__(16) uint64_t s_mbar[NSTG];
    extern __shared__ char smem[];
    const uint32_t tiles = (s2u(smem) + 1023u) & ~1023u;
    const uint32_t tptr  = s2u(s_tptr);
    uint32_t mb[NSTG];
    #pragma unroll
    for (int i = 0; i < NSTG; i++) mb[i] = s2u(&s_mbar[i]);

    const int t   = threadIdx.x;
    const int wid = t >> 5;
    const int bm  = blockIdx.y * 128, bn = blockIdx.x * 128;

    if (wid == 0) TC_ALLOC(tptr, 128);
    if (t == 0) {
        #pragma unroll
        for (int i = 0; i < NSTG; i++) mbar_init(mb[i], 1);
    }
    __syncthreads();
    const uint32_t tmem = s_tptr[0];

    const int r  = t >> 3;
    const int ck = t & 7;
    const int nch = K >> 6;
    int use[NSTG];
    #pragma unroll
    for (int i = 0; i < NSTG; i++) use[i] = 0;

    auto load_chunk = [&](int c, int s) {
        const uint32_t base = tiles + s * STAGE_B;
        const uint32_t aH = base, aL = base + 16384;
        const uint32_t bH = base + 32768, bL = base + 49152;
        const int k0 = c << 6;
        #pragma unroll
        for (int it = 0; it < 4; it++) {
            int row = r + it * 32;
            size_t g = (size_t)(bm + row) * K + k0 + ck * 8;
            uint32_t so = swz((uint32_t)(row * 128 + ck * 16));
            cpasync16(aH + so, Ah + g);
            cpasync16(aL + so, Al + g);
        }
        #pragma unroll
        for (int it = 0; it < 4; it++) {
            int row = r + it * 32;
            size_t g = (size_t)(bn + row) * K + k0 + ck * 8;
            uint32_t so = swz((uint32_t)(row * 128 + ck * 16));
            cpasync16(bH + so, Bh + g);
            cpasync16(bL + so, Bl + g);
        }
        CP_COMMIT();
    };

    load_chunk(0, 0);
    for (int c = 0; c < nch; c++) {
        const int s = c % NSTG;
        if (c + 1 < nch) {
            const int s2 = (c + 1) % NSTG;
            if (use[s2] > 0) mbar_wait(mb[s2], (use[s2] - 1) & 1);
            load_chunk(c + 1, s2);
            CP_WAIT1();
        } else {
            CP_WAIT0();
        }
        FENCE_ASYNC();
        __syncthreads();
        if (t == 0) {
            const uint32_t base = tiles + s * STAGE_B;
            uint64_t dah = mkdesc(base),         dal = mkdesc(base + 16384);
            uint64_t dbh = mkdesc(base + 32768), dbl = mkdesc(base + 49152);
            #pragma unroll
            for (int j = 0; j < 4; j++)
                mma_f16_ss(tmem, dah + 2 * j, dbh + 2 * j, GIDESC,
                           (c == 0 && j == 0) ? 0u : 1u);
            #pragma unroll
            for (int j = 0; j < 4; j++)
                mma_f16_ss(tmem, dah + 2 * j, dbl + 2 * j, GIDESC, 1u);
            #pragma unroll
            for (int j = 0; j < 4; j++)
                mma_f16_ss(tmem, dal + 2 * j, dbh + 2 * j, GIDESC, 1u);
            TC_COMMIT(mb[s]);
        }
        use[s]++;
    }
    #pragma unroll
    for (int i = 0; i < NSTG; i++)
        if (use[i] > 0) mbar_wait(mb[i], (use[i] - 1) & 1);
    TC_FENCE_AFTER();

    {
        const int sub = wid & 3, half = wid >> 2, lane = t & 31;
        const int rowg = bm + sub * 32 + lane;
        #pragma unroll
        for (int cc = 0; cc < 2; cc++) {
            const int col0 = half * 64 + cc * 32;
            uint32_t regs[32];
            TCLD32(regs, tmem + col0);
            TC_WAIT_LD();
            const int colbase = bn + col0;
            if (EPI == 0) {
                #pragma unroll
                for (int j = 0; j < 32; j += 4) {
                    float4 v;
                    v.x = __uint_as_float(regs[j]);
                    v.y = __uint_as_float(regs[j + 1]);
                    v.z = __uint_as_float(regs[j + 2]);
                    v.w = __uint_as_float(regs[j + 3]);
                    *(float4*)(C + (size_t)rowg * N + colbase + j) = v;
                }
            } else if (EPI == 1) {
                #pragma unroll
                for (int j = 0; j < 32; j += 4) {
                    float4 bv = *(const float4*)(bias + colbase + j);
                    float4 v;
                    v.x = __uint_as_float(regs[j])     + bv.x;
                    v.y = __uint_as_float(regs[j + 1]) + bv.y;
                    v.z = __uint_as_float(regs[j + 2]) + bv.z;
                    v.w = __uint_as_float(regs[j + 3]) + bv.w;
                    *(float4*)(C + (size_t)rowg * N + colbase + j) = v;
                }
            } else if (EPI == 3) {
                #pragma unroll
                for (int j = 0; j < 32; j += 4) {
                    float4 bv = *(const float4*)(bias + colbase + j);
                    float4 v;
                    v.x = fmaxf(__uint_as_float(regs[j])     + bv.x, 0.f);
                    v.y = fmaxf(__uint_as_float(regs[j + 1]) + bv.y, 0.f);
                    v.z = fmaxf(__uint_as_float(regs[j + 2]) + bv.z, 0.f);
                    v.w = fmaxf(__uint_as_float(regs[j + 3]) + bv.w, 0.f);
                    split_store4(Ch, Cl, (size_t)rowg * N + colbase + j, v);
                }
            } else if (EPI == 4) {
                #pragma unroll
                for (int j = 0; j < 32; j += 4) {
                    float4 v;
                    v.x = __uint_as_float(regs[j]);
                    v.y = __uint_as_float(regs[j + 1]);
                    v.z = __uint_as_float(regs[j + 2]);
                    v.w = __uint_as_float(regs[j + 3]);
                    split_store4(Ch, Cl, (size_t)rowg * N + colbase + j, v);
                }
            } else {  // EPI == 5
                if (colbase < vsplit) {
                    #pragma unroll
                    for (int j = 0; j < 32; j += 4) {
                        float4 v;
                        v.x = __uint_as_float(regs[j]);
                        v.y = __uint_as_float(regs[j + 1]);
                        v.z = __uint_as_float(regs[j + 2]);
                        v.w = __uint_as_float(regs[j + 3]);
                        split_store4(Ch, Cl, (size_t)rowg * N + colbase + j, v);
                    }
                } else {
                    const int vcol = colbase - vsplit;
                    const int z  = (rowg >> 9) * 8 + (vcol >> 6);
                    const int d0 = vcol & 63;
                    const int tok = rowg & 511;
                    const size_t vb = ((size_t)z * 64 + d0) * 512 + tok;
                    #pragma unroll
                    for (int j = 0; j < 32; j++) {
                        float fv = __uint_as_float(regs[j]);
                        bf16 h = __float2bfloat16_rn(fv);
                        bf16 l = __float2bfloat16_rn(fv - __bfloat162float(h));
                        Vh[vb + (size_t)j * 512] = h;
                        Vl[vb + (size_t)j * 512] = l;
                    }
                }
            }
        }
    }
    __syncthreads();
    if (wid == 0) TC_DEALLOC(tmem, 128);
#else
    const int t  = threadIdx.x;
    const int bm = blockIdx.y * 128, bn = blockIdx.x * 128;
    const int r0 = (t >> 4) * 8;
    const int c0 = (t & 15) * 8;
    for (int i = 0; i < 8; i++) {
        int rowg = bm + r0 + i;
        for (int j = 0; j < 8; j++) {
            int col = bn + c0 + j;
            float acc = 0.f;
            for (int k = 0; k < K; k++) {
                float av = __bfloat162float(Ah[(size_t)rowg * K + k])
                         + __bfloat162float(Al[(size_t)rowg * K + k]);
                float bv = __bfloat162float(Bh[(size_t)col * K + k])
                         + __bfloat162float(Bl[(size_t)col * K + k]);
                acc += av * bv;
            }
            if (EPI == 1 || EPI == 3) acc += bias[col];
            if (EPI == 3) acc = fmaxf(acc, 0.f);
            if (EPI == 0 || EPI == 1) {
                C[(size_t)rowg * N + col] = acc;
            } else if (EPI == 3 || EPI == 4 || (EPI == 5 && col < vsplit)) {
                bf16 h = __float2bfloat16_rn(acc);
                Ch[(size_t)rowg * N + col] = h;
                Cl[(size_t)rowg * N + col] =
                    __float2bfloat16_rn(acc - __bfloat162float(h));
            } else {
                int vcol = col - vsplit;
                int z = (rowg >> 9) * 8 + (vcol >> 6);
                int d = vcol & 63, tok = rowg & 511;
                bf16 h = __float2bfloat16_rn(acc);
                Vh[((size_t)z * 64 + d) * 512 + tok] = h;
                Vl[((size_t)z * 64 + d) * 512 + tok] =
                    __float2bfloat16_rn(acc - __bfloat162float(h));
            }
        }
    }
#endif
}

// ---------------------------------------------------------------------------
// bgemm2: MT=2 for the logits GEMM (round-11 grid: x = N fast, streaming)
// ---------------------------------------------------------------------------
#define STAGE2_B   98304
#define NSTG2      2
#define SMEM_GEMM2 (NSTG2 * STAGE2_B + 1024)

__global__ __launch_bounds__(256)
void bgemm2(const bf16* __restrict__ Ah, const bf16* __restrict__ Al,
            const bf16* __restrict__ Bh, const bf16* __restrict__ Bl,
            const float* __restrict__ bias, float* __restrict__ C,
            int M, int N, int K)
{
#if HAS_TC
    __shared__ __align__(16) uint32_t s_tptr[4];
    __shared__ __align__(16) uint64_t s_mbar[NSTG2];
    extern __shared__ char smem[];
    const uint32_t tiles = (s2u(smem) + 1023u) & ~1023u;
    const uint32_t tptr  = s2u(s_tptr);
    uint32_t mb[NSTG2];
    #pragma unroll
    for (int i = 0; i < NSTG2; i++) mb[i] = s2u(&s_mbar[i]);

    const int t   = threadIdx.x;
    const int wid = t >> 5;
    const int bm  = blockIdx.y * 256, bn = blockIdx.x * 128;

    if (wid == 0) TC_ALLOC(tptr, 256);
    if (t == 0) {
        #pragma unroll
        for (int i = 0; i < NSTG2; i++) mbar_init(mb[i], 1);
    }
    __syncthreads();
    const uint32_t tmem = s_tptr[0];

    const int r  = t >> 3;
    const int ck = t & 7;
    const int nch = K >> 6;
    int use[NSTG2];
    #pragma unroll
    for (int i = 0; i < NSTG2; i++) use[i] = 0;

    auto load_chunk = [&](int c, int s) {
        const uint32_t base = tiles + s * STAGE2_B;
        const int k0 = c << 6;
        #pragma unroll
        for (int m = 0; m < 2; m++) {
            const uint32_t aH = base + m * 32768, aL = aH + 16384;
            #pragma unroll
            for (int it = 0; it < 4; it++) {
                int row = r + it * 32;
                size_t g = (size_t)(bm + m * 128 + row) * K + k0 + ck * 8;
                uint32_t so = swz((uint32_t)(row * 128 + ck * 16));
                cpasync16(aH + so, Ah + g);
                cpasync16(aL + so, Al + g);
            }
        }
        const uint32_t bH = base + 65536, bL = base + 81920;
        #pragma unroll
        for (int it = 0; it < 4; it++) {
            int row = r + it * 32;
            size_t g = (size_t)(bn + row) * K + k0 + ck * 8;
            uint32_t so = swz((uint32_t)(row * 128 + ck * 16));
            cpasync16(bH + so, Bh + g);
            cpasync16(bL + so, Bl + g);
        }
        CP_COMMIT();
    };

    load_chunk(0, 0);
    for (int c = 0; c < nch; c++) {
        const int s = c % NSTG2;
        if (c + 1 < nch) {
            const int s2 = (c + 1) % NSTG2;
            if (use[s2] > 0) mbar_wait(mb[s2], (use[s2] - 1) & 1);
            load_chunk(c + 1, s2);
            CP_WAIT1();
        } else {
            CP_WAIT0();
        }
        FENCE_ASYNC();
        __syncthreads();
        if (t == 0) {
            const uint32_t base = tiles + s * STAGE2_B;
            uint64_t dbh = mkdesc(base + 65536), dbl = mkdesc(base + 81920);
            #pragma unroll
            for (int m = 0; m < 2; m++) {
                uint64_t dah = mkdesc(base + m * 32768);
                uint64_t dal = mkdesc(base + m * 32768 + 16384);
                const uint32_t acc = tmem + m * 128;
                #pragma unroll
                for (int j = 0; j < 4; j++)
                    mma_f16_ss(acc, dah + 2 * j, dbh + 2 * j, GIDESC,
                               (c == 0 && j == 0) ? 0u : 1u);
                #pragma unroll
                for (int j = 0; j < 4; j++)
                    mma_f16_ss(acc, dah + 2 * j, dbl + 2 * j, GIDESC, 1u);
                #pragma unroll
                for (int j = 0; j < 4; j++)
                    mma_f16_ss(acc, dal + 2 * j, dbh + 2 * j, GIDESC, 1u);
            }
            TC_COMMIT(mb[s]);
        }
        use[s]++;
    }
    #pragma unroll
    for (int i = 0; i < NSTG2; i++)
        if (use[i] > 0) mbar_wait(mb[i], (use[i] - 1) & 1);
    TC_FENCE_AFTER();

    {
        const int m = wid >> 2, sub = wid & 3, lane = t & 31;
        const int rowg = bm + m * 128 + sub * 32 + lane;
        #pragma unroll
        for (int cc = 0; cc < 4; cc++) {
            const int col0 = cc * 32;
            uint32_t regs[32];
            TCLD32(regs, tmem + m * 128 + col0);
            TC_WAIT_LD();
            const int colbase = bn + col0;
            #pragma unroll
            for (int j = 0; j < 32; j += 4) {
                float4 bv = *(const float4*)(bias + colbase + j);
                float4 v;
                v.x = __uint_as_float(regs[j])     + bv.x;
                v.y = __uint_as_float(regs[j + 1]) + bv.y;
                v.z = __uint_as_float(regs[j + 2]) + bv.z;
                v.w = __uint_as_float(regs[j + 3]) + bv.w;
                *(float4*)(C + (size_t)rowg * N + colbase + j) = v;
            }
        }
    }
    __syncthreads();
    if (wid == 0) TC_DEALLOC(tmem, 256);
#else
    const int t  = threadIdx.x;
    const int bm = blockIdx.y * 256, bn = blockIdx.x * 128;
    const int r0 = (t >> 4) * 16;
    const int c0 = (t & 15) * 8;
    for (int i = 0; i < 16; i++) {
        int rowg = bm + r0 + i;
        for (int j = 0; j < 8; j++) {
            int col = bn + c0 + j;
            float acc = 0.f;
            for (int k = 0; k < K; k++) {
                float av = __bfloat162float(Ah[(size_t)rowg * K + k])
                         + __bfloat162float(Al[(size_t)rowg * K + k]);
                float bv = __bfloat162float(Bh[(size_t)col * K + k])
                         + __bfloat162float(Bl[(size_t)col * K + k]);
                acc += av * bv;
            }
            C[(size_t)rowg * N + col] = acc + bias[col];
        }
    }
#endif
}

// ---------------------------------------------------------------------------
// QK^T GEMM (round-11 proven): one CTA per (q-tile, z), 4 k-tiles, 48 MMAs
// into 512-col TMEM, single commit/wait. Grid (4, 32).
// ---------------------------------------------------------------------------
#define QK_SMEM (32768 + 4 * 32768 + 1024)
__global__ __launch_bounds__(256) void qk_gemm(
    const bf16* __restrict__ Qh, const bf16* __restrict__ Ql, int qp,
    const bf16* __restrict__ Kh, const bf16* __restrict__ Kl, int kp,
    float* __restrict__ scores)
{
    const int z = blockIdx.y, b = z >> 3, h = z & 7;
    const int bm = blockIdx.x * 128;
    const size_t qoff = (size_t)(b * S_) * qp + h * 64;
    const size_t koff = (size_t)(b * S_) * kp + h * 64;
#if HAS_TC
    __shared__ __align__(16) uint32_t s_tptr[4];
    __shared__ __align__(16) uint64_t s_mbar[1];
    extern __shared__ char smem[];
    const uint32_t tiles = (s2u(smem) + 1023u) & ~1023u;
    const uint32_t tptr  = s2u(s_tptr);
    const uint32_t mb    = s2u(&s_mbar[0]);

    const int t   = threadIdx.x;
    const int wid = t >> 5;
    if (wid == 0) TC_ALLOC(tptr, 512);
    if (t == 0) mbar_init(mb, 1);
    __syncthreads();
    const uint32_t tmem = s_tptr[0];

    const int r  = t >> 3;
    const int ck = t & 7;
    const uint32_t aH = tiles, aL = tiles + 16384;
    #pragma unroll
    for (int it = 0; it < 4; it++) {
        int row = r + it * 32;
        uint32_t so = swz((uint32_t)(row * 128 + ck * 16));
        cpasync16(aH + so, Qh + qoff + (size_t)(bm + row) * qp + ck * 8);
        cpasync16(aL + so, Ql + qoff + (size_t)(bm + row) * qp + ck * 8);
    }
    #pragma unroll
    for (int kb = 0; kb < 4; kb++) {
        const uint32_t bH = tiles + 32768 + kb * 32768, bL = bH + 16384;
        #pragma unroll
        for (int it = 0; it < 4; it++) {
            int row = r + it * 32;
            uint32_t so = swz((uint32_t)(row * 128 + ck * 16));
            cpasync16(bH + so, Kh + koff + (size_t)(kb * 128 + row) * kp + ck * 8);
            cpasync16(bL + so, Kl + koff + (size_t)(kb * 128 + row) * kp + ck * 8);
        }
    }
    CP_COMMIT(); CP_WAIT0();
    FENCE_ASYNC();
    __syncthreads();
    if (t == 0) {
        uint64_t dah = mkdesc(aH), dal = mkdesc(aL);
        #pragma unroll
        for (int kb = 0; kb < 4; kb++) {
            const uint32_t bH = tiles + 32768 + kb * 32768;
            uint64_t dbh = mkdesc(bH), dbl = mkdesc(bH + 16384);
            const uint32_t acc = tmem + kb * 128;
            #pragma unroll
            for (int j = 0; j < 4; j++)
                mma_f16_ss(acc, dah + 2 * j, dbh + 2 * j, GIDESC, j ? 1u : 0u);
            #pragma unroll
            for (int j = 0; j < 4; j++)
                mma_f16_ss(acc, dah + 2 * j, dbl + 2 * j, GIDESC, 1u);
            #pragma unroll
            for (int j = 0; j < 4; j++)
                mma_f16_ss(acc, dal + 2 * j, dbh + 2 * j, GIDESC, 1u);
        }
        TC_COMMIT(mb);
    }
    mbar_wait(mb, 0);
    TC_FENCE_AFTER();
    {
        const int sub = wid & 3, half = wid >> 2, lane = t & 31;
        const int rowg = bm + sub * 32 + lane;
        float* out = scores + ((size_t)z * S_ + rowg) * S_;
        #pragma unroll
        for (int kb = 0; kb < 4; kb++) {
            #pragma unroll
            for (int cc = 0; cc < 2; cc++) {
                const int col0 = half * 64 + cc * 32;
                uint32_t regs[32];
                TCLD32(regs, tmem + kb * 128 + col0);
                TC_WAIT_LD();
                #pragma unroll
                for (int j = 0; j < 32; j += 4) {
                    float4 v;
                    v.x = __uint_as_float(regs[j])     * 0.125f;
                    v.y = __uint_as_float(regs[j + 1]) * 0.125f;
                    v.z = __uint_as_float(regs[j + 2]) * 0.125f;
                    v.w = __uint_as_float(regs[j + 3]) * 0.125f;
                    *(float4*)(out + kb * 128 + col0 + j) = v;
                }
            }
        }
    }
    __syncthreads();
    if (wid == 0) TC_DEALLOC(tmem, 512);
#else
    const int t = threadIdx.x;
    for (int idx = t; idx < 128 * 512; idx += 256) {
        int rr = idx >> 9, cc = idx & 511;
        float acc = 0.f;
        for (int k = 0; k < 64; k++) {
            float qv = __bfloat162float(Qh[qoff + (size_t)(bm + rr) * qp + k])
                     + __bfloat162float(Ql[qoff + (size_t)(bm + rr) * qp + k]);
            float kv = __bfloat162float(Kh[koff + (size_t)cc * kp + k])
                     + __bfloat162float(Kl[koff + (size_t)cc * kp + k]);
            acc += qv * kv;
        }
        scores[((size_t)z * S_ + bm + rr) * S_ + cc] = acc * 0.125f;
    }
#endif
}

// ---------------------------------------------------------------------------
// Masked softmax -> P hi/lo, WARP-PER-ROW: 8 rows/block, grid (64, 32).
// Token mask preloaded to smem once per block; shuffle-only reductions.
// ---------------------------------------------------------------------------
__global__ __launch_bounds__(256) void softmax_kernel(
    const float* __restrict__ scores, const int* __restrict__ kv_tok,
    bf16* __restrict__ Ph, bf16* __restrict__ Pl, int causal)
{
    __shared__ float s_mask[512];
    const int z = blockIdx.y, b = z >> 3;
    const int t = threadIdx.x;
    const int wid = t >> 5, lane = t & 31;
    const int q = blockIdx.x * 8 + wid;

    s_mask[t]       = (kv_tok[b * S_ + t]       == 0) ? NEGV : 0.f;
    s_mask[t + 256] = (kv_tok[b * S_ + t + 256] == 0) ? NEGV : 0.f;
    __syncthreads();

    const size_t base = ((size_t)z * S_ + q) * S_;
    float vals[16];
    float m = -3.0e38f;
    #pragma unroll
    for (int c = 0; c < 4; c++) {
        int k0 = lane * 4 + c * 128;
        float4 s = *(const float4*)(scores + base + k0);
        float* v4 = vals + c * 4;
        v4[0] = s.x + s_mask[k0];
        v4[1] = s.y + s_mask[k0 + 1];
        v4[2] = s.z + s_mask[k0 + 2];
        v4[3] = s.w + s_mask[k0 + 3];
        if (causal) {
            #pragma unroll
            for (int j = 0; j < 4; j++)
                if (k0 + j > q) v4[j] += NEGV;
        }
        #pragma unroll
        for (int j = 0; j < 4; j++) m = fmaxf(m, v4[j]);
    }
    #pragma unroll
    for (int off = 16; off > 0; off >>= 1)
        m = fmaxf(m, __shfl_xor_sync(0xffffffffu, m, off));

    float e[16], ssum = 0.f;
    #pragma unroll
    for (int j = 0; j < 16; j++) { e[j] = __expf(vals[j] - m); ssum += e[j]; }
    #pragma unroll
    for (int off = 16; off > 0; off >>= 1)
        ssum += __shfl_xor_sync(0xffffffffu, ssum, off);
    const float inv = 1.f / ssum;

    #pragma unroll
    for (int c = 0; c < 4; c++) {
        int k0 = lane * 4 + c * 128;
        float4 p = make_float4(e[c * 4] * inv, e[c * 4 + 1] * inv,
                               e[c * 4 + 2] * inv, e[c * 4 + 3] * inv);
        split_store4(Ph, Pl, base + k0, p);
    }
}

// ---------------------------------------------------------------------------
// AV GEMM: out = P @ V via V^T, grid (1,4,32), 3-stage pipeline (round-11)
// ---------------------------------------------------------------------------
#define AV_STAGE  49152
#define AV_NSTG   3
#define AV_SMEM   (AV_NSTG * AV_STAGE + 1024)
#define AVIDESC   IDESC_N(64)
__global__ __launch_bounds__(256) void av_gemm(
    const bf16* __restrict__ Ph, const bf16* __restrict__ Pl,
    const bf16* __restrict__ Vth, const bf16* __restrict__ Vtl,
    bf16* __restrict__ Oh, bf16* __restrict__ Ol)
{
    const int z = blockIdx.z, b = z >> 3, h = z & 7;
    const int bm = blockIdx.y * 128;
    const bf16* Pzh = Ph  + (size_t)z * S_ * S_;
    const bf16* Pzl = Pl  + (size_t)z * S_ * S_;
    const bf16* Vzh = Vth + (size_t)z * 64 * S_;
    const bf16* Vzl = Vtl + (size_t)z * 64 * S_;
#if HAS_TC
    __shared__ __align__(16) uint32_t s_tptr[4];
    __shared__ __align__(16) uint64_t s_mbar[AV_NSTG];
    extern __shared__ char smem[];
    const uint32_t tiles = (s2u(smem) + 1023u) & ~1023u;
    const uint32_t tptr  = s2u(s_tptr);
    uint32_t mb[AV_NSTG];
    #pragma unroll
    for (int i = 0; i < AV_NSTG; i++) mb[i] = s2u(&s_mbar[i]);

    const int t   = threadIdx.x;
    const int wid = t >> 5;
    if (wid == 0) TC_ALLOC(tptr, 128);
    if (t == 0) {
        #pragma unroll
        for (int i = 0; i < AV_NSTG; i++) mbar_init(mb[i], 1);
    }
    __syncthreads();
    const uint32_t tmem = s_tptr[0];

    const int r  = t >> 3;
    const int ck = t & 7;
    int use[AV_NSTG];
    #pragma unroll
    for (int i = 0; i < AV_NSTG; i++) use[i] = 0;

    auto load_chunk = [&](int c, int s) {
        const uint32_t base = tiles + s * AV_STAGE;
        const uint32_t aH = base, aL = base + 16384;
        const uint32_t bH = base + 32768, bL = base + 40960;
        const int k0 = c << 6;
        #pragma unroll
        for (int it = 0; it < 4; it++) {
            int row = r + it * 32;
            size_t g = (size_t)(bm + row) * S_ + k0 + ck * 8;
            uint32_t so = swz((uint32_t)(row * 128 + ck * 16));
            cpasync16(aH + so, Pzh + g);
            cpasync16(aL + so, Pzl + g);
        }
        #pragma unroll
        for (int it = 0; it < 2; it++) {
            int row = r + it * 32;
            size_t g = (size_t)row * S_ + k0 + ck * 8;
            uint32_t so = swz((uint32_t)(row * 128 + ck * 16));
            cpasync16(bH + so, Vzh + g);
            cpasync16(bL + so, Vzl + g);
        }
        CP_COMMIT();
    };

    const int nch = S_ >> 6;
    load_chunk(0, 0);
    for (int c = 0; c < nch; c++) {
        const int s = c % AV_NSTG;
        if (c + 1 < nch) {
            const int s2 = (c + 1) % AV_NSTG;
            if (use[s2] > 0) mbar_wait(mb[s2], (use[s2] - 1) & 1);
            load_chunk(c + 1, s2);
            CP_WAIT1();
        } else {
            CP_WAIT0();
        }
        FENCE_ASYNC();
        __syncthreads();
        if (t == 0) {
            const uint32_t base = tiles + s * AV_STAGE;
            uint64_t dah = mkdesc(base),         dal = mkdesc(base + 16384);
            uint64_t dbh = mkdesc(base + 32768), dbl = mkdesc(base + 40960);
            #pragma unroll
            for (int j = 0; j < 4; j++)
                mma_f16_ss(tmem, dah + 2 * j, dbh + 2 * j, AVIDESC,
                           (c == 0 && j == 0) ? 0u : 1u);
            #pragma unroll
            for (int j = 0; j < 4; j++)
                mma_f16_ss(tmem, dah + 2 * j, dbl + 2 * j, AVIDESC, 1u);
            #pragma unroll
            for (int j = 0; j < 4; j++)
                mma_f16_ss(tmem, dal + 2 * j, dbh + 2 * j, AVIDESC, 1u);
            TC_COMMIT(mb[s]);
        }
        use[s]++;
    }
    #pragma unroll
    for (int i = 0; i < AV_NSTG; i++)
        if (use[i] > 0) mbar_wait(mb[i], (use[i] - 1) & 1);
    TC_FENCE_AFTER();
    {
        const int sub = wid & 3, half = wid >> 2, lane = t & 31;
        const int rowg = bm + sub * 32 + lane;
        const int col0 = half * 32;
        uint32_t regs[32];
        TCLD32(regs, tmem + col0);
        TC_WAIT_LD();
        #pragma unroll
        for (int j = 0; j < 32; j += 4) {
            float4 v;
            v.x = __uint_as_float(regs[j]);
            v.y = __uint_as_float(regs[j + 1]);
            v.z = __uint_as_float(regs[j + 2]);
            v.w = __uint_as_float(regs[j + 3]);
            size_t idx = ((size_t)(b * S_) + rowg) * D_ + h * 64 + col0 + j;
            split_store4(Oh, Ol, idx, v);
        }
    }
    __syncthreads();
    if (wid == 0) TC_DEALLOC(tmem, 128);
#else
    const int t = threadIdx.x;
    for (int idx = t; idx < 128 * 64; idx += 256) {
        int rr = idx >> 6, cc = idx & 63;
        float acc = 0.f;
        for (int k = 0; k < S_; k++) {
            float pv = __bfloat162float(Pzh[(size_t)(bm + rr) * S_ + k])
                     + __bfloat162float(Pzl[(size_t)(bm + rr) * S_ + k]);
            float vv = __bfloat162float(Vzh[(size_t)cc * S_ + k])
                     + __bfloat162float(Vzl[(size_t)cc * S_ + k]);
            acc += pv * vv;
        }
        size_t oidx = ((size_t)(b * S_) + bm + rr) * D_ + h * 64 + cc;
        bf16 hh2 = __float2bfloat16_rn(acc);
        Oh[oidx] = hh2;
        Ol[oidx] = __float2bfloat16_rn(acc - __bfloat162float(hh2));
    }
#endif
}

// ---------------------------------------------------------------------------
// Host driver
// ---------------------------------------------------------------------------
static inline void run_bgemm(int epi, const bf16* Ah, const bf16* Al,
                             const bf16* Bh, const bf16* Bl, const float* bias,
                             float* C, bf16* Ch, bf16* Cl,
                             bf16* Vh, bf16* Vl, int vsplit,
                             int M, int N, int K)
{
    dim3 grid(N / 128, M / 128);
    if (epi == 0)
        bgemm<0><<<grid, 256, SMEM_GEMM>>>(Ah, Al, Bh, Bl, bias, C, Ch, Cl, Vh, Vl, vsplit, M, N, K);
    else if (epi == 1)
        bgemm<1><<<grid, 256, SMEM_GEMM>>>(Ah, Al, Bh, Bl, bias, C, Ch, Cl, Vh, Vl, vsplit, M, N, K);
    else if (epi == 3)
        bgemm<3><<<grid, 256, SMEM_GEMM>>>(Ah, Al, Bh, Bl, bias, C, Ch, Cl, Vh, Vl, vsplit, M, N, K);
    else if (epi == 4)
        bgemm<4><<<grid, 256, SMEM_GEMM>>>(Ah, Al, Bh, Bl, bias, C, Ch, Cl, Vh, Vl, vsplit, M, N, K);
    else
        bgemm<5><<<grid, 256, SMEM_GEMM>>>(Ah, Al, Bh, Bl, bias, C, Ch, Cl, Vh, Vl, vsplit, M, N, K);
}

extern "C" void kernel_launch(void* const* d_in, const int* in_sizes, int n_in,
                              void* d_out, int out_size)
{
    const int DDi = D_ * D_;

    int iEWq, iEWk, iEWv, iEWo, iEW1, iEb1, iEW2, iEb2;
    int iDWq1, iDWk1, iDWv1, iDWo1, iDWq2, iDWk2, iDWv2, iDWo2;
    int iDW1, iDb1, iDW2, iDb2, iWout, iBout;
    if (n_in >= 8 && in_sizes[7] == L_ * DDi) {
        iEWq = 3; iEWk = 4; iEWv = 5; iEWo = 6;
        iDWq1 = 7; iDWk1 = 8; iDWv1 = 9; iDWo1 = 10;
        iDWq2 = 11; iDWk2 = 12; iDWv2 = 13; iDWo2 = 14;
        iEW1 = 15; iEb1 = 16; iEW2 = 17; iEb2 = 18;
        iDW1 = 19; iDb1 = 20; iDW2 = 21; iDb2 = 22;
        iWout = 23; iBout = 24;
    } else {
        iEWq = 3; iEWk = 4; iEWv = 5; iEWo = 6;
        iEW1 = 7; iEb1 = 8; iEW2 = 9; iEb2 = 10;
        iDWq1 = 11; iDWk1 = 12; iDWv1 = 13; iDWo1 = 14;
        iDWq2 = 15; iDWk2 = 16; iDWv2 = 17; iDWo2 = 18;
        iDW1 = 19; iDb1 = 20; iDW2 = 21; iDb2 = 22;
        iWout = 23; iBout = 24;
    }

    const int*   src  = (const int*)d_in[0];
    const int*   tgt  = (const int*)d_in[1];
    const float* emb  = (const float*)d_in[2];
    const float* eWq  = (const float*)d_in[iEWq];
    const float* eWk  = (const float*)d_in[iEWk];
    const float* eWv  = (const float*)d_in[iEWv];
    const float* eWo  = (const float*)d_in[iEWo];
    const float* eW1  = (const float*)d_in[iEW1];
    const float* eb1  = (const float*)d_in[iEb1];
    const float* eW2  = (const float*)d_in[iEW2];
    const float* eb2  = (const float*)d_in[iEb2];
    const float* dWq1 = (const float*)d_in[iDWq1];
    const float* dWk1 = (const float*)d_in[iDWk1];
    const float* dWv1 = (const float*)d_in[iDWv1];
    const float* dWo1 = (const float*)d_in[iDWo1];
    const float* dWq2 = (const float*)d_in[iDWq2];
    const float* dWk2 = (const float*)d_in[iDWk2];
    const float* dWv2 = (const float*)d_in[iDWv2];
    const float* dWo2 = (const float*)d_in[iDWo2];
    const float* dW1  = (const float*)d_in[iDW1];
    const float* db1  = (const float*)d_in[iDb1];
    const float* dW2  = (const float*)d_in[iDW2];
    const float* db2  = (const float*)d_in[iDb2];
    const float* Wout = (const float*)d_in[iWout];
    const float* bout = (const float*)d_in[iBout];

    cudaFuncSetAttribute(bgemm<0>, cudaFuncAttributeMaxDynamicSharedMemorySize, SMEM_GEMM);
    cudaFuncSetAttribute(bgemm<1>, cudaFuncAttributeMaxDynamicSharedMemorySize, SMEM_GEMM);
    cudaFuncSetAttribute(bgemm<3>, cudaFuncAttributeMaxDynamicSharedMemorySize, SMEM_GEMM);
    cudaFuncSetAttribute(bgemm<4>, cudaFuncAttributeMaxDynamicSharedMemorySize, SMEM_GEMM);
    cudaFuncSetAttribute(bgemm<5>, cudaFuncAttributeMaxDynamicSharedMemorySize, SMEM_GEMM);
    cudaFuncSetAttribute(bgemm2,   cudaFuncAttributeMaxDynamicSharedMemorySize, SMEM_GEMM2);
    cudaFuncSetAttribute(qk_gemm,  cudaFuncAttributeMaxDynamicSharedMemorySize, QK_SMEM);
    cudaFuncSetAttribute(av_gemm,  cudaFuncAttributeMaxDynamicSharedMemorySize, AV_SMEM);

    float *x, *a, *out, *f, *y0, *o, *scores;
    cudaGetSymbolAddress((void**)&x,   g_x);
    cudaGetSymbolAddress((void**)&a,   g_a);
    cudaGetSymbolAddress((void**)&out, g_out);
    cudaGetSymbolAddress((void**)&f,   g_f);
    cudaGetSymbolAddress((void**)&y0,  g_y0);
    cudaGetSymbolAddress((void**)&o,   g_o);
    cudaGetSymbolAddress((void**)&scores, g_scores);

    bf16 *xh, *xl, *outh, *outl, *ath, *atl, *y0h, *y0l, *oh, *ol, *hh, *hl, *wh, *wl;
    bf16 *qkvh, *qkvl, *kv2h, *kv2l, *q2h, *q2l, *ph, *pl, *vth, *vtl;
    cudaGetSymbolAddress((void**)&xh,   g_xh);
    cudaGetSymbolAddress((void**)&xl,   g_xl);
    cudaGetSymbolAddress((void**)&outh, g_outh);
    cudaGetSymbolAddress((void**)&outl, g_outl);
    cudaGetSymbolAddress((void**)&ath,  g_ath);
    cudaGetSymbolAddress((void**)&atl,  g_atl);
    cudaGetSymbolAddress((void**)&y0h,  g_y0h);
    cudaGetSymbolAddress((void**)&y0l,  g_y0l);
    cudaGetSymbolAddress((void**)&oh,   g_oh);
    cudaGetSymbolAddress((void**)&ol,   g_ol);
    cudaGetSymbolAddress((void**)&hh,   g_hh);
    cudaGetSymbolAddress((void**)&hl,   g_hl);
    cudaGetSymbolAddress((void**)&wh,   g_wh);
    cudaGetSymbolAddress((void**)&wl,   g_wl);
    cudaGetSymbolAddress((void**)&qkvh, g_qkvh);
    cudaGetSymbolAddress((void**)&qkvl, g_qkvl);
    cudaGetSymbolAddress((void**)&kv2h, g_kv2h);
    cudaGetSymbolAddress((void**)&kv2l, g_kv2l);
    cudaGetSymbolAddress((void**)&q2h,  g_q2h);
    cudaGetSymbolAddress((void**)&q2l,  g_q2l);
    cudaGetSymbolAddress((void**)&ph,   g_ph);
    cudaGetSymbolAddress((void**)&pl,   g_pl);
    cudaGetSymbolAddress((void**)&vth,  g_vth);
    cudaGetSymbolAddress((void**)&vtl,  g_vtl);

    // ---- Weight conversion: ONE launch ----
    {
        const int li = L_ - 1;
        WcvTable tab;
        int ts = 0, ne = 0;
        auto add = [&](const float* s, unsigned long long dst,
                       unsigned long long ls, int K, int N, int nz) {
            WcvEntry& E = tab.e[ne++];
            E.src = s; E.dst = dst; E.lstride = ls;
            E.K = K; E.N = N; E.ntx = N / 32; E.nty = K / 32; E.nz = nz;
            E.tstart = ts;
            ts += (N / 32) * (K / 32) * nz;
        };
        add(eWq, O_EQKV,          3 * DD, D_, D_, 6);
        add(eWk, O_EQKV + DD,     3 * DD, D_, D_, 6);
        add(eWv, O_EQKV + 2 * DD, 3 * DD, D_, D_, 6);
        add(eWo, O_EWO, DD,  D_, D_, 6);
        add(eW1, O_EW1, DDF, D_, DFF_, 6);
        add(eW2, O_EW2, DDF, DFF_, D_, 6);
        add(dWq1 + (size_t)li * DDi, O_DQKV1,          0, D_, D_, 1);
        add(dWk1 + (size_t)li * DDi, O_DQKV1 + DD,     0, D_, D_, 1);
        add(dWv1 + (size_t)li * DDi, O_DQKV1 + 2 * DD, 0, D_, D_, 1);
        add(dWo1 + (size_t)li * DDi, O_DWO1, 0, D_, D_, 1);
        add(dWq2 + (size_t)li * DDi, O_DWQ2, 0, D_, D_, 1);
        add(dWk2 + (size_t)li * DDi, O_DKV2,      0, D_, D_, 1);
        add(dWv2 + (size_t)li * DDi, O_DKV2 + DD, 0, D_, D_, 1);
        add(dWo2 + (size_t)li * DDi, O_DWO2, 0, D_, D_, 1);
        add(dW1 + (size_t)li * (D_ * DFF_), O_DW1, 0, D_, DFF_, 1);
        add(dW2 + (size_t)li * (D_ * DFF_), O_DW2, 0, DFF_, D_, 1);
        add(Wout, O_WOUT, 0, D_, V_, 1);
        wconv_all<<<ts, dim3(32, 8)>>>(tab, ne, wh, wl);
    }

    const dim3 qkGrid(4, 32), smGrid(S_ / 8, 32), avGrid(1, 4, 32);
    const int li = L_ - 1;

    // ---------------- Encoder ----------------
    embed_kernel<<<BS_, 128>>>(src, emb, x, xh, xl);
    for (int i = 0; i < L_; i++) {
        run_bgemm(5, xh, xl, wh + O_EQKV + (size_t)i * 3 * DD, wl + O_EQKV + (size_t)i * 3 * DD,
                  nullptr, nullptr, qkvh, qkvl, vth, vtl, 1024, BS_, 3 * D_, D_);
        qk_gemm<<<qkGrid, 256, QK_SMEM>>>(qkvh, qkvl, 3 * D_,
                                          qkvh + D_, qkvl + D_, 3 * D_, scores);
        softmax_kernel<<<smGrid, 256>>>(scores, src, ph, pl, 0);
        av_gemm<<<avGrid, 256, AV_SMEM>>>(ph, pl, vth, vtl, ath, atl);
        run_bgemm(0, ath, atl, wh + O_EWO + (size_t)i * DD, wl + O_EWO + (size_t)i * DD,
                  nullptr, a, nullptr, nullptr, nullptr, nullptr, 0, BS_, D_, D_);
        add_ln_kernel<<<BS_, 128>>>(x, a, out, outh, outl);
        run_bgemm(3, outh, outl, wh + O_EW1 + (size_t)i * DDF, wl + O_EW1 + (size_t)i * DDF,
                  eb1 + (size_t)i * DFF_, nullptr, hh, hl, nullptr, nullptr, 0, BS_, DFF_, D_);
        run_bgemm(1, hh, hl, wh + O_EW2 + (size_t)i * DDF, wl + O_EW2 + (size_t)i * DDF,
                  eb2 + (size_t)i * D_, f, nullptr, nullptr, nullptr, nullptr, 0, BS_, D_, DFF_);
        add_ln_kernel<<<BS_, 128>>>(a, f, x, xh, xl);
    }

    // ---------------- Decoder (last layer only) ----------------
    embed_kernel<<<BS_, 128>>>(tgt, emb, y0, y0h, y0l);
    {
        run_bgemm(5, y0h, y0l, wh + O_DQKV1, wl + O_DQKV1, nullptr, nullptr,
                  qkvh, qkvl, vth, vtl, 1024, BS_, 3 * D_, D_);
        qk_gemm<<<qkGrid, 256, QK_SMEM>>>(qkvh, qkvl, 3 * D_,
                                          qkvh + D_, qkvl + D_, 3 * D_, scores);
        softmax_kernel<<<smGrid, 256>>>(scores, tgt, ph, pl, 1);
        av_gemm<<<avGrid, 256, AV_SMEM>>>(ph, pl, vth, vtl, ath, atl);
        run_bgemm(0, ath, atl, wh + O_DWO1, wl + O_DWO1, nullptr, a,
                  nullptr, nullptr, nullptr, nullptr, 0, BS_, D_, D_);
        add_ln_kernel<<<BS_, 128>>>(y0, a, o, oh, ol);

        run_bgemm(4, oh, ol, wh + O_DWQ2, wl + O_DWQ2, nullptr, nullptr,
                  q2h, q2l, nullptr, nullptr, 0, BS_, D_, D_);
        run_bgemm(5, xh, xl, wh + O_DKV2, wl + O_DKV2, nullptr, nullptr,
                  kv2h, kv2l, vth, vtl, 512, BS_, 2 * D_, D_);
        qk_gemm<<<qkGrid, 256, QK_SMEM>>>(q2h, q2l, D_, kv2h, kv2l, 2 * D_, scores);
        softmax_kernel<<<smGrid, 256>>>(scores, src, ph, pl, 0);
        av_gemm<<<avGrid, 256, AV_SMEM>>>(ph, pl, vth, vtl, ath, atl);
        run_bgemm(0, ath, atl, wh + O_DWO2, wl + O_DWO2, nullptr, a,
                  nullptr, nullptr, nullptr, nullptr, 0, BS_, D_, D_);
        add_ln_kernel<<<BS_, 128>>>(o, a, o, oh, ol);

        run_bgemm(3, oh, ol, wh + O_DW1, wl + O_DW1, db1 + (size_t)li * DFF_,
                  nullptr, hh, hl, nullptr, nullptr, 0, BS_, DFF_, D_);
        run_bgemm(1, hh, hl, wh + O_DW2, wl + O_DW2, db2 + (size_t)li * D_,
                  f, nullptr, nullptr, nullptr, nullptr, 0, BS_, D_, DFF_);
        add_ln_kernel<<<BS_, 128>>>(o, f, o, oh, ol);
    }

    // ---------------- Logits (MT=2, round-11 grid: x = N streaming) -------
    bgemm2<<<dim3(V_ / 128, BS_ / 256), 256, SMEM_GEMM2>>>(
        oh, ol, wh + O_WOUT, wl + O_WOUT, bout, (float*)d_out, BS_, V_, D_);
}

// round 16
// speedup vs baseline: 1.1596x; 1.0024x over previous
#include <cuda_runtime.h>
#include <cuda_bf16.h>
#include <math.h>
#include <stdint.h>

#define D_    512
#define S_    512
#define B_    4
#define H_    8
#define L_    6
#define DFF_  2048
#define V_    32000
#define BS_   (B_ * S_)
#define NEGV  (-1e10f)

#if defined(__CUDA_ARCH_FEAT_SM103_ALL) || defined(__CUDA_ARCH_FEAT_SM100_ALL) || defined(__CUDA_ARCH_FEAT_SM101_ALL)
#define HAS_TC 1
#else
#define HAS_TC 0
#endif

typedef __nv_bfloat16  bf16;
typedef __nv_bfloat162 bf162;

// ---------------------------------------------------------------------------
// Scratch (device globals)
// ---------------------------------------------------------------------------
__device__ float g_x[BS_ * D_];
__device__ float g_a[BS_ * D_];
__device__ float g_f[BS_ * D_];
__device__ float g_y0[BS_ * D_];
__device__ float g_o[BS_ * D_];

__device__ bf16 g_xh[BS_ * D_],   g_xl[BS_ * D_];
__device__ bf16 g_outh[BS_ * D_], g_outl[BS_ * D_];
__device__ bf16 g_ath[BS_ * D_],  g_atl[BS_ * D_];
__device__ bf16 g_y0h[BS_ * D_],  g_y0l[BS_ * D_];
__device__ bf16 g_oh[BS_ * D_],   g_ol[BS_ * D_];
__device__ bf16 g_hh[BS_ * DFF_], g_hl[BS_ * DFF_];

// Attention scratch
__device__ bf16  g_qkvh[BS_ * 3 * D_], g_qkvl[BS_ * 3 * D_];
__device__ bf16  g_kv2h[BS_ * 2 * D_], g_kv2l[BS_ * 2 * D_];
__device__ bf16  g_q2h[BS_ * D_],      g_q2l[BS_ * D_];
__device__ float g_scores[32ull * S_ * S_];
__device__ bf16  g_ph[32ull * S_ * S_], g_pl[32ull * S_ * S_];
__device__ bf16  g_vth[32ull * 64 * S_], g_vtl[32ull * 64 * S_];

// Transposed+split weights arena (element offsets). Per-layer-contiguous QKV.
#define DD      (512ull * 512ull)
#define DDF     (512ull * 2048ull)
#define O_EQKV  0ull
#define O_EWO   4718592ull
#define O_EW1   6291456ull
#define O_EW2   12582912ull
#define O_DQKV1 18874368ull
#define O_DWO1  19660800ull
#define O_DWQ2  19922944ull
#define O_DKV2  20185088ull
#define O_DWO2  20709376ull
#define O_DW1   20971520ull
#define O_DW2   22020096ull
#define O_WOUT  23068672ull
#define NWTOT   39452672ull
__device__ bf16 g_wh[NWTOT];
__device__ bf16 g_wl[NWTOT];

// ---------------------------------------------------------------------------
// PTX helpers
// ---------------------------------------------------------------------------
__device__ __forceinline__ uint32_t s2u(const void* p) {
    uint32_t a;
    asm("{ .reg .u64 t; cvta.to.shared.u64 t, %1; cvt.u32.u64 %0, t; }"
        : "=r"(a) : "l"(p));
    return a;
}
__device__ __forceinline__ uint32_t swz(uint32_t o) { return o ^ ((o >> 3) & 0x70u); }

__device__ __forceinline__ void mbar_init(uint32_t a, uint32_t c) {
    asm volatile("mbarrier.init.shared.b64 [%0], %1;" :: "r"(a), "r"(c) : "memory");
}
__device__ __forceinline__ void mbar_wait(uint32_t a, uint32_t ph) {
    uint32_t done;
    asm volatile(
        "{\n\t.reg .pred p;\n\t"
        "mbarrier.try_wait.parity.acquire.cta.shared::cta.b64 p, [%1], %2;\n\t"
        "selp.b32 %0,1,0,p;\n\t}"
        : "=r"(done) : "r"(a), "r"(ph) : "memory");
    if (!done) {
        asm volatile(
            "{\n\t.reg .pred P1;\n\t"
            "WAIT_LOOP_%=:\n\t"
            "mbarrier.try_wait.parity.acquire.cta.shared::cta.b64 P1, [%0], %1, 0x989680;\n\t"
            "@P1 bra.uni WAIT_DONE_%=;\n\t"
            "bra.uni WAIT_LOOP_%=;\n\t"
            "WAIT_DONE_%=:\n\t}"
            :: "r"(a), "r"(ph) : "memory");
    }
}
#define FENCE_ASYNC() asm volatile("fence.proxy.async.shared::cta;" ::: "memory")

__device__ __forceinline__ void cpasync16(uint32_t saddr, const void* g) {
    asm volatile("cp.async.cg.shared.global [%0], [%1], 16;"
                 :: "r"(saddr), "l"(g));
}
#define CP_COMMIT() asm volatile("cp.async.commit_group;" ::: "memory")
#define CP_WAIT1()  asm volatile("cp.async.wait_group 1;" ::: "memory")
#define CP_WAIT0()  asm volatile("cp.async.wait_group 0;" ::: "memory")

#if HAS_TC
__device__ __forceinline__ uint64_t mkdesc(uint32_t addr) {
    const uint64_t base = (2ull << 61) | (1ull << 46) | (64ull << 32) | (1ull << 16);
    return base | ((uint64_t)(addr >> 4) & 0x3FFFull);
}
__device__ __forceinline__ void mma_f16_ss(uint32_t d, uint64_t ad, uint64_t bd,
                                           uint32_t idesc, uint32_t en) {
    asm volatile(
        "{\n\t.reg .pred p;\n\tsetp.ne.u32 p, %5, 0;\n\t"
        "tcgen05.mma.cta_group::1.kind::f16 [%0], %1, %2, %3, {%4,%4,%4,%4}, p;\n\t}"
        :: "r"(d), "l"(ad), "l"(bd), "r"(idesc), "r"(0u), "r"(en) : "memory");
}
#define TC_ALLOC(sa, n)  asm volatile("tcgen05.alloc.cta_group::1.sync.aligned.shared::cta.b32 [%0], %1;" :: "r"(sa), "r"(n) : "memory")
#define TC_DEALLOC(t, n) asm volatile("tcgen05.dealloc.cta_group::1.sync.aligned.b32 %0, %1;" :: "r"(t), "r"(n))
#define TC_COMMIT(mb)    asm volatile("tcgen05.commit.cta_group::1.mbarrier::arrive::one.shared::cluster.b64 [%0];" :: "r"(mb) : "memory")
#define TC_FENCE_AFTER() asm volatile("tcgen05.fence::after_thread_sync;" ::: "memory")
#define TC_WAIT_LD()     asm volatile("tcgen05.wait::ld.sync.aligned;" ::: "memory")

#define TCLD32(r, a) \
    asm volatile( \
        "tcgen05.ld.sync.aligned.32x32b.x32.b32 " \
        "{%0, %1, %2, %3, %4, %5, %6, %7, " \
        " %8, %9, %10, %11, %12, %13, %14, %15, " \
        " %16, %17, %18, %19, %20, %21, %22, %23, " \
        " %24, %25, %26, %27, %28, %29, %30, %31}, [%32];" \
        : "=r"((r)[0]),  "=r"((r)[1]),  "=r"((r)[2]),  "=r"((r)[3]), \
          "=r"((r)[4]),  "=r"((r)[5]),  "=r"((r)[6]),  "=r"((r)[7]), \
          "=r"((r)[8]),  "=r"((r)[9]),  "=r"((r)[10]), "=r"((r)[11]), \
          "=r"((r)[12]), "=r"((r)[13]), "=r"((r)[14]), "=r"((r)[15]), \
          "=r"((r)[16]), "=r"((r)[17]), "=r"((r)[18]), "=r"((r)[19]), \
          "=r"((r)[20]), "=r"((r)[21]), "=r"((r)[22]), "=r"((r)[23]), \
          "=r"((r)[24]), "=r"((r)[25]), "=r"((r)[26]), "=r"((r)[27]), \
          "=r"((r)[28]), "=r"((r)[29]), "=r"((r)[30]), "=r"((r)[31]) \
        : "r"(a))
#endif  // HAS_TC

#define IDESC_N(n) ((1u<<4)|(1u<<7)|(1u<<10)|(((n)/8u)<<17)|(8u<<24))

__device__ __forceinline__ void split_store4(bf16* __restrict__ Hh,
                                             bf16* __restrict__ Hl,
                                             size_t idx, float4 v) {
    bf16 hx = __float2bfloat16_rn(v.x), hy = __float2bfloat16_rn(v.y);
    bf16 hz = __float2bfloat16_rn(v.z), hw = __float2bfloat16_rn(v.w);
    bf16 lx = __float2bfloat16_rn(v.x - __bfloat162float(hx));
    bf16 ly = __float2bfloat16_rn(v.y - __bfloat162float(hy));
    bf16 lz = __float2bfloat16_rn(v.z - __bfloat162float(hz));
    bf16 lw = __float2bfloat16_rn(v.w - __bfloat162float(hw));
    bf162 p;
    p.x = hx; p.y = hy; *(bf162*)(Hh + idx)     = p;
    p.x = hz; p.y = hw; *(bf162*)(Hh + idx + 2) = p;
    p.x = lx; p.y = ly; *(bf162*)(Hl + idx)     = p;
    p.x = lz; p.y = lw; *(bf162*)(Hl + idx + 2) = p;
}

// ---------------------------------------------------------------------------
// Mega weight-conversion kernel
// ---------------------------------------------------------------------------
struct WcvEntry {
    const float* src;
    unsigned long long dst;
    unsigned long long lstride;
    int K, N, ntx, nty, nz, tstart;
};
struct WcvTable { WcvEntry e[17]; };

__global__ __launch_bounds__(256) void wconv_all(
    WcvTable tab, int nent, bf16* __restrict__ oh, bf16* __restrict__ ol)
{
    __shared__ float tile[32][33];
    int tid = blockIdx.x;
    int i = 0;
    while (i + 1 < nent && tid >= tab.e[i + 1].tstart) i++;
    const WcvEntry E = tab.e[i];
    int t = tid - E.tstart;
    int per_z = E.ntx * E.nty;
    int z  = t / per_z;
    int rm = t - z * per_z;
    int txb = rm % E.ntx, tyb = rm / E.ntx;
    const int n0 = txb * 32, k0 = tyb * 32;
    const int K = E.K, N = E.N;
    const float* Wb = E.src + (size_t)z * K * N;
    bf16* ohb = oh + E.dst + (size_t)z * E.lstride;
    bf16* olb = ol + E.dst + (size_t)z * E.lstride;

    const int tx = threadIdx.x, ty = threadIdx.y;
    #pragma unroll
    for (int ii = 0; ii < 4; ii++)
        tile[ty + 8 * ii][tx] = Wb[(size_t)(k0 + ty + 8 * ii) * N + n0 + tx];
    __syncthreads();
    #pragma unroll
    for (int ii = 0; ii < 4; ii++) {
        float v = tile[tx][ty + 8 * ii];
        int n = n0 + ty + 8 * ii, k = k0 + tx;
        size_t idx = (size_t)n * K + k;
        bf16 h = __float2bfloat16_rn(v);
        ohb[idx] = h;
        olb[idx] = __float2bfloat16_rn(v - __bfloat162float(h));
    }
}

// ---------------------------------------------------------------------------
// Embedding + positional encoding (+ bf16 split)
// ---------------------------------------------------------------------------
__global__ __launch_bounds__(128) void embed_kernel(
    const int* __restrict__ ids, const float* __restrict__ emb,
    float* __restrict__ out, bf16* __restrict__ oh, bf16* __restrict__ ol)
{
    const int row = blockIdx.x;
    const int s   = row & (S_ - 1);
    const int tok = ids[row];
    const int t   = threadIdx.x;
    const float c = -logf(10000.0f) / (float)D_;
    float4 v;
    float tmp[4];
    #pragma unroll
    for (int j = 0; j < 4; j++) {
        int d  = t * 4 + j;
        int tj = d >> 1;
        float div = expf((float)(2 * tj) * c);
        float ang = (float)s * div;
        float pe  = (d & 1) ? cosf(ang) : sinf(ang);
        tmp[j] = emb[(size_t)tok * D_ + d] + pe;
    }
    v.x = tmp[0]; v.y = tmp[1]; v.z = tmp[2]; v.w = tmp[3];
    size_t base = (size_t)row * D_ + t * 4;
    *(float4*)(out + base) = v;
    split_store4(oh, ol, base, v);
}

// ---------------------------------------------------------------------------
// Fused residual + LayerNorm (+ bf16 split). Out==nullptr skips fp32 store.
// ---------------------------------------------------------------------------
__global__ __launch_bounds__(128) void add_ln_kernel(
    const float* __restrict__ A, const float* __restrict__ Bv,
    float* __restrict__ Out, bf16* __restrict__ Oh, bf16* __restrict__ Ol)
{
    const int row = blockIdx.x;
    const int t   = threadIdx.x;
    const size_t base = (size_t)row * D_ + t * 4;
    float4 a = *(const float4*)(A + base);
    float4 b = *(const float4*)(Bv + base);
    float4 vv;
    vv.x = a.x + b.x; vv.y = a.y + b.y; vv.z = a.z + b.z; vv.w = a.w + b.w;

    float s  = vv.x + vv.y + vv.z + vv.w;
    float sq = vv.x * vv.x + vv.y * vv.y + vv.z * vv.z + vv.w * vv.w;
    __shared__ float redS[4], redQ[4];
    #pragma unroll
    for (int off = 16; off > 0; off >>= 1) {
        s  += __shfl_xor_sync(0xffffffffu, s,  off);
        sq += __shfl_xor_sync(0xffffffffu, sq, off);
    }
    const int wid = t >> 5, lane = t & 31;
    if (lane == 0) { redS[wid] = s; redQ[wid] = sq; }
    __syncthreads();
    s  = redS[0] + redS[1] + redS[2] + redS[3];
    sq = redQ[0] + redQ[1] + redQ[2] + redQ[3];
    float mean = s * (1.0f / D_);
    float var  = sq * (1.0f / D_) - mean * mean;
    float inv  = rsqrtf(var + 1e-5f);
    float4 o;
    o.x = (vv.x - mean) * inv; o.y = (vv.y - mean) * inv;
    o.z = (vv.z - mean) * inv; o.w = (vv.w - mean) * inv;
    if (Out) *(float4*)(Out + base) = o;
    split_store4(Oh, Ol, base, o);
}

// ---------------------------------------------------------------------------
// tcgen05 split-fp32 GEMM, MT=1, 3-stage cp.async pipeline.
// EPI: 0 ->C ; 1 +bias->C ; 3 +bias+relu->hi/lo ; 4 split->hi/lo ;
//      5 split->hi/lo for cols<vsplit, V-transposed hi/lo otherwise
// Epilogue uses pipelined TMEM readback (prefetch next TCLD before stores).
// ---------------------------------------------------------------------------
#define GIDESC    IDESC_N(128)
#define STAGE_B   65536
#define NSTG      3
#define SMEM_GEMM (NSTG * STAGE_B + 1024)

template<int EPI>
__global__ __launch_bounds__(256)
void bgemm(const bf16* __restrict__ Ah, const bf16* __restrict__ Al,
           const bf16* __restrict__ Bh, const bf16* __restrict__ Bl,
           const float* __restrict__ bias, float* __restrict__ C,
           bf16* __restrict__ Ch, bf16* __restrict__ Cl,
           bf16* __restrict__ Vh, bf16* __restrict__ Vl, int vsplit,
           int M, int N, int K)
{
#if HAS_TC
    __shared__ __align__(16) uint32_t s_tptr[4];
    __shared__ __align__(16) uint64_t s_mbar[NSTG];
    extern __shared__ char smem[];
    const uint32_t tiles = (s2u(smem) + 1023u) & ~1023u;
    const uint32_t tptr  = s2u(s_tptr);
    uint32_t mb[NSTG];
    #pragma unroll
    for (int i = 0; i < NSTG; i++) mb[i] = s2u(&s_mbar[i]);

    const int t   = threadIdx.x;
    const int wid = t >> 5;
    const int bm  = blockIdx.y * 128, bn = blockIdx.x * 128;

    if (wid == 0) TC_ALLOC(tptr, 128);
    if (t == 0) {
        #pragma unroll
        for (int i = 0; i < NSTG; i++) mbar_init(mb[i], 1);
    }
    __syncthreads();
    const uint32_t tmem = s_tptr[0];

    const int r  = t >> 3;
    const int ck = t & 7;
    const int nch = K >> 6;
    int use[NSTG];
    #pragma unroll
    for (int i = 0; i < NSTG; i++) use[i] = 0;

    auto load_chunk = [&](int c, int s) {
        const uint32_t base = tiles + s * STAGE_B;
        const uint32_t aH = base, aL = base + 16384;
        const uint32_t bH = base + 32768, bL = base + 49152;
        const int k0 = c << 6;
        #pragma unroll
        for (int it = 0; it < 4; it++) {
            int row = r + it * 32;
            size_t g = (size_t)(bm + row) * K + k0 + ck * 8;
            uint32_t so = swz((uint32_t)(row * 128 + ck * 16));
            cpasync16(aH + so, Ah + g);
            cpasync16(aL + so, Al + g);
        }
        #pragma unroll
        for (int it = 0; it < 4; it++) {
            int row = r + it * 32;
            size_t g = (size_t)(bn + row) * K + k0 + ck * 8;
            uint32_t so = swz((uint32_t)(row * 128 + ck * 16));
            cpasync16(bH + so, Bh + g);
            cpasync16(bL + so, Bl + g);
        }
        CP_COMMIT();
    };

    load_chunk(0, 0);
    for (int c = 0; c < nch; c++) {
        const int s = c % NSTG;
        if (c + 1 < nch) {
            const int s2 = (c + 1) % NSTG;
            if (use[s2] > 0) mbar_wait(mb[s2], (use[s2] - 1) & 1);
            load_chunk(c + 1, s2);
            CP_WAIT1();
        } else {
            CP_WAIT0();
        }
        FENCE_ASYNC();
        __syncthreads();
        if (t == 0) {
            const uint32_t base = tiles + s * STAGE_B;
            uint64_t dah = mkdesc(base),         dal = mkdesc(base + 16384);
            uint64_t dbh = mkdesc(base + 32768), dbl = mkdesc(base + 49152);
            #pragma unroll
            for (int j = 0; j < 4; j++)
                mma_f16_ss(tmem, dah + 2 * j, dbh + 2 * j, GIDESC,
                           (c == 0 && j == 0) ? 0u : 1u);
            #pragma unroll
            for (int j = 0; j < 4; j++)
                mma_f16_ss(tmem, dah + 2 * j, dbl + 2 * j, GIDESC, 1u);
            #pragma unroll
            for (int j = 0; j < 4; j++)
                mma_f16_ss(tmem, dal + 2 * j, dbh + 2 * j, GIDESC, 1u);
            TC_COMMIT(mb[s]);
        }
        use[s]++;
    }
    #pragma unroll
    for (int i = 0; i < NSTG; i++)
        if (use[i] > 0) mbar_wait(mb[i], (use[i] - 1) & 1);
    TC_FENCE_AFTER();

    {
        const int sub = wid & 3, half = wid >> 2, lane = t & 31;
        const int rowg = bm + sub * 32 + lane;
        uint32_t regs[2][32];
        TCLD32(regs[0], tmem + half * 64);
        TC_WAIT_LD();
        #pragma unroll
        for (int cc = 0; cc < 2; cc++) {
            if (cc + 1 < 2)
                TCLD32(regs[(cc + 1) & 1], tmem + half * 64 + 32);
            const uint32_t* rg = regs[cc & 1];
            const int col0 = half * 64 + cc * 32;
            const int colbase = bn + col0;
            if (EPI == 0) {
                #pragma unroll
                for (int j = 0; j < 32; j += 4) {
                    float4 v;
                    v.x = __uint_as_float(rg[j]);
                    v.y = __uint_as_float(rg[j + 1]);
                    v.z = __uint_as_float(rg[j + 2]);
                    v.w = __uint_as_float(rg[j + 3]);
                    *(float4*)(C + (size_t)rowg * N + colbase + j) = v;
                }
            } else if (EPI == 1) {
                #pragma unroll
                for (int j = 0; j < 32; j += 4) {
                    float4 bv = *(const float4*)(bias + colbase + j);
                    float4 v;
                    v.x = __uint_as_float(rg[j])     + bv.x;
                    v.y = __uint_as_float(rg[j + 1]) + bv.y;
                    v.z = __uint_as_float(rg[j + 2]) + bv.z;
                    v.w = __uint_as_float(rg[j + 3]) + bv.w;
                    *(float4*)(C + (size_t)rowg * N + colbase + j) = v;
                }
            } else if (EPI == 3) {
                #pragma unroll
                for (int j = 0; j < 32; j += 4) {
                    float4 bv = *(const float4*)(bias + colbase + j);
                    float4 v;
                    v.x = fmaxf(__uint_as_float(rg[j])     + bv.x, 0.f);
                    v.y = fmaxf(__uint_as_float(rg[j + 1]) + bv.y, 0.f);
                    v.z = fmaxf(__uint_as_float(rg[j + 2]) + bv.z, 0.f);
                    v.w = fmaxf(__uint_as_float(rg[j + 3]) + bv.w, 0.f);
                    split_store4(Ch, Cl, (size_t)rowg * N + colbase + j, v);
                }
            } else if (EPI == 4) {
                #pragma unroll
                for (int j = 0; j < 32; j += 4) {
                    float4 v;
                    v.x = __uint_as_float(rg[j]);
                    v.y = __uint_as_float(rg[j + 1]);
                    v.z = __uint_as_float(rg[j + 2]);
                    v.w = __uint_as_float(rg[j + 3]);
                    split_store4(Ch, Cl, (size_t)rowg * N + colbase + j, v);
                }
            } else {  // EPI == 5
                if (colbase < vsplit) {
                    #pragma unroll
                    for (int j = 0; j < 32; j += 4) {
                        float4 v;
                        v.x = __uint_as_float(rg[j]);
                        v.y = __uint_as_float(rg[j + 1]);
                        v.z = __uint_as_float(rg[j + 2]);
                        v.w = __uint_as_float(rg[j + 3]);
                        split_store4(Ch, Cl, (size_t)rowg * N + colbase + j, v);
                    }
                } else {
                    const int vcol = colbase - vsplit;
                    const int z  = (rowg >> 9) * 8 + (vcol >> 6);
                    const int d0 = vcol & 63;
                    const int tok = rowg & 511;
                    const size_t vb = ((size_t)z * 64 + d0) * 512 + tok;
                    #pragma unroll
                    for (int j = 0; j < 32; j++) {
                        float fv = __uint_as_float(rg[j]);
                        bf16 h = __float2bfloat16_rn(fv);
                        bf16 l = __float2bfloat16_rn(fv - __bfloat162float(h));
                        Vh[vb + (size_t)j * 512] = h;
                        Vl[vb + (size_t)j * 512] = l;
                    }
                }
            }
            if (cc + 1 < 2) TC_WAIT_LD();
        }
    }
    __syncthreads();
    if (wid == 0) TC_DEALLOC(tmem, 128);
#else
    const int t  = threadIdx.x;
    const int bm = blockIdx.y * 128, bn = blockIdx.x * 128;
    const int r0 = (t >> 4) * 8;
    const int c0 = (t & 15) * 8;
    for (int i = 0; i < 8; i++) {
        int rowg = bm + r0 + i;
        for (int j = 0; j < 8; j++) {
            int col = bn + c0 + j;
            float acc = 0.f;
            for (int k = 0; k < K; k++) {
                float av = __bfloat162float(Ah[(size_t)rowg * K + k])
                         + __bfloat162float(Al[(size_t)rowg * K + k]);
                float bv = __bfloat162float(Bh[(size_t)col * K + k])
                         + __bfloat162float(Bl[(size_t)col * K + k]);
                acc += av * bv;
            }
            if (EPI == 1 || EPI == 3) acc += bias[col];
            if (EPI == 3) acc = fmaxf(acc, 0.f);
            if (EPI == 0 || EPI == 1) {
                C[(size_t)rowg * N + col] = acc;
            } else if (EPI == 3 || EPI == 4 || (EPI == 5 && col < vsplit)) {
                bf16 h = __float2bfloat16_rn(acc);
                Ch[(size_t)rowg * N + col] = h;
                Cl[(size_t)rowg * N + col] =
                    __float2bfloat16_rn(acc - __bfloat162float(h));
            } else {
                int vcol = col - vsplit;
                int z = (rowg >> 9) * 8 + (vcol >> 6);
                int d = vcol & 63, tok = rowg & 511;
                bf16 h = __float2bfloat16_rn(acc);
                Vh[((size_t)z * 64 + d) * 512 + tok] = h;
                Vl[((size_t)z * 64 + d) * 512 + tok] =
                    __float2bfloat16_rn(acc - __bfloat162float(h));
            }
        }
    }
#endif
}

// ---------------------------------------------------------------------------
// bgemm2: MT=2 for the logits GEMM (grid x = N fast, streaming). Pipelined
// TMEM readback per m-tile.
// ---------------------------------------------------------------------------
#define STAGE2_B   98304
#define NSTG2      2
#define SMEM_GEMM2 (NSTG2 * STAGE2_B + 1024)

__global__ __launch_bounds__(256)
void bgemm2(const bf16* __restrict__ Ah, const bf16* __restrict__ Al,
            const bf16* __restrict__ Bh, const bf16* __restrict__ Bl,
            const float* __restrict__ bias, float* __restrict__ C,
            int M, int N, int K)
{
#if HAS_TC
    __shared__ __align__(16) uint32_t s_tptr[4];
    __shared__ __align__(16) uint64_t s_mbar[NSTG2];
    extern __shared__ char smem[];
    const uint32_t tiles = (s2u(smem) + 1023u) & ~1023u;
    const uint32_t tptr  = s2u(s_tptr);
    uint32_t mb[NSTG2];
    #pragma unroll
    for (int i = 0; i < NSTG2; i++) mb[i] = s2u(&s_mbar[i]);

    const int t   = threadIdx.x;
    const int wid = t >> 5;
    const int bm  = blockIdx.y * 256, bn = blockIdx.x * 128;

    if (wid == 0) TC_ALLOC(tptr, 256);
    if (t == 0) {
        #pragma unroll
        for (int i = 0; i < NSTG2; i++) mbar_init(mb[i], 1);
    }
    __syncthreads();
    const uint32_t tmem = s_tptr[0];

    const int r  = t >> 3;
    const int ck = t & 7;
    const int nch = K >> 6;
    int use[NSTG2];
    #pragma unroll
    for (int i = 0; i < NSTG2; i++) use[i] = 0;

    auto load_chunk = [&](int c, int s) {
        const uint32_t base = tiles + s * STAGE2_B;
        const int k0 = c << 6;
        #pragma unroll
        for (int m = 0; m < 2; m++) {
            const uint32_t aH = base + m * 32768, aL = aH + 16384;
            #pragma unroll
            for (int it = 0; it < 4; it++) {
                int row = r + it * 32;
                size_t g = (size_t)(bm + m * 128 + row) * K + k0 + ck * 8;
                uint32_t so = swz((uint32_t)(row * 128 + ck * 16));
                cpasync16(aH + so, Ah + g);
                cpasync16(aL + so, Al + g);
            }
        }
        const uint32_t bH = base + 65536, bL = base + 81920;
        #pragma unroll
        for (int it = 0; it < 4; it++) {
            int row = r + it * 32;
            size_t g = (size_t)(bn + row) * K + k0 + ck * 8;
            uint32_t so = swz((uint32_t)(row * 128 + ck * 16));
            cpasync16(bH + so, Bh + g);
            cpasync16(bL + so, Bl + g);
        }
        CP_COMMIT();
    };

    load_chunk(0, 0);
    for (int c = 0; c < nch; c++) {
        const int s = c % NSTG2;
        if (c + 1 < nch) {
            const int s2 = (c + 1) % NSTG2;
            if (use[s2] > 0) mbar_wait(mb[s2], (use[s2] - 1) & 1);
            load_chunk(c + 1, s2);
            CP_WAIT1();
        } else {
            CP_WAIT0();
        }
        FENCE_ASYNC();
        __syncthreads();
        if (t == 0) {
            const uint32_t base = tiles + s * STAGE2_B;
            uint64_t dbh = mkdesc(base + 65536), dbl = mkdesc(base + 81920);
            #pragma unroll
            for (int m = 0; m < 2; m++) {
                uint64_t dah = mkdesc(base + m * 32768);
                uint64_t dal = mkdesc(base + m * 32768 + 16384);
                const uint32_t acc = tmem + m * 128;
                #pragma unroll
                for (int j = 0; j < 4; j++)
                    mma_f16_ss(acc, dah + 2 * j, dbh + 2 * j, GIDESC,
                               (c == 0 && j == 0) ? 0u : 1u);
                #pragma unroll
                for (int j = 0; j < 4; j++)
                    mma_f16_ss(acc, dah + 2 * j, dbl + 2 * j, GIDESC, 1u);
                #pragma unroll
                for (int j = 0; j < 4; j++)
                    mma_f16_ss(acc, dal + 2 * j, dbh + 2 * j, GIDESC, 1u);
            }
            TC_COMMIT(mb[s]);
        }
        use[s]++;
    }
    #pragma unroll
    for (int i = 0; i < NSTG2; i++)
        if (use[i] > 0) mbar_wait(mb[i], (use[i] - 1) & 1);
    TC_FENCE_AFTER();

    {
        const int m = wid >> 2, sub = wid & 3, lane = t & 31;
        const int rowg = bm + m * 128 + sub * 32 + lane;
        uint32_t regs[2][32];
        TCLD32(regs[0], tmem + m * 128);
        TC_WAIT_LD();
        #pragma unroll
        for (int cc = 0; cc < 4; cc++) {
            if (cc + 1 < 4)
                TCLD32(regs[(cc + 1) & 1], tmem + m * 128 + (cc + 1) * 32);
            const uint32_t* rg = regs[cc & 1];
            const int colbase = bn + cc * 32;
            #pragma unroll
            for (int j = 0; j < 32; j += 4) {
                float4 bv = *(const float4*)(bias + colbase + j);
                float4 v;
                v.x = __uint_as_float(rg[j])     + bv.x;
                v.y = __uint_as_float(rg[j + 1]) + bv.y;
                v.z = __uint_as_float(rg[j + 2]) + bv.z;
                v.w = __uint_as_float(rg[j + 3]) + bv.w;
                *(float4*)(C + (size_t)rowg * N + colbase + j) = v;
            }
            if (cc + 1 < 4) TC_WAIT_LD();
        }
    }
    __syncthreads();
    if (wid == 0) TC_DEALLOC(tmem, 256);
#else
    const int t  = threadIdx.x;
    const int bm = blockIdx.y * 256, bn = blockIdx.x * 128;
    const int r0 = (t >> 4) * 16;
    const int c0 = (t & 15) * 8;
    for (int i = 0; i < 16; i++) {
        int rowg = bm + r0 + i;
        for (int j = 0; j < 8; j++) {
            int col = bn + c0 + j;
            float acc = 0.f;
            for (int k = 0; k < K; k++) {
                float av = __bfloat162float(Ah[(size_t)rowg * K + k])
                         + __bfloat162float(Al[(size_t)rowg * K + k]);
                float bv = __bfloat162float(Bh[(size_t)col * K + k])
                         + __bfloat162float(Bl[(size_t)col * K + k]);
                acc += av * bv;
            }
            C[(size_t)rowg * N + col] = acc + bias[col];
        }
    }
#endif
}

// ---------------------------------------------------------------------------
// QK^T GEMM: one CTA per (q-tile, z), 4 k-tiles, 48 MMAs into 512-col TMEM,
// single commit/wait. Pipelined TMEM readback (8 iterations). Grid (4, 32).
// ---------------------------------------------------------------------------
#define QK_SMEM (32768 + 4 * 32768 + 1024)
__global__ __launch_bounds__(256) void qk_gemm(
    const bf16* __restrict__ Qh, const bf16* __restrict__ Ql, int qp,
    const bf16* __restrict__ Kh, const bf16* __restrict__ Kl, int kp,
    float* __restrict__ scores)
{
    const int z = blockIdx.y, b = z >> 3, h = z & 7;
    const int bm = blockIdx.x * 128;
    const size_t qoff = (size_t)(b * S_) * qp + h * 64;
    const size_t koff = (size_t)(b * S_) * kp + h * 64;
#if HAS_TC
    __shared__ __align__(16) uint32_t s_tptr[4];
    __shared__ __align__(16) uint64_t s_mbar[1];
    extern __shared__ char smem[];
    const uint32_t tiles = (s2u(smem) + 1023u) & ~1023u;
    const uint32_t tptr  = s2u(s_tptr);
    const uint32_t mb    = s2u(&s_mbar[0]);

    const int t   = threadIdx.x;
    const int wid = t >> 5;
    if (wid == 0) TC_ALLOC(tptr, 512);
    if (t == 0) mbar_init(mb, 1);
    __syncthreads();
    const uint32_t tmem = s_tptr[0];

    const int r  = t >> 3;
    const int ck = t & 7;
    const uint32_t aH = tiles, aL = tiles + 16384;
    #pragma unroll
    for (int it = 0; it < 4; it++) {
        int row = r + it * 32;
        uint32_t so = swz((uint32_t)(row * 128 + ck * 16));
        cpasync16(aH + so, Qh + qoff + (size_t)(bm + row) * qp + ck * 8);
        cpasync16(aL + so, Ql + qoff + (size_t)(bm + row) * qp + ck * 8);
    }
    #pragma unroll
    for (int kb = 0; kb < 4; kb++) {
        const uint32_t bH = tiles + 32768 + kb * 32768, bL = bH + 16384;
        #pragma unroll
        for (int it = 0; it < 4; it++) {
            int row = r + it * 32;
            uint32_t so = swz((uint32_t)(row * 128 + ck * 16));
            cpasync16(bH + so, Kh + koff + (size_t)(kb * 128 + row) * kp + ck * 8);
            cpasync16(bL + so, Kl + koff + (size_t)(kb * 128 + row) * kp + ck * 8);
        }
    }
    CP_COMMIT(); CP_WAIT0();
    FENCE_ASYNC();
    __syncthreads();
    if (t == 0) {
        uint64_t dah = mkdesc(aH), dal = mkdesc(aL);
        #pragma unroll
        for (int kb = 0; kb < 4; kb++) {
            const uint32_t bH = tiles + 32768 + kb * 32768;
            uint64_t dbh = mkdesc(bH), dbl = mkdesc(bH + 16384);
            const uint32_t acc = tmem + kb * 128;
            #pragma unroll
            for (int j = 0; j < 4; j++)
                mma_f16_ss(acc, dah + 2 * j, dbh + 2 * j, GIDESC, j ? 1u : 0u);
            #pragma unroll
            for (int j = 0; j < 4; j++)
                mma_f16_ss(acc, dah + 2 * j, dbl + 2 * j, GIDESC, 1u);
            #pragma unroll
            for (int j = 0; j < 4; j++)
                mma_f16_ss(acc, dal + 2 * j, dbh + 2 * j, GIDESC, 1u);
        }
        TC_COMMIT(mb);
    }
    mbar_wait(mb, 0);
    TC_FENCE_AFTER();
    {
        const int sub = wid & 3, half = wid >> 2, lane = t & 31;
        const int rowg = bm + sub * 32 + lane;
        float* out = scores + ((size_t)z * S_ + rowg) * S_;
        // 8 iterations: idx -> (kb = idx>>1, cc = idx&1)
        uint32_t regs[2][32];
        auto tm_addr = [&](int idx) {
            return tmem + (idx >> 1) * 128 + half * 64 + (idx & 1) * 32;
        };
        TCLD32(regs[0], tm_addr(0));
        TC_WAIT_LD();
        #pragma unroll
        for (int idx = 0; idx < 8; idx++) {
            if (idx + 1 < 8)
                TCLD32(regs[(idx + 1) & 1], tm_addr(idx + 1));
            const uint32_t* rg = regs[idx & 1];
            const int ocol = (idx >> 1) * 128 + half * 64 + (idx & 1) * 32;
            #pragma unroll
            for (int j = 0; j < 32; j += 4) {
                float4 v;
                v.x = __uint_as_float(rg[j])     * 0.125f;
                v.y = __uint_as_float(rg[j + 1]) * 0.125f;
                v.z = __uint_as_float(rg[j + 2]) * 0.125f;
                v.w = __uint_as_float(rg[j + 3]) * 0.125f;
                *(float4*)(out + ocol + j) = v;
            }
            if (idx + 1 < 8) TC_WAIT_LD();
        }
    }
    __syncthreads();
    if (wid == 0) TC_DEALLOC(tmem, 512);
#else
    const int t = threadIdx.x;
    for (int idx = t; idx < 128 * 512; idx += 256) {
        int rr = idx >> 9, cc = idx & 511;
        float acc = 0.f;
        for (int k = 0; k < 64; k++) {
            float qv = __bfloat162float(Qh[qoff + (size_t)(bm + rr) * qp + k])
                     + __bfloat162float(Ql[qoff + (size_t)(bm + rr) * qp + k]);
            float kv = __bfloat162float(Kh[koff + (size_t)cc * kp + k])
                     + __bfloat162float(Kl[koff + (size_t)cc * kp + k]);
            acc += qv * kv;
        }
        scores[((size_t)z * S_ + bm + rr) * S_ + cc] = acc * 0.125f;
    }
#endif
}

// ---------------------------------------------------------------------------
// Masked softmax -> P hi/lo, warp-per-row: 8 rows/block, grid (64, 32).
// ---------------------------------------------------------------------------
__global__ __launch_bounds__(256) void softmax_kernel(
    const float* __restrict__ scores, const int* __restrict__ kv_tok,
    bf16* __restrict__ Ph, bf16* __restrict__ Pl, int causal)
{
    __shared__ float s_mask[512];
    const int z = blockIdx.y, b = z >> 3;
    const int t = threadIdx.x;
    const int wid = t >> 5, lane = t & 31;
    const int q = blockIdx.x * 8 + wid;

    s_mask[t]       = (kv_tok[b * S_ + t]       == 0) ? NEGV : 0.f;
    s_mask[t + 256] = (kv_tok[b * S_ + t + 256] == 0) ? NEGV : 0.f;
    __syncthreads();

    const size_t base = ((size_t)z * S_ + q) * S_;
    float vals[16];
    float m = -3.0e38f;
    #pragma unroll
    for (int c = 0; c < 4; c++) {
        int k0 = lane * 4 + c * 128;
        float4 s = *(const float4*)(scores + base + k0);
        float* v4 = vals + c * 4;
        v4[0] = s.x + s_mask[k0];
        v4[1] = s.y + s_mask[k0 + 1];
        v4[2] = s.z + s_mask[k0 + 2];
        v4[3] = s.w + s_mask[k0 + 3];
        if (causal) {
            #pragma unroll
            for (int j = 0; j < 4; j++)
                if (k0 + j > q) v4[j] += NEGV;
        }
        #pragma unroll
        for (int j = 0; j < 4; j++) m = fmaxf(m, v4[j]);
    }
    #pragma unroll
    for (int off = 16; off > 0; off >>= 1)
        m = fmaxf(m, __shfl_xor_sync(0xffffffffu, m, off));

    float e[16], ssum = 0.f;
    #pragma unroll
    for (int j = 0; j < 16; j++) { e[j] = __expf(vals[j] - m); ssum += e[j]; }
    #pragma unroll
    for (int off = 16; off > 0; off >>= 1)
        ssum += __shfl_xor_sync(0xffffffffu, ssum, off);
    const float inv = 1.f / ssum;

    #pragma unroll
    for (int c = 0; c < 4; c++) {
        int k0 = lane * 4 + c * 128;
        float4 p = make_float4(e[c * 4] * inv, e[c * 4 + 1] * inv,
                               e[c * 4 + 2] * inv, e[c * 4 + 3] * inv);
        split_store4(Ph, Pl, base + k0, p);
    }
}

// ---------------------------------------------------------------------------
// AV GEMM: out = P @ V via V^T, grid (1,4,32), 3-stage pipeline
// ---------------------------------------------------------------------------
#define AV_STAGE  49152
#define AV_NSTG   3
#define AV_SMEM   (AV_NSTG * AV_STAGE + 1024)
#define AVIDESC   IDESC_N(64)
__global__ __launch_bounds__(256) void av_gemm(
    const bf16* __restrict__ Ph, const bf16* __restrict__ Pl,
    const bf16* __restrict__ Vth, const bf16* __restrict__ Vtl,
    bf16* __restrict__ Oh, bf16* __restrict__ Ol)
{
    const int z = blockIdx.z, b = z >> 3, h = z & 7;
    const int bm = blockIdx.y * 128;
    const bf16* Pzh = Ph  + (size_t)z * S_ * S_;
    const bf16* Pzl = Pl  + (size_t)z * S_ * S_;
    const bf16* Vzh = Vth + (size_t)z * 64 * S_;
    const bf16* Vzl = Vtl + (size_t)z * 64 * S_;
#if HAS_TC
    __shared__ __align__(16) uint32_t s_tptr[4];
    __shared__ __align__(16) uint64_t s_mbar[AV_NSTG];
    extern __shared__ char smem[];
    const uint32_t tiles = (s2u(smem) + 1023u) & ~1023u;
    const uint32_t tptr  = s2u(s_tptr);
    uint32_t mb[AV_NSTG];
    #pragma unroll
    for (int i = 0; i < AV_NSTG; i++) mb[i] = s2u(&s_mbar[i]);

    const int t   = threadIdx.x;
    const int wid = t >> 5;
    if (wid == 0) TC_ALLOC(tptr, 128);
    if (t == 0) {
        #pragma unroll
        for (int i = 0; i < AV_NSTG; i++) mbar_init(mb[i], 1);
    }
    __syncthreads();
    const uint32_t tmem = s_tptr[0];

    const int r  = t >> 3;
    const int ck = t & 7;
    int use[AV_NSTG];
    #pragma unroll
    for (int i = 0; i < AV_NSTG; i++) use[i] = 0;

    auto load_chunk = [&](int c, int s) {
        const uint32_t base = tiles + s * AV_STAGE;
        const uint32_t aH = base, aL = base + 16384;
        const uint32_t bH = base + 32768, bL = base + 40960;
        const int k0 = c << 6;
        #pragma unroll
        for (int it = 0; it < 4; it++) {
            int row = r + it * 32;
            size_t g = (size_t)(bm + row) * S_ + k0 + ck * 8;
            uint32_t so = swz((uint32_t)(row * 128 + ck * 16));
            cpasync16(aH + so, Pzh + g);
            cpasync16(aL + so, Pzl + g);
        }
        #pragma unroll
        for (int it = 0; it < 2; it++) {
            int row = r + it * 32;
            size_t g = (size_t)row * S_ + k0 + ck * 8;
            uint32_t so = swz((uint32_t)(row * 128 + ck * 16));
            cpasync16(bH + so, Vzh + g);
            cpasync16(bL + so, Vzl + g);
        }
        CP_COMMIT();
    };

    const int nch = S_ >> 6;
    load_chunk(0, 0);
    for (int c = 0; c < nch; c++) {
        const int s = c % AV_NSTG;
        if (c + 1 < nch) {
            const int s2 = (c + 1) % AV_NSTG;
            if (use[s2] > 0) mbar_wait(mb[s2], (use[s2] - 1) & 1);
            load_chunk(c + 1, s2);
            CP_WAIT1();
        } else {
            CP_WAIT0();
        }
        FENCE_ASYNC();
        __syncthreads();
        if (t == 0) {
            const uint32_t base = tiles + s * AV_STAGE;
            uint64_t dah = mkdesc(base),         dal = mkdesc(base + 16384);
            uint64_t dbh = mkdesc(base + 32768), dbl = mkdesc(base + 40960);
            #pragma unroll
            for (int j = 0; j < 4; j++)
                mma_f16_ss(tmem, dah + 2 * j, dbh + 2 * j, AVIDESC,
                           (c == 0 && j == 0) ? 0u : 1u);
            #pragma unroll
            for (int j = 0; j < 4; j++)
                mma_f16_ss(tmem, dah + 2 * j, dbl + 2 * j, AVIDESC, 1u);
            #pragma unroll
            for (int j = 0; j < 4; j++)
                mma_f16_ss(tmem, dal + 2 * j, dbh + 2 * j, AVIDESC, 1u);
            TC_COMMIT(mb[s]);
        }
        use[s]++;
    }
    #pragma unroll
    for (int i = 0; i < AV_NSTG; i++)
        if (use[i] > 0) mbar_wait(mb[i], (use[i] - 1) & 1);
    TC_FENCE_AFTER();
    {
        const int sub = wid & 3, half = wid >> 2, lane = t & 31;
        const int rowg = bm + sub * 32 + lane;
        const int col0 = half * 32;
        uint32_t regs[32];
        TCLD32(regs, tmem + col0);
        TC_WAIT_LD();
        #pragma unroll
        for (int j = 0; j < 32; j += 4) {
            float4 v;
            v.x = __uint_as_float(regs[j]);
            v.y = __uint_as_float(regs[j + 1]);
            v.z = __uint_as_float(regs[j + 2]);
            v.w = __uint_as_float(regs[j + 3]);
            size_t idx = ((size_t)(b * S_) + rowg) * D_ + h * 64 + col0 + j;
            split_store4(Oh, Ol, idx, v);
        }
    }
    __syncthreads();
    if (wid == 0) TC_DEALLOC(tmem, 128);
#else
    const int t = threadIdx.x;
    for (int idx = t; idx < 128 * 64; idx += 256) {
        int rr = idx >> 6, cc = idx & 63;
        float acc = 0.f;
        for (int k = 0; k < S_; k++) {
            float pv = __bfloat162float(Pzh[(size_t)(bm + rr) * S_ + k])
                     + __bfloat162float(Pzl[(size_t)(bm + rr) * S_ + k]);
            float vv = __bfloat162float(Vzh[(size_t)cc * S_ + k])
                     + __bfloat162float(Vzl[(size_t)cc * S_ + k]);
            acc += pv * vv;
        }
        size_t oidx = ((size_t)(b * S_) + bm + rr) * D_ + h * 64 + cc;
        bf16 hh2 = __float2bfloat16_rn(acc);
        Oh[oidx] = hh2;
        Ol[oidx] = __float2bfloat16_rn(acc - __bfloat162float(hh2));
    }
#endif
}

// ---------------------------------------------------------------------------
// Host driver
// ---------------------------------------------------------------------------
static inline void run_bgemm(int epi, const bf16* Ah, const bf16* Al,
                             const bf16* Bh, const bf16* Bl, const float* bias,
                             float* C, bf16* Ch, bf16* Cl,
                             bf16* Vh, bf16* Vl, int vsplit,
                             int M, int N, int K)
{
    dim3 grid(N / 128, M / 128);
    if (epi == 0)
        bgemm<0><<<grid, 256, SMEM_GEMM>>>(Ah, Al, Bh, Bl, bias, C, Ch, Cl, Vh, Vl, vsplit, M, N, K);
    else if (epi == 1)
        bgemm<1><<<grid, 256, SMEM_GEMM>>>(Ah, Al, Bh, Bl, bias, C, Ch, Cl, Vh, Vl, vsplit, M, N, K);
    else if (epi == 3)
        bgemm<3><<<grid, 256, SMEM_GEMM>>>(Ah, Al, Bh, Bl, bias, C, Ch, Cl, Vh, Vl, vsplit, M, N, K);
    else if (epi == 4)
        bgemm<4><<<grid, 256, SMEM_GEMM>>>(Ah, Al, Bh, Bl, bias, C, Ch, Cl, Vh, Vl, vsplit, M, N, K);
    else
        bgemm<5><<<grid, 256, SMEM_GEMM>>>(Ah, Al, Bh, Bl, bias, C, Ch, Cl, Vh, Vl, vsplit, M, N, K);
}

extern "C" void kernel_launch(void* const* d_in, const int* in_sizes, int n_in,
                              void* d_out, int out_size)
{
    const int DDi = D_ * D_;

    int iEWq, iEWk, iEWv, iEWo, iEW1, iEb1, iEW2, iEb2;
    int iDWq1, iDWk1, iDWv1, iDWo1, iDWq2, iDWk2, iDWv2, iDWo2;
    int iDW1, iDb1, iDW2, iDb2, iWout, iBout;
    if (n_in >= 8 && in_sizes[7] == L_ * DDi) {
        iEWq = 3; iEWk = 4; iEWv = 5; iEWo = 6;
        iDWq1 = 7; iDWk1 = 8; iDWv1 = 9; iDWo1 = 10;
        iDWq2 = 11; iDWk2 = 12; iDWv2 = 13; iDWo2 = 14;
        iEW1 = 15; iEb1 = 16; iEW2 = 17; iEb2 = 18;
        iDW1 = 19; iDb1 = 20; iDW2 = 21; iDb2 = 22;
        iWout = 23; iBout = 24;
    } else {
        iEWq = 3; iEWk = 4; iEWv = 5; iEWo = 6;
        iEW1 = 7; iEb1 = 8; iEW2 = 9; iEb2 = 10;
        iDWq1 = 11; iDWk1 = 12; iDWv1 = 13; iDWo1 = 14;
        iDWq2 = 15; iDWk2 = 16; iDWv2 = 17; iDWo2 = 18;
        iDW1 = 19; iDb1 = 20; iDW2 = 21; iDb2 = 22;
        iWout = 23; iBout = 24;
    }

    const int*   src  = (const int*)d_in[0];
    const int*   tgt  = (const int*)d_in[1];
    const float* emb  = (const float*)d_in[2];
    const float* eWq  = (const float*)d_in[iEWq];
    const float* eWk  = (const float*)d_in[iEWk];
    const float* eWv  = (const float*)d_in[iEWv];
    const float* eWo  = (const float*)d_in[iEWo];
    const float* eW1  = (const float*)d_in[iEW1];
    const float* eb1  = (const float*)d_in[iEb1];
    const float* eW2  = (const float*)d_in[iEW2];
    const float* eb2  = (const float*)d_in[iEb2];
    const float* dWq1 = (const float*)d_in[iDWq1];
    const float* dWk1 = (const float*)d_in[iDWk1];
    const float* dWv1 = (const float*)d_in[iDWv1];
    const float* dWo1 = (const float*)d_in[iDWo1];
    const float* dWq2 = (const float*)d_in[iDWq2];
    const float* dWk2 = (const float*)d_in[iDWk2];
    const float* dWv2 = (const float*)d_in[iDWv2];
    const float* dWo2 = (const float*)d_in[iDWo2];
    const float* dW1  = (const float*)d_in[iDW1];
    const float* db1  = (const float*)d_in[iDb1];
    const float* dW2  = (const float*)d_in[iDW2];
    const float* db2  = (const float*)d_in[iDb2];
    const float* Wout = (const float*)d_in[iWout];
    const float* bout = (const float*)d_in[iBout];

    cudaFuncSetAttribute(bgemm<0>, cudaFuncAttributeMaxDynamicSharedMemorySize, SMEM_GEMM);
    cudaFuncSetAttribute(bgemm<1>, cudaFuncAttributeMaxDynamicSharedMemorySize, SMEM_GEMM);
    cudaFuncSetAttribute(bgemm<3>, cudaFuncAttributeMaxDynamicSharedMemorySize, SMEM_GEMM);
    cudaFuncSetAttribute(bgemm<4>, cudaFuncAttributeMaxDynamicSharedMemorySize, SMEM_GEMM);
    cudaFuncSetAttribute(bgemm<5>, cudaFuncAttributeMaxDynamicSharedMemorySize, SMEM_GEMM);
    cudaFuncSetAttribute(bgemm2,   cudaFuncAttributeMaxDynamicSharedMemorySize, SMEM_GEMM2);
    cudaFuncSetAttribute(qk_gemm,  cudaFuncAttributeMaxDynamicSharedMemorySize, QK_SMEM);
    cudaFuncSetAttribute(av_gemm,  cudaFuncAttributeMaxDynamicSharedMemorySize, AV_SMEM);

    float *x, *a, *f, *y0, *o, *scores;
    cudaGetSymbolAddress((void**)&x,   g_x);
    cudaGetSymbolAddress((void**)&a,   g_a);
    cudaGetSymbolAddress((void**)&f,   g_f);
    cudaGetSymbolAddress((void**)&y0,  g_y0);
    cudaGetSymbolAddress((void**)&o,   g_o);
    cudaGetSymbolAddress((void**)&scores, g_scores);

    bf16 *xh, *xl, *outh, *outl, *ath, *atl, *y0h, *y0l, *oh, *ol, *hh, *hl, *wh, *wl;
    bf16 *qkvh, *qkvl, *kv2h, *kv2l, *q2h, *q2l, *ph, *pl, *vth, *vtl;
    cudaGetSymbolAddress((void**)&xh,   g_xh);
    cudaGetSymbolAddress((void**)&xl,   g_xl);
    cudaGetSymbolAddress((void**)&outh, g_outh);
    cudaGetSymbolAddress((void**)&outl, g_outl);
    cudaGetSymbolAddress((void**)&ath,  g_ath);
    cudaGetSymbolAddress((void**)&atl,  g_atl);
    cudaGetSymbolAddress((void**)&y0h,  g_y0h);
    cudaGetSymbolAddress((void**)&y0l,  g_y0l);
    cudaGetSymbolAddress((void**)&oh,   g_oh);
    cudaGetSymbolAddress((void**)&ol,   g_ol);
    cudaGetSymbolAddress((void**)&hh,   g_hh);
    cudaGetSymbolAddress((void**)&hl,   g_hl);
    cudaGetSymbolAddress((void**)&wh,   g_wh);
    cudaGetSymbolAddress((void**)&wl,   g_wl);
    cudaGetSymbolAddress((void**)&qkvh, g_qkvh);
    cudaGetSymbolAddress((void**)&qkvl, g_qkvl);
    cudaGetSymbolAddress((void**)&kv2h, g_kv2h);
    cudaGetSymbolAddress((void**)&kv2l, g_kv2l);
    cudaGetSymbolAddress((void**)&q2h,  g_q2h);
    cudaGetSymbolAddress((void**)&q2l,  g_q2l);
    cudaGetSymbolAddress((void**)&ph,   g_ph);
    cudaGetSymbolAddress((void**)&pl,   g_pl);
    cudaGetSymbolAddress((void**)&vth,  g_vth);
    cudaGetSymbolAddress((void**)&vtl,  g_vtl);

    // ---- Weight conversion: ONE launch ----
    {
        const int li = L_ - 1;
        WcvTable tab;
        int ts = 0, ne = 0;
        auto add = [&](const float* s, unsigned long long dst,
                       unsigned long long ls, int K, int N, int nz) {
            WcvEntry& E = tab.e[ne++];
            E.src = s; E.dst = dst; E.lstride = ls;
            E.K = K; E.N = N; E.ntx = N / 32; E.nty = K / 32; E.nz = nz;
            E.tstart = ts;
            ts += (N / 32) * (K / 32) * nz;
        };
        add(eWq, O_EQKV,          3 * DD, D_, D_, 6);
        add(eWk, O_EQKV + DD,     3 * DD, D_, D_, 6);
        add(eWv, O_EQKV + 2 * DD, 3 * DD, D_, D_, 6);
        add(eWo, O_EWO, DD,  D_, D_, 6);
        add(eW1, O_EW1, DDF, D_, DFF_, 6);
        add(eW2, O_EW2, DDF, DFF_, D_, 6);
        add(dWq1 + (size_t)li * DDi, O_DQKV1,          0, D_, D_, 1);
        add(dWk1 + (size_t)li * DDi, O_DQKV1 + DD,     0, D_, D_, 1);
        add(dWv1 + (size_t)li * DDi, O_DQKV1 + 2 * DD, 0, D_, D_, 1);
        add(dWo1 + (size_t)li * DDi, O_DWO1, 0, D_, D_, 1);
        add(dWq2 + (size_t)li * DDi, O_DWQ2, 0, D_, D_, 1);
        add(dWk2 + (size_t)li * DDi, O_DKV2,      0, D_, D_, 1);
        add(dWv2 + (size_t)li * DDi, O_DKV2 + DD, 0, D_, D_, 1);
        add(dWo2 + (size_t)li * DDi, O_DWO2, 0, D_, D_, 1);
        add(dW1 + (size_t)li * (D_ * DFF_), O_DW1, 0, D_, DFF_, 1);
        add(dW2 + (size_t)li * (D_ * DFF_), O_DW2, 0, DFF_, D_, 1);
        add(Wout, O_WOUT, 0, D_, V_, 1);
        wconv_all<<<ts, dim3(32, 8)>>>(tab, ne, wh, wl);
    }

    const dim3 qkGrid(4, 32), smGrid(S_ / 8, 32), avGrid(1, 4, 32);
    const int li = L_ - 1;

    // ---------------- Encoder ----------------
    embed_kernel<<<BS_, 128>>>(src, emb, x, xh, xl);
    for (int i = 0; i < L_; i++) {
        run_bgemm(5, xh, xl, wh + O_EQKV + (size_t)i * 3 * DD, wl + O_EQKV + (size_t)i * 3 * DD,
                  nullptr, nullptr, qkvh, qkvl, vth, vtl, 1024, BS_, 3 * D_, D_);
        qk_gemm<<<qkGrid, 256, QK_SMEM>>>(qkvh, qkvl, 3 * D_,
                                          qkvh + D_, qkvl + D_, 3 * D_, scores);
        softmax_kernel<<<smGrid, 256>>>(scores, src, ph, pl, 0);
        av_gemm<<<avGrid, 256, AV_SMEM>>>(ph, pl, vth, vtl, ath, atl);
        run_bgemm(0, ath, atl, wh + O_EWO + (size_t)i * DD, wl + O_EWO + (size_t)i * DD,
                  nullptr, a, nullptr, nullptr, nullptr, nullptr, 0, BS_, D_, D_);
        add_ln_kernel<<<BS_, 128>>>(x, a, nullptr, outh, outl);   // fp32 out is dead
        run_bgemm(3, outh, outl, wh + O_EW1 + (size_t)i * DDF, wl + O_EW1 + (size_t)i * DDF,
                  eb1 + (size_t)i * DFF_, nullptr, hh, hl, nullptr, nullptr, 0, BS_, DFF_, D_);
        run_bgemm(1, hh, hl, wh + O_EW2 + (size_t)i * DDF, wl + O_EW2 + (size_t)i * DDF,
                  eb2 + (size_t)i * D_, f, nullptr, nullptr, nullptr, nullptr, 0, BS_, D_, DFF_);
        add_ln_kernel<<<BS_, 128>>>(a, f, x, xh, xl);
    }

    // ---------------- Decoder (last layer only) ----------------
    embed_kernel<<<BS_, 128>>>(tgt, emb, y0, y0h, y0l);
    {
        run_bgemm(5, y0h, y0l, wh + O_DQKV1, wl + O_DQKV1, nullptr, nullptr,
                  qkvh, qkvl, vth, vtl, 1024, BS_, 3 * D_, D_);
        qk_gemm<<<qkGrid, 256, QK_SMEM>>>(qkvh, qkvl, 3 * D_,
                                          qkvh + D_, qkvl + D_, 3 * D_, scores);
        softmax_kernel<<<smGrid, 256>>>(scores, tgt, ph, pl, 1);
        av_gemm<<<avGrid, 256, AV_SMEM>>>(ph, pl, vth, vtl, ath, atl);
        run_bgemm(0, ath, atl, wh + O_DWO1, wl + O_DWO1, nullptr, a,
                  nullptr, nullptr, nullptr, nullptr, 0, BS_, D_, D_);
        add_ln_kernel<<<BS_, 128>>>(y0, a, o, oh, ol);

        run_bgemm(4, oh, ol, wh + O_DWQ2, wl + O_DWQ2, nullptr, nullptr,
                  q2h, q2l, nullptr, nullptr, 0, BS_, D_, D_);
        run_bgemm(5, xh, xl, wh + O_DKV2, wl + O_DKV2, nullptr, nullptr,
                  kv2h, kv2l, vth, vtl, 512, BS_, 2 * D_, D_);
        qk_gemm<<<qkGrid, 256, QK_SMEM>>>(q2h, q2l, D_, kv2h, kv2l, 2 * D_, scores);
        softmax_kernel<<<smGrid, 256>>>(scores, src, ph, pl, 0);
        av_gemm<<<avGrid, 256, AV_SMEM>>>(ph, pl, vth, vtl, ath, atl);
        run_bgemm(0, ath, atl, wh + O_DWO2, wl + O_DWO2, nullptr, a,
                  nullptr, nullptr, nullptr, nullptr, 0, BS_, D_, D_);
        add_ln_kernel<<<BS_, 128>>>(o, a, o, oh, ol);

        run_bgemm(3, oh, ol, wh + O_DW1, wl + O_DW1, db1 + (size_t)li * DFF_,
                  nullptr, hh, hl, nullptr, nullptr, 0, BS_, DFF_, D_);
        run_bgemm(1, hh, hl, wh + O_DW2, wl + O_DW2, db2 + (size_t)li * D_,
                  f, nullptr, nullptr, nullptr, nullptr, 0, BS_, D_, DFF_);
        add_ln_kernel<<<BS_, 128>>>(o, f, o, oh, ol);
    }

    // ---------------- Logits (MT=2, x = N streaming) ----------------
    bgemm2<<<dim3(V_ / 128, BS_ / 256), 256, SMEM_GEMM2>>>(
        oh, ol, wh + O_WOUT, wl + O_WOUT, bout, (float*)d_out, BS_, V_, D_);
}